// round 1
// baseline (speedup 1.0000x reference)
#include <cuda_runtime.h>

#define BATCH 2
#define SEQ   2048
#define DIM   2048
#define NH    16
#define HD    128
#define ROWS  (BATCH*SEQ)   // 4096

// ---------------- scratch (static device globals; no allocs allowed) --------
__device__ float g_q[ROWS*DIM];
__device__ float g_k[ROWS*DIM];
__device__ float g_v[ROWS*DIM];
__device__ float g_o[ROWS*DIM];

// ---------------- GEMM: C[M,N] = A[M,K] * B[N,K]^T ---------------------------
#define BM 128
#define BN 128
#define BK 16

__global__ void __launch_bounds__(256, 2) gemm_nt_kernel(
    const float* __restrict__ A, const float* __restrict__ B,
    float* __restrict__ C, int M, int N, int K)
{
    __shared__ float As[BK][BM + 4];
    __shared__ float Bs[BK][BN + 4];

    const int t  = threadIdx.x;
    const int tx = t & 15;
    const int ty = t >> 4;
    const int m0 = blockIdx.y * BM;
    const int n0 = blockIdx.x * BN;
    const int lrow = t >> 2;          // 0..63
    const int lcol = (t & 3) << 2;    // 0,4,8,12

    float acc[8][8];
#pragma unroll
    for (int i = 0; i < 8; i++)
#pragma unroll
        for (int j = 0; j < 8; j++) acc[i][j] = 0.f;

    for (int k0 = 0; k0 < K; k0 += BK) {
#pragma unroll
        for (int rr = 0; rr < 2; rr++) {
            int r = lrow + rr * 64;
            float4 va = *(const float4*)(A + (size_t)(m0 + r) * K + k0 + lcol);
            As[lcol + 0][r] = va.x; As[lcol + 1][r] = va.y;
            As[lcol + 2][r] = va.z; As[lcol + 3][r] = va.w;
            float4 vb = *(const float4*)(B + (size_t)(n0 + r) * K + k0 + lcol);
            Bs[lcol + 0][r] = vb.x; Bs[lcol + 1][r] = vb.y;
            Bs[lcol + 2][r] = vb.z; Bs[lcol + 3][r] = vb.w;
        }
        __syncthreads();

#pragma unroll
        for (int kk = 0; kk < BK; kk++) {
            float4 a0 = *(const float4*)&As[kk][ty * 8];
            float4 a1 = *(const float4*)&As[kk][ty * 8 + 4];
            float4 b0 = *(const float4*)&Bs[kk][tx * 8];
            float4 b1 = *(const float4*)&Bs[kk][tx * 8 + 4];
            float a[8] = {a0.x, a0.y, a0.z, a0.w, a1.x, a1.y, a1.z, a1.w};
            float b[8] = {b0.x, b0.y, b0.z, b0.w, b1.x, b1.y, b1.z, b1.w};
#pragma unroll
            for (int i = 0; i < 8; i++)
#pragma unroll
                for (int j = 0; j < 8; j++)
                    acc[i][j] += a[i] * b[j];
        }
        __syncthreads();
    }

#pragma unroll
    for (int i = 0; i < 8; i++) {
        float* crow = C + (size_t)(m0 + ty * 8 + i) * N + n0 + tx * 8;
        float4 c0 = {acc[i][0], acc[i][1], acc[i][2], acc[i][3]};
        float4 c1 = {acc[i][4], acc[i][5], acc[i][6], acc[i][7]};
        *(float4*)(crow)     = c0;
        *(float4*)(crow + 4) = c1;
    }
}

// ---------------- RoPE (in-place, float2 = one (re,im) pair) ----------------
__global__ void rope_kernel(float* __restrict__ a,
                            const float* __restrict__ fc,
                            const float* __restrict__ fs)
{
    int idx = blockIdx.x * blockDim.x + threadIdx.x;   // over ROWS*DIM/2 pairs
    int i = idx & 63;                 // pair index within head (HD/2 = 64)
    int s = (idx >> 10) & (SEQ - 1);  // DIM/2 = 1024 pairs per token row
    float2 v = ((float2*)a)[idx];
    float c  = fc[s * 64 + i];
    float sn = fs[s * 64 + i];
    float2 r;
    r.x = v.x * c - v.y * sn;
    r.y = v.x * sn + v.y * c;
    ((float2*)a)[idx] = r;
}

// ---------------- streaming causal attention (flash-style) ------------------
#define ATM 64
#define ATN 64
#define QS  132   // padded stride for Q/K/V tiles (128 + 4)
#define PS  68    // padded stride for score tile  (64 + 4)
#define ATTN_SMEM_FLOATS (3*ATM*QS + ATM*PS + 3*ATM)
#define ATTN_SMEM_BYTES  (ATTN_SMEM_FLOATS * 4)

__global__ void __launch_bounds__(256) attn_kernel(
    const float* __restrict__ q, const float* __restrict__ k,
    const float* __restrict__ v, float* __restrict__ o)
{
    extern __shared__ float sm[];
    float* Qs   = sm;                 // [64][132]
    float* Ks   = Qs + ATM * QS;      // [64][132]
    float* Vs   = Ks + ATN * QS;      // [64][132]
    float* Pp   = Vs + ATN * QS;      // [64][68]
    float* mrow = Pp + ATM * PS;      // [64]
    float* lrow = mrow + ATM;         // [64]
    float* arow = lrow + ATM;         // [64]

    const int t  = threadIdx.x;
    const int qt = blockIdx.x, h = blockIdx.y, b = blockIdx.z;
    const size_t head = ((size_t)b * SEQ) * DIM + (size_t)h * HD;

    // load Q tile
    for (int idx = t; idx < ATM * 32; idx += 256) {
        int r = idx >> 5, c4 = (idx & 31) << 2;
        *(float4*)(Qs + r * QS + c4) =
            *(const float4*)(q + head + (size_t)(qt * ATM + r) * DIM + c4);
    }
    if (t < ATM) { mrow[t] = -1e30f; lrow[t] = 0.f; }

    // O accumulators: thread owns rows {2*pr, 2*pr+1}, cols cg*4 + 32*jj (+0..3)
    float oa[16], ob[16];
#pragma unroll
    for (int i = 0; i < 16; i++) { oa[i] = 0.f; ob[i] = 0.f; }
    const int pr = t >> 3;    // 0..31 row pair
    const int cg = t & 7;     // 0..7 col group

    // phase-A mapping: rows tym+16i, cols txm+16j
    const int tym = t >> 4, txm = t & 15;
    const float scale = 0.08838834764831845f;   // 1/sqrt(128)

    for (int kt = 0; kt <= qt; kt++) {
        __syncthreads();   // previous phase C done with Vs/Pp
        for (int idx = t; idx < ATN * 32; idx += 256) {
            int r = idx >> 5, c4 = (idx & 31) << 2;
            size_t g = head + (size_t)(kt * ATN + r) * DIM + c4;
            *(float4*)(Ks + r * QS + c4) = *(const float4*)(k + g);
            *(float4*)(Vs + r * QS + c4) = *(const float4*)(v + g);
        }
        __syncthreads();

        // --- phase A: S = scale * Q K^T (+ causal mask) -> Pp
        {
            float acc[4][4];
#pragma unroll
            for (int i = 0; i < 4; i++)
#pragma unroll
                for (int j = 0; j < 4; j++) acc[i][j] = 0.f;

            for (int d = 0; d < HD; d += 4) {
                float4 qa[4], kb[4];
#pragma unroll
                for (int i = 0; i < 4; i++)
                    qa[i] = *(const float4*)(Qs + (tym + 16 * i) * QS + d);
#pragma unroll
                for (int j = 0; j < 4; j++)
                    kb[j] = *(const float4*)(Ks + (txm + 16 * j) * QS + d);
#pragma unroll
                for (int i = 0; i < 4; i++)
#pragma unroll
                    for (int j = 0; j < 4; j++)
                        acc[i][j] += qa[i].x * kb[j].x + qa[i].y * kb[j].y
                                   + qa[i].z * kb[j].z + qa[i].w * kb[j].w;
            }
#pragma unroll
            for (int i = 0; i < 4; i++) {
                int rq = tym + 16 * i;
                int qg = qt * ATM + rq;
#pragma unroll
                for (int j = 0; j < 4; j++) {
                    int rc = txm + 16 * j;
                    float sc = acc[i][j] * scale;
                    if (kt * ATN + rc > qg) sc -= 1e9f;
                    Pp[rq * PS + rc] = sc;
                }
            }
        }
        __syncthreads();

        // --- phase B: per-row online softmax bookkeeping
        if (t < ATM) {
            float* prow = Pp + t * PS;
            float mo = mrow[t];
            float mt = mo;
#pragma unroll 8
            for (int j = 0; j < ATN; j++) mt = fmaxf(mt, prow[j]);
            float al = __expf(mo - mt);
            float sum = 0.f;
#pragma unroll 8
            for (int j = 0; j < ATN; j++) {
                float p = __expf(prow[j] - mt);
                prow[j] = p;
                sum += p;
            }
            mrow[t] = mt;
            arow[t] = al;
            lrow[t] = lrow[t] * al + sum;
        }
        __syncthreads();

        // --- phase C: O = O*alpha + P @ V
        {
            float al0 = arow[2 * pr], al1 = arow[2 * pr + 1];
#pragma unroll
            for (int i = 0; i < 16; i++) { oa[i] *= al0; ob[i] *= al1; }
            const float* p0 = Pp + (2 * pr) * PS;
            const float* p1 = p0 + PS;
#pragma unroll 4
            for (int kk = 0; kk < ATN; kk++) {
                float w0 = p0[kk], w1 = p1[kk];
                const float* vr = Vs + kk * QS;
#pragma unroll
                for (int jj = 0; jj < 4; jj++) {
                    float4 vv = *(const float4*)(vr + cg * 4 + jj * 32);
                    oa[jj*4+0] += w0 * vv.x; oa[jj*4+1] += w0 * vv.y;
                    oa[jj*4+2] += w0 * vv.z; oa[jj*4+3] += w0 * vv.w;
                    ob[jj*4+0] += w1 * vv.x; ob[jj*4+1] += w1 * vv.y;
                    ob[jj*4+2] += w1 * vv.z; ob[jj*4+3] += w1 * vv.w;
                }
            }
        }
    }

    // normalize + write
    float li0 = 1.f / lrow[2 * pr];
    float li1 = 1.f / lrow[2 * pr + 1];
    size_t o0 = head + (size_t)(qt * ATM + 2 * pr) * DIM;
#pragma unroll
    for (int jj = 0; jj < 4; jj++) {
        float4 w0 = {oa[jj*4+0]*li0, oa[jj*4+1]*li0, oa[jj*4+2]*li0, oa[jj*4+3]*li0};
        float4 w1 = {ob[jj*4+0]*li1, ob[jj*4+1]*li1, ob[jj*4+2]*li1, ob[jj*4+3]*li1};
        *(float4*)(o + o0 + cg * 4 + jj * 32)       = w0;
        *(float4*)(o + o0 + DIM + cg * 4 + jj * 32) = w1;
    }
}

// ---------------- launcher ---------------------------------------------------
extern "C" void kernel_launch(void* const* d_in, const int* in_sizes, int n_in,
                              void* d_out, int out_size)
{
    const float* x    = (const float*)d_in[0];
    const float* wq   = (const float*)d_in[1];
    const float* wk   = (const float*)d_in[2];
    const float* wv   = (const float*)d_in[3];
    const float* wo   = (const float*)d_in[4];
    const float* fcos = (const float*)d_in[5];
    const float* fsin = (const float*)d_in[6];
    // d_in[7] = mask: causal, implemented analytically in attn_kernel
    float* out = (float*)d_out;

    float *q, *k, *v, *o;
    cudaGetSymbolAddress((void**)&q, g_q);
    cudaGetSymbolAddress((void**)&k, g_k);
    cudaGetSymbolAddress((void**)&v, g_v);
    cudaGetSymbolAddress((void**)&o, g_o);

    cudaFuncSetAttribute(attn_kernel,
                         cudaFuncAttributeMaxDynamicSharedMemorySize,
                         ATTN_SMEM_BYTES);

    dim3 gg(DIM / BN, ROWS / BM);   // (16, 32)

    gemm_nt_kernel<<<gg, 256>>>(x, wq, q, ROWS, DIM, DIM);
    gemm_nt_kernel<<<gg, 256>>>(x, wk, k, ROWS, DIM, DIM);
    gemm_nt_kernel<<<gg, 256>>>(x, wv, v, ROWS, DIM, DIM);

    int npairs = ROWS * DIM / 2;
    rope_kernel<<<npairs / 256, 256>>>(q, fcos, fsin);
    rope_kernel<<<npairs / 256, 256>>>(k, fcos, fsin);

    attn_kernel<<<dim3(SEQ / ATM, NH, BATCH), 256, ATTN_SMEM_BYTES>>>(q, k, v, o);

    gemm_nt_kernel<<<gg, 256>>>(o, wo, out, ROWS, DIM, DIM);
}

// round 3
// speedup vs baseline: 1.5703x; 1.5703x over previous
#include <cuda_runtime.h>
#include <cuda_bf16.h>
#include <cstdint>

#define BATCH 2
#define SEQ   2048
#define DIM   2048
#define NH    16
#define HD    128
#define ROWS  (BATCH*SEQ)   // 4096

// ---------------- scratch (static device globals; no allocs allowed) --------
__device__ float g_q[ROWS*DIM];
__device__ float g_k[ROWS*DIM];
__device__ float g_v[ROWS*DIM];
__device__ float g_o[ROWS*DIM];

__device__ __nv_bfloat16 g_xhi[ROWS*DIM];
__device__ __nv_bfloat16 g_xlo[ROWS*DIM];
__device__ __nv_bfloat16 g_ohi[ROWS*DIM];
__device__ __nv_bfloat16 g_olo[ROWS*DIM];
__device__ __nv_bfloat16 g_whi[4][DIM*DIM];   // q,k,v,o
__device__ __nv_bfloat16 g_wlo[4][DIM*DIM];

// ---------------- fp32 -> bf16 hi/lo split ----------------------------------
__global__ void split_kernel(const float* __restrict__ in,
                             __nv_bfloat16* __restrict__ hi,
                             __nv_bfloat16* __restrict__ lo, int n4)
{
    int idx = blockIdx.x * blockDim.x + threadIdx.x;
    if (idx >= n4) return;
    float4 v = ((const float4*)in)[idx];
    __nv_bfloat16 h0 = __float2bfloat16(v.x);
    __nv_bfloat16 h1 = __float2bfloat16(v.y);
    __nv_bfloat16 h2 = __float2bfloat16(v.z);
    __nv_bfloat16 h3 = __float2bfloat16(v.w);
    __nv_bfloat16 l0 = __float2bfloat16(v.x - __bfloat162float(h0));
    __nv_bfloat16 l1 = __float2bfloat16(v.y - __bfloat162float(h1));
    __nv_bfloat16 l2 = __float2bfloat16(v.z - __bfloat162float(h2));
    __nv_bfloat16 l3 = __float2bfloat16(v.w - __bfloat162float(h3));
    ((__nv_bfloat162*)hi)[idx*2+0] = __nv_bfloat162(h0, h1);
    ((__nv_bfloat162*)hi)[idx*2+1] = __nv_bfloat162(h2, h3);
    ((__nv_bfloat162*)lo)[idx*2+0] = __nv_bfloat162(l0, l1);
    ((__nv_bfloat162*)lo)[idx*2+1] = __nv_bfloat162(l2, l3);
}

// ============================================================================
// bf16x3 tensor-core GEMM: C[M,N] = (Ahi+Alo)[M,K] * ((Bhi+Blo)[N,K])^T
// 128x128x32 CTA tile, 8 warps (2m x 4n), warp tile 64x32, mma.m16n8k16.bf16
// ============================================================================
#define BM 128
#define BN 128
#define BK 32
#define HSTR 40                    // smem row stride in halfs (80B, conflict-free)
#define TILE_H (BM*HSTR)           // 5120 halfs per tile buffer
#define GEMM_SMEM_BYTES (8*TILE_H*2)   // 4 tiles x 2 bufs x 5120 halfs = 81920 B

__device__ __forceinline__ void cp_async16(void* smem, const void* gmem) {
    uint32_t s = (uint32_t)__cvta_generic_to_shared(smem);
    asm volatile("cp.async.cg.shared.global [%0], [%1], 16;\n" :: "r"(s), "l"(gmem));
}
#define CP_COMMIT() asm volatile("cp.async.commit_group;\n" ::: "memory")
#define CP_WAIT1()  asm volatile("cp.async.wait_group 1;\n" ::: "memory")
#define CP_WAIT0()  asm volatile("cp.async.wait_group 0;\n" ::: "memory")

__device__ __forceinline__ void mma_bf16(float* c, const uint32_t* a, const uint32_t* b) {
    asm volatile(
        "mma.sync.aligned.m16n8k16.row.col.f32.bf16.bf16.f32 "
        "{%0,%1,%2,%3}, {%4,%5,%6,%7}, {%8,%9}, {%0,%1,%2,%3};\n"
        : "+f"(c[0]), "+f"(c[1]), "+f"(c[2]), "+f"(c[3])
        : "r"(a[0]), "r"(a[1]), "r"(a[2]), "r"(a[3]),
          "r"(b[0]), "r"(b[1]));
}

__device__ __forceinline__ uint32_t lds32(const __nv_bfloat16* p) {
    return *(const uint32_t*)p;
}

__global__ void __launch_bounds__(256) gemm_bf16x3(
    const __nv_bfloat16* __restrict__ Ahi, const __nv_bfloat16* __restrict__ Alo,
    const __nv_bfloat16* __restrict__ Bhi, const __nv_bfloat16* __restrict__ Blo,
    float* __restrict__ C, int M, int N, int K)
{
    extern __shared__ __nv_bfloat16 smh[];
    __nv_bfloat16* sAh = smh;               // [2][TILE_H]
    __nv_bfloat16* sAl = smh + 2 * TILE_H;
    __nv_bfloat16* sBh = smh + 4 * TILE_H;
    __nv_bfloat16* sBl = smh + 6 * TILE_H;

    const int t    = threadIdx.x;
    const int lane = t & 31;
    const int wid  = t >> 5;
    const int gid  = lane >> 2;   // 0..7
    const int tig  = lane & 3;    // 0..3
    const int wm   = (wid & 1) * 64;
    const int wn   = (wid >> 1) * 32;
    const int m0   = blockIdx.y * BM;
    const int n0   = blockIdx.x * BN;

    // tile-load mapping: thread -> rows {r, r+64}, 16B chunk ci (8 halfs)
    const int r  = t >> 2;        // 0..63
    const int ci = t & 3;         // 0..3

    float acc[4][4][4];
#pragma unroll
    for (int i = 0; i < 4; i++)
#pragma unroll
        for (int j = 0; j < 4; j++)
#pragma unroll
            for (int e = 0; e < 4; e++) acc[i][j][e] = 0.f;

    const int NK = K / BK;
    int buf = 0;

#define LOAD_STAGE(BUFI, K0)                                                    \
    {                                                                           \
        _Pragma("unroll")                                                       \
        for (int rr = 0; rr < 2; rr++) {                                        \
            int row = r + rr * 64;                                              \
            size_t ga = (size_t)(m0 + row) * K + (K0) + ci * 8;                 \
            size_t gb = (size_t)(n0 + row) * K + (K0) + ci * 8;                 \
            int so = (BUFI) * TILE_H + row * HSTR + ci * 8;                     \
            cp_async16(sAh + so, Ahi + ga);                                     \
            cp_async16(sAl + so, Alo + ga);                                     \
            cp_async16(sBh + so, Bhi + gb);                                     \
            cp_async16(sBl + so, Blo + gb);                                     \
        }                                                                       \
        CP_COMMIT();                                                            \
    }

    LOAD_STAGE(0, 0);

    for (int kt = 0; kt < NK; kt++) {
        if (kt + 1 < NK) {
            LOAD_STAGE(buf ^ 1, (kt + 1) * BK);
            CP_WAIT1();
        } else {
            CP_WAIT0();
        }
        __syncthreads();

        const int base = buf * TILE_H;
#pragma unroll
        for (int kk = 0; kk < 2; kk++) {
            uint32_t ah[4][4], al[4][4], bh[4][2], bl[4][2];
#pragma unroll
            for (int ms = 0; ms < 4; ms++) {
                int off = base + (wm + ms * 16 + gid) * HSTR + kk * 16 + 2 * tig;
                ah[ms][0] = lds32(sAh + off);
                ah[ms][1] = lds32(sAh + off + 8 * HSTR);
                ah[ms][2] = lds32(sAh + off + 8);
                ah[ms][3] = lds32(sAh + off + 8 * HSTR + 8);
                al[ms][0] = lds32(sAl + off);
                al[ms][1] = lds32(sAl + off + 8 * HSTR);
                al[ms][2] = lds32(sAl + off + 8);
                al[ms][3] = lds32(sAl + off + 8 * HSTR + 8);
            }
#pragma unroll
            for (int ns = 0; ns < 4; ns++) {
                int off = base + (wn + ns * 8 + gid) * HSTR + kk * 16 + 2 * tig;
                bh[ns][0] = lds32(sBh + off);
                bh[ns][1] = lds32(sBh + off + 8);
                bl[ns][0] = lds32(sBl + off);
                bl[ns][1] = lds32(sBl + off + 8);
            }
#pragma unroll
            for (int ms = 0; ms < 4; ms++)
#pragma unroll
                for (int ns = 0; ns < 4; ns++) {
                    mma_bf16(acc[ms][ns], ah[ms], bh[ns]);
                    mma_bf16(acc[ms][ns], ah[ms], bl[ns]);
                    mma_bf16(acc[ms][ns], al[ms], bh[ns]);
                }
        }
        __syncthreads();
        buf ^= 1;
    }

    // epilogue (m16n8 C layout: c01 at (gid, 2tig), c23 at (gid+8, 2tig))
#pragma unroll
    for (int ms = 0; ms < 4; ms++) {
#pragma unroll
        for (int ns = 0; ns < 4; ns++) {
            int row = m0 + wm + ms * 16 + gid;
            int col = n0 + wn + ns * 8 + tig * 2;
            float2 c0 = {acc[ms][ns][0], acc[ms][ns][1]};
            float2 c1 = {acc[ms][ns][2], acc[ms][ns][3]};
            *(float2*)&C[(size_t)row * N + col]       = c0;
            *(float2*)&C[(size_t)(row + 8) * N + col] = c1;
        }
    }
}

// ---------------- RoPE (in-place, float2 = one (re,im) pair) ----------------
__global__ void rope_kernel(float* __restrict__ a,
                            const float* __restrict__ fc,
                            const float* __restrict__ fs)
{
    int idx = blockIdx.x * blockDim.x + threadIdx.x;
    int i = idx & 63;
    int s = (idx >> 10) & (SEQ - 1);
    float2 v = ((float2*)a)[idx];
    float c  = fc[s * 64 + i];
    float sn = fs[s * 64 + i];
    float2 rr;
    rr.x = v.x * c - v.y * sn;
    rr.y = v.x * sn + v.y * c;
    ((float2*)a)[idx] = rr;
}

// ---------------- streaming causal attention (flash-style, fp32) ------------
#define ATM 64
#define ATN 64
#define QS  132
#define PS  68
#define ATTN_SMEM_FLOATS (3*ATM*QS + ATM*PS + 3*ATM)
#define ATTN_SMEM_BYTES  (ATTN_SMEM_FLOATS * 4)

__global__ void __launch_bounds__(256) attn_kernel(
    const float* __restrict__ q, const float* __restrict__ k,
    const float* __restrict__ v, float* __restrict__ o)
{
    extern __shared__ float sm[];
    float* Qs   = sm;
    float* Ks   = Qs + ATM * QS;
    float* Vs   = Ks + ATN * QS;
    float* Pp   = Vs + ATN * QS;
    float* mrow = Pp + ATM * PS;
    float* lrow = mrow + ATM;
    float* arow = lrow + ATM;

    const int t  = threadIdx.x;
    const int qt = blockIdx.x, h = blockIdx.y, b = blockIdx.z;
    const size_t head = ((size_t)b * SEQ) * DIM + (size_t)h * HD;

    for (int idx = t; idx < ATM * 32; idx += 256) {
        int r = idx >> 5, c4 = (idx & 31) << 2;
        *(float4*)(Qs + r * QS + c4) =
            *(const float4*)(q + head + (size_t)(qt * ATM + r) * DIM + c4);
    }
    if (t < ATM) { mrow[t] = -1e30f; lrow[t] = 0.f; }

    float oa[16], ob[16];
#pragma unroll
    for (int i = 0; i < 16; i++) { oa[i] = 0.f; ob[i] = 0.f; }
    const int pr = t >> 3;
    const int cg = t & 7;
    const int tym = t >> 4, txm = t & 15;
    const float scale = 0.08838834764831845f;

    for (int kt = 0; kt <= qt; kt++) {
        __syncthreads();
        for (int idx = t; idx < ATN * 32; idx += 256) {
            int r = idx >> 5, c4 = (idx & 31) << 2;
            size_t g = head + (size_t)(kt * ATN + r) * DIM + c4;
            *(float4*)(Ks + r * QS + c4) = *(const float4*)(k + g);
            *(float4*)(Vs + r * QS + c4) = *(const float4*)(v + g);
        }
        __syncthreads();

        {
            float acc[4][4];
#pragma unroll
            for (int i = 0; i < 4; i++)
#pragma unroll
                for (int j = 0; j < 4; j++) acc[i][j] = 0.f;

            for (int d = 0; d < HD; d += 4) {
                float4 qa[4], kb[4];
#pragma unroll
                for (int i = 0; i < 4; i++)
                    qa[i] = *(const float4*)(Qs + (tym + 16 * i) * QS + d);
#pragma unroll
                for (int j = 0; j < 4; j++)
                    kb[j] = *(const float4*)(Ks + (txm + 16 * j) * QS + d);
#pragma unroll
                for (int i = 0; i < 4; i++)
#pragma unroll
                    for (int j = 0; j < 4; j++)
                        acc[i][j] += qa[i].x * kb[j].x + qa[i].y * kb[j].y
                                   + qa[i].z * kb[j].z + qa[i].w * kb[j].w;
            }
#pragma unroll
            for (int i = 0; i < 4; i++) {
                int rq = tym + 16 * i;
                int qg = qt * ATM + rq;
#pragma unroll
                for (int j = 0; j < 4; j++) {
                    int rc = txm + 16 * j;
                    float sc = acc[i][j] * scale;
                    if (kt * ATN + rc > qg) sc -= 1e9f;
                    Pp[rq * PS + rc] = sc;
                }
            }
        }
        __syncthreads();

        if (t < ATM) {
            float* prow = Pp + t * PS;
            float mo = mrow[t];
            float mt = mo;
#pragma unroll 8
            for (int j = 0; j < ATN; j++) mt = fmaxf(mt, prow[j]);
            float al = __expf(mo - mt);
            float sum = 0.f;
#pragma unroll 8
            for (int j = 0; j < ATN; j++) {
                float p = __expf(prow[j] - mt);
                prow[j] = p;
                sum += p;
            }
            mrow[t] = mt;
            arow[t] = al;
            lrow[t] = lrow[t] * al + sum;
        }
        __syncthreads();

        {
            float al0 = arow[2 * pr], al1 = arow[2 * pr + 1];
#pragma unroll
            for (int i = 0; i < 16; i++) { oa[i] *= al0; ob[i] *= al1; }
            const float* p0 = Pp + (2 * pr) * PS;
            const float* p1 = p0 + PS;
#pragma unroll 4
            for (int kk = 0; kk < ATN; kk++) {
                float w0 = p0[kk], w1 = p1[kk];
                const float* vr = Vs + kk * QS;
#pragma unroll
                for (int jj = 0; jj < 4; jj++) {
                    float4 vv = *(const float4*)(vr + cg * 4 + jj * 32);
                    oa[jj*4+0] += w0 * vv.x; oa[jj*4+1] += w0 * vv.y;
                    oa[jj*4+2] += w0 * vv.z; oa[jj*4+3] += w0 * vv.w;
                    ob[jj*4+0] += w1 * vv.x; ob[jj*4+1] += w1 * vv.y;
                    ob[jj*4+2] += w1 * vv.z; ob[jj*4+3] += w1 * vv.w;
                }
            }
        }
    }

    float li0 = 1.f / lrow[2 * pr];
    float li1 = 1.f / lrow[2 * pr + 1];
    size_t o0 = head + (size_t)(qt * ATM + 2 * pr) * DIM;
#pragma unroll
    for (int jj = 0; jj < 4; jj++) {
        float4 w0 = {oa[jj*4+0]*li0, oa[jj*4+1]*li0, oa[jj*4+2]*li0, oa[jj*4+3]*li0};
        float4 w1 = {ob[jj*4+0]*li1, ob[jj*4+1]*li1, ob[jj*4+2]*li1, ob[jj*4+3]*li1};
        *(float4*)(o + o0 + cg * 4 + jj * 32)       = w0;
        *(float4*)(o + o0 + DIM + cg * 4 + jj * 32) = w1;
    }
}

// ---------------- launcher ---------------------------------------------------
extern "C" void kernel_launch(void* const* d_in, const int* in_sizes, int n_in,
                              void* d_out, int out_size)
{
    const float* x    = (const float*)d_in[0];
    const float* w[4] = {(const float*)d_in[1], (const float*)d_in[2],
                         (const float*)d_in[3], (const float*)d_in[4]};
    const float* fcos = (const float*)d_in[5];
    const float* fsin = (const float*)d_in[6];
    float* out = (float*)d_out;

    float *q, *k, *v, *o;
    cudaGetSymbolAddress((void**)&q, g_q);
    cudaGetSymbolAddress((void**)&k, g_k);
    cudaGetSymbolAddress((void**)&v, g_v);
    cudaGetSymbolAddress((void**)&o, g_o);

    __nv_bfloat16 *xhi, *xlo, *ohi, *olo, *whi, *wlo;
    cudaGetSymbolAddress((void**)&xhi, g_xhi);
    cudaGetSymbolAddress((void**)&xlo, g_xlo);
    cudaGetSymbolAddress((void**)&ohi, g_ohi);
    cudaGetSymbolAddress((void**)&olo, g_olo);
    cudaGetSymbolAddress((void**)&whi, g_whi);
    cudaGetSymbolAddress((void**)&wlo, g_wlo);

    cudaFuncSetAttribute(gemm_bf16x3,
                         cudaFuncAttributeMaxDynamicSharedMemorySize,
                         GEMM_SMEM_BYTES);
    cudaFuncSetAttribute(attn_kernel,
                         cudaFuncAttributeMaxDynamicSharedMemorySize,
                         ATTN_SMEM_BYTES);

    // split x and weights
    int nx4 = ROWS * DIM / 4;
    int nw4 = DIM * DIM / 4;
    split_kernel<<<nx4 / 256, 256>>>(x, xhi, xlo, nx4);
    for (int i = 0; i < 4; i++)
        split_kernel<<<nw4 / 256, 256>>>(w[i], whi + (size_t)i * DIM * DIM,
                                         wlo + (size_t)i * DIM * DIM, nw4);

    dim3 gg(DIM / BN, ROWS / BM);   // (16, 32)

    gemm_bf16x3<<<gg, 256, GEMM_SMEM_BYTES>>>(xhi, xlo, whi + 0*(size_t)DIM*DIM,
                                              wlo + 0*(size_t)DIM*DIM, q, ROWS, DIM, DIM);
    gemm_bf16x3<<<gg, 256, GEMM_SMEM_BYTES>>>(xhi, xlo, whi + 1*(size_t)DIM*DIM,
                                              wlo + 1*(size_t)DIM*DIM, k, ROWS, DIM, DIM);
    gemm_bf16x3<<<gg, 256, GEMM_SMEM_BYTES>>>(xhi, xlo, whi + 2*(size_t)DIM*DIM,
                                              wlo + 2*(size_t)DIM*DIM, v, ROWS, DIM, DIM);

    int npairs = ROWS * DIM / 2;
    rope_kernel<<<npairs / 256, 256>>>(q, fcos, fsin);
    rope_kernel<<<npairs / 256, 256>>>(k, fcos, fsin);

    attn_kernel<<<dim3(SEQ / ATM, NH, BATCH), 256, ATTN_SMEM_BYTES>>>(q, k, v, o);

    split_kernel<<<nx4 / 256, 256>>>(o, ohi, olo, nx4);
    gemm_bf16x3<<<gg, 256, GEMM_SMEM_BYTES>>>(ohi, olo, whi + 3*(size_t)DIM*DIM,
                                              wlo + 3*(size_t)DIM*DIM, out, ROWS, DIM, DIM);
}

// round 4
// speedup vs baseline: 2.1798x; 1.3882x over previous
#include <cuda_runtime.h>
#include <cuda_bf16.h>
#include <cstdint>

#define BATCH 2
#define SEQ   2048
#define DIM   2048
#define NH    16
#define HD    128
#define ROWS  (BATCH*SEQ)   // 4096

// ---------------- scratch (static device globals; no allocs allowed) --------
__device__ float g_q[ROWS*DIM];
__device__ float g_k[ROWS*DIM];
__device__ float g_v[ROWS*DIM];
__device__ float g_o[ROWS*DIM];

__device__ __nv_bfloat16 g_xhi[ROWS*DIM];
__device__ __nv_bfloat16 g_xlo[ROWS*DIM];
__device__ __nv_bfloat16 g_ohi[ROWS*DIM];
__device__ __nv_bfloat16 g_olo[ROWS*DIM];
__device__ __nv_bfloat16 g_whi[4][DIM*DIM];   // q,k,v,o
__device__ __nv_bfloat16 g_wlo[4][DIM*DIM];

__device__ __nv_bfloat16 g_qhi[ROWS*DIM];
__device__ __nv_bfloat16 g_qlo[ROWS*DIM];
__device__ __nv_bfloat16 g_khi[ROWS*DIM];
__device__ __nv_bfloat16 g_klo[ROWS*DIM];
__device__ __nv_bfloat16 g_vthi[ROWS*DIM];    // per-head transposed [b,h,d,s]
__device__ __nv_bfloat16 g_vtlo[ROWS*DIM];

// ---------------- fp32 -> bf16 hi/lo split ----------------------------------
__global__ void split_kernel(const float* __restrict__ in,
                             __nv_bfloat16* __restrict__ hi,
                             __nv_bfloat16* __restrict__ lo, int n4)
{
    int idx = blockIdx.x * blockDim.x + threadIdx.x;
    if (idx >= n4) return;
    float4 v = ((const float4*)in)[idx];
    __nv_bfloat16 h0 = __float2bfloat16(v.x);
    __nv_bfloat16 h1 = __float2bfloat16(v.y);
    __nv_bfloat16 h2 = __float2bfloat16(v.z);
    __nv_bfloat16 h3 = __float2bfloat16(v.w);
    __nv_bfloat16 l0 = __float2bfloat16(v.x - __bfloat162float(h0));
    __nv_bfloat16 l1 = __float2bfloat16(v.y - __bfloat162float(h1));
    __nv_bfloat16 l2 = __float2bfloat16(v.z - __bfloat162float(h2));
    __nv_bfloat16 l3 = __float2bfloat16(v.w - __bfloat162float(h3));
    ((__nv_bfloat162*)hi)[idx*2+0] = __nv_bfloat162(h0, h1);
    ((__nv_bfloat162*)hi)[idx*2+1] = __nv_bfloat162(h2, h3);
    ((__nv_bfloat162*)lo)[idx*2+0] = __nv_bfloat162(l0, l1);
    ((__nv_bfloat162*)lo)[idx*2+1] = __nv_bfloat162(l2, l3);
}

// ---------------- RoPE + split: fp32 in -> rotated bf16 hi/lo out -----------
__global__ void rope_split_kernel(const float* __restrict__ a,
                                  const float* __restrict__ fc,
                                  const float* __restrict__ fs,
                                  __nv_bfloat16* __restrict__ hi,
                                  __nv_bfloat16* __restrict__ lo)
{
    int idx = blockIdx.x * blockDim.x + threadIdx.x;   // pair index
    int i = idx & 63;
    int s = (idx >> 10) & (SEQ - 1);
    float2 v = ((const float2*)a)[idx];
    float c  = fc[s * 64 + i];
    float sn = fs[s * 64 + i];
    float rx = v.x * c - v.y * sn;
    float ry = v.x * sn + v.y * c;
    __nv_bfloat16 hx = __float2bfloat16(rx);
    __nv_bfloat16 hy = __float2bfloat16(ry);
    __nv_bfloat16 lx = __float2bfloat16(rx - __bfloat162float(hx));
    __nv_bfloat16 ly = __float2bfloat16(ry - __bfloat162float(hy));
    ((__nv_bfloat162*)hi)[idx] = __nv_bfloat162(hx, hy);
    ((__nv_bfloat162*)lo)[idx] = __nv_bfloat162(lx, ly);
}

// ---------------- V transpose + split: [b,s,h,d] -> [b,h,d,s] bf16 hi/lo ----
__global__ void vtrans_split_kernel(const float* __restrict__ v,
                                    __nv_bfloat16* __restrict__ vthi,
                                    __nv_bfloat16* __restrict__ vtlo)
{
    __shared__ float tile[32][33];
    int c0 = blockIdx.x * 32, s0 = blockIdx.y * 32;
    int tx = threadIdx.x, ty = threadIdx.y;
#pragma unroll
    for (int i = 0; i < 4; i++)
        tile[ty + 8*i][tx] = v[(size_t)(s0 + ty + 8*i) * DIM + c0 + tx];
    __syncthreads();
    int sg = s0 + tx;
    int b  = sg >> 11;            // / SEQ
    int sl = sg & (SEQ - 1);
#pragma unroll
    for (int i = 0; i < 4; i++) {
        int cg = c0 + ty + 8*i;
        int h  = cg >> 7;
        int d  = cg & 127;
        float val = tile[tx][ty + 8*i];
        __nv_bfloat16 hv = __float2bfloat16(val);
        __nv_bfloat16 lv = __float2bfloat16(val - __bfloat162float(hv));
        size_t o = ((size_t)((b * NH + h) * HD + d)) * SEQ + sl;
        vthi[o] = hv;
        vtlo[o] = lv;
    }
}

// ============================================================================
// common mma / cp.async helpers
// ============================================================================
__device__ __forceinline__ void cp_async16(void* smem, const void* gmem) {
    uint32_t s = (uint32_t)__cvta_generic_to_shared(smem);
    asm volatile("cp.async.cg.shared.global [%0], [%1], 16;\n" :: "r"(s), "l"(gmem));
}
#define CP_COMMIT() asm volatile("cp.async.commit_group;\n" ::: "memory")
#define CP_WAIT1()  asm volatile("cp.async.wait_group 1;\n" ::: "memory")
#define CP_WAIT0()  asm volatile("cp.async.wait_group 0;\n" ::: "memory")

__device__ __forceinline__ void mma_bf16(float* c, const uint32_t* a, const uint32_t* b) {
    asm volatile(
        "mma.sync.aligned.m16n8k16.row.col.f32.bf16.bf16.f32 "
        "{%0,%1,%2,%3}, {%4,%5,%6,%7}, {%8,%9}, {%0,%1,%2,%3};\n"
        : "+f"(c[0]), "+f"(c[1]), "+f"(c[2]), "+f"(c[3])
        : "r"(a[0]), "r"(a[1]), "r"(a[2]), "r"(a[3]),
          "r"(b[0]), "r"(b[1]));
}
__device__ __forceinline__ uint32_t lds32(const __nv_bfloat16* p) {
    return *(const uint32_t*)p;
}

// ============================================================================
// bf16x3 tensor-core GEMM: C[M,N] = (Ahi+Alo)[M,K] * ((Bhi+Blo)[N,K])^T
// ============================================================================
#define BM 128
#define BN 128
#define BK 32
#define HSTR 40
#define TILE_H (BM*HSTR)
#define GEMM_SMEM_BYTES (8*TILE_H*2)

__global__ void __launch_bounds__(256) gemm_bf16x3(
    const __nv_bfloat16* __restrict__ Ahi, const __nv_bfloat16* __restrict__ Alo,
    const __nv_bfloat16* __restrict__ Bhi, const __nv_bfloat16* __restrict__ Blo,
    float* __restrict__ C, int M, int N, int K)
{
    extern __shared__ __nv_bfloat16 smh[];
    __nv_bfloat16* sAh = smh;
    __nv_bfloat16* sAl = smh + 2 * TILE_H;
    __nv_bfloat16* sBh = smh + 4 * TILE_H;
    __nv_bfloat16* sBl = smh + 6 * TILE_H;

    const int t    = threadIdx.x;
    const int lane = t & 31;
    const int wid  = t >> 5;
    const int gid  = lane >> 2;
    const int tig  = lane & 3;
    const int wm   = (wid & 1) * 64;
    const int wn   = (wid >> 1) * 32;
    const int m0   = blockIdx.y * BM;
    const int n0   = blockIdx.x * BN;

    const int r  = t >> 2;
    const int ci = t & 3;

    float acc[4][4][4];
#pragma unroll
    for (int i = 0; i < 4; i++)
#pragma unroll
        for (int j = 0; j < 4; j++)
#pragma unroll
            for (int e = 0; e < 4; e++) acc[i][j][e] = 0.f;

    const int NK = K / BK;
    int buf = 0;

#define LOAD_STAGE(BUFI, K0)                                                    \
    {                                                                           \
        _Pragma("unroll")                                                       \
        for (int rr = 0; rr < 2; rr++) {                                        \
            int row = r + rr * 64;                                              \
            size_t ga = (size_t)(m0 + row) * K + (K0) + ci * 8;                 \
            size_t gb = (size_t)(n0 + row) * K + (K0) + ci * 8;                 \
            int so = (BUFI) * TILE_H + row * HSTR + ci * 8;                     \
            cp_async16(sAh + so, Ahi + ga);                                     \
            cp_async16(sAl + so, Alo + ga);                                     \
            cp_async16(sBh + so, Bhi + gb);                                     \
            cp_async16(sBl + so, Blo + gb);                                     \
        }                                                                       \
        CP_COMMIT();                                                            \
    }

    LOAD_STAGE(0, 0);

    for (int kt = 0; kt < NK; kt++) {
        if (kt + 1 < NK) {
            LOAD_STAGE(buf ^ 1, (kt + 1) * BK);
            CP_WAIT1();
        } else {
            CP_WAIT0();
        }
        __syncthreads();

        const int base = buf * TILE_H;
#pragma unroll
        for (int kk = 0; kk < 2; kk++) {
            uint32_t ah[4][4], al[4][4], bh[4][2], bl[4][2];
#pragma unroll
            for (int ms = 0; ms < 4; ms++) {
                int off = base + (wm + ms * 16 + gid) * HSTR + kk * 16 + 2 * tig;
                ah[ms][0] = lds32(sAh + off);
                ah[ms][1] = lds32(sAh + off + 8 * HSTR);
                ah[ms][2] = lds32(sAh + off + 8);
                ah[ms][3] = lds32(sAh + off + 8 * HSTR + 8);
                al[ms][0] = lds32(sAl + off);
                al[ms][1] = lds32(sAl + off + 8 * HSTR);
                al[ms][2] = lds32(sAl + off + 8);
                al[ms][3] = lds32(sAl + off + 8 * HSTR + 8);
            }
#pragma unroll
            for (int ns = 0; ns < 4; ns++) {
                int off = base + (wn + ns * 8 + gid) * HSTR + kk * 16 + 2 * tig;
                bh[ns][0] = lds32(sBh + off);
                bh[ns][1] = lds32(sBh + off + 8);
                bl[ns][0] = lds32(sBl + off);
                bl[ns][1] = lds32(sBl + off + 8);
            }
#pragma unroll
            for (int ms = 0; ms < 4; ms++)
#pragma unroll
                for (int ns = 0; ns < 4; ns++) {
                    mma_bf16(acc[ms][ns], ah[ms], bh[ns]);
                    mma_bf16(acc[ms][ns], ah[ms], bl[ns]);
                    mma_bf16(acc[ms][ns], al[ms], bh[ns]);
                }
        }
        __syncthreads();
        buf ^= 1;
    }

#pragma unroll
    for (int ms = 0; ms < 4; ms++) {
#pragma unroll
        for (int ns = 0; ns < 4; ns++) {
            int row = m0 + wm + ms * 16 + gid;
            int col = n0 + wn + ns * 8 + tig * 2;
            float2 c0 = {acc[ms][ns][0], acc[ms][ns][1]};
            float2 c1 = {acc[ms][ns][2], acc[ms][ns][3]};
            *(float2*)&C[(size_t)row * N + col]       = c0;
            *(float2*)&C[(size_t)(row + 8) * N + col] = c1;
        }
    }
}

// ============================================================================
// tensor-core flash attention, bf16x3 compensated, causal
// tile: 128 q-rows x 64 k-cols, 8 warps, HD=128
// ============================================================================
#define AQ  128
#define AK  64
#define AHS 136    // Q/K smem row stride (halfs)
#define AVS 72     // Vt smem row stride (halfs)
// smem offsets in halfs
#define A_QH        0
#define A_QL        17408
#define A_KH(bf)    (34816 + (bf)*8704)
#define A_KL(bf)    (52224 + (bf)*8704)
#define A_VH(bf)    (69632 + (bf)*9216)
#define A_VL(bf)    (88064 + (bf)*9216)
#define ATTN_SMEM_BYTES (106496*2)   // 212992 B

__global__ void __launch_bounds__(256) attn_tc_kernel(
    const __nv_bfloat16* __restrict__ qhi, const __nv_bfloat16* __restrict__ qlo,
    const __nv_bfloat16* __restrict__ khi, const __nv_bfloat16* __restrict__ klo,
    const __nv_bfloat16* __restrict__ vthi, const __nv_bfloat16* __restrict__ vtlo,
    float* __restrict__ o)
{
    extern __shared__ __nv_bfloat16 smh[];

    const int t    = threadIdx.x;
    const int lane = t & 31;
    const int wid  = t >> 5;      // 0..7
    const int gid  = lane >> 2;   // 0..7
    const int tig  = lane & 3;    // 0..3
    const int qt = blockIdx.x, h = blockIdx.y, b = blockIdx.z;

    // ---- load Q tile (hi+lo), rows 0..127, 16 chunks/row ----
    {
        int row = t >> 1;
        int cb  = (t & 1) * 8;
        size_t g = (size_t)(b * SEQ + qt * AQ + row) * DIM + h * HD + cb * 8;
        int so = row * AHS + cb * 8;
#pragma unroll
        for (int c = 0; c < 8; c++) {
            cp_async16(smh + A_QH + so + c * 8, qhi + g + c * 8);
            cp_async16(smh + A_QL + so + c * 8, qlo + g + c * 8);
        }
    }

#define LOAD_KV(BUFI, KT)                                                       \
    {                                                                           \
        int row = t >> 2;                                                       \
        int cb  = (t & 3) * 4;                                                  \
        size_t g = (size_t)(b * SEQ + (KT) * AK + row) * DIM + h * HD + cb * 8; \
        int so = row * AHS + cb * 8;                                            \
        _Pragma("unroll")                                                       \
        for (int c = 0; c < 4; c++) {                                           \
            cp_async16(smh + A_KH(BUFI) + so + c * 8, khi + g + c * 8);         \
            cp_async16(smh + A_KL(BUFI) + so + c * 8, klo + g + c * 8);         \
        }                                                                       \
        int vrow = t >> 1;                                                      \
        int vcb  = (t & 1) * 4;                                                 \
        size_t gv = (size_t)((b * NH + h) * HD + vrow) * SEQ + (KT) * AK + vcb * 8; \
        int sv = vrow * AVS + vcb * 8;                                          \
        _Pragma("unroll")                                                       \
        for (int c = 0; c < 4; c++) {                                           \
            cp_async16(smh + A_VH(BUFI) + sv + c * 8, vthi + gv + c * 8);       \
            cp_async16(smh + A_VL(BUFI) + sv + c * 8, vtlo + gv + c * 8);       \
        }                                                                       \
    }

    LOAD_KV(0, 0);
    CP_COMMIT();

    float sacc[8][4];
    float oacc[16][4];
#pragma unroll
    for (int i = 0; i < 16; i++)
#pragma unroll
        for (int e = 0; e < 4; e++) oacc[i][e] = 0.f;
    float m0 = -1e30f, m1 = -1e30f, l0 = 0.f, l1 = 0.f;

    const float scale = 0.08838834764831845f;   // 1/sqrt(128)
    const int gr0 = qt * AQ + wid * 16 + gid;   // global q row (c0,c1)
    const int ktmax = 2 * qt + 1;
    int buf = 0;

    for (int kt = 0; kt <= ktmax; kt++) {
        if (kt < ktmax) {
            LOAD_KV(buf ^ 1, kt + 1);
            CP_COMMIT();
            CP_WAIT1();
        } else {
            CP_WAIT0();
        }
        __syncthreads();

        // ---- S = Q K^T (bf16x3) ----
#pragma unroll
        for (int ns = 0; ns < 8; ns++)
#pragma unroll
            for (int e = 0; e < 4; e++) sacc[ns][e] = 0.f;

        const __nv_bfloat16* kh = smh + A_KH(buf);
        const __nv_bfloat16* kl = smh + A_KL(buf);
#pragma unroll
        for (int kk = 0; kk < 8; kk++) {
            int ao = (wid * 16 + gid) * AHS + kk * 16 + 2 * tig;
            uint32_t ah[4], al[4];
            ah[0] = lds32(smh + A_QH + ao);
            ah[1] = lds32(smh + A_QH + ao + 8 * AHS);
            ah[2] = lds32(smh + A_QH + ao + 8);
            ah[3] = lds32(smh + A_QH + ao + 8 * AHS + 8);
            al[0] = lds32(smh + A_QL + ao);
            al[1] = lds32(smh + A_QL + ao + 8 * AHS);
            al[2] = lds32(smh + A_QL + ao + 8);
            al[3] = lds32(smh + A_QL + ao + 8 * AHS + 8);
#pragma unroll
            for (int ns = 0; ns < 8; ns++) {
                int bo = (ns * 8 + gid) * AHS + kk * 16 + 2 * tig;
                uint32_t bh[2] = {lds32(kh + bo), lds32(kh + bo + 8)};
                uint32_t bl[2] = {lds32(kl + bo), lds32(kl + bo + 8)};
                mma_bf16(sacc[ns], ah, bh);
                mma_bf16(sacc[ns], al, bh);
                mma_bf16(sacc[ns], ah, bl);
            }
        }

        // ---- scale + causal mask ----
        if (kt * AK + 63 > qt * AQ + wid * 16) {
            int rl0 = gr0 - kt * AK;
            int rl1 = rl0 + 8;
#pragma unroll
            for (int ns = 0; ns < 8; ns++) {
#pragma unroll
                for (int e = 0; e < 4; e++) {
                    float v = sacc[ns][e] * scale;
                    int cl = ns * 8 + 2 * tig + (e & 1);
                    int rl = (e < 2) ? rl0 : rl1;
                    sacc[ns][e] = (cl > rl) ? -1e30f : v;
                }
            }
        } else {
#pragma unroll
            for (int ns = 0; ns < 8; ns++)
#pragma unroll
                for (int e = 0; e < 4; e++) sacc[ns][e] *= scale;
        }

        // ---- online softmax (rows warp-local) ----
        float mx0 = -1e30f, mx1 = -1e30f;
#pragma unroll
        for (int ns = 0; ns < 8; ns++) {
            mx0 = fmaxf(mx0, fmaxf(sacc[ns][0], sacc[ns][1]));
            mx1 = fmaxf(mx1, fmaxf(sacc[ns][2], sacc[ns][3]));
        }
        mx0 = fmaxf(mx0, __shfl_xor_sync(0xffffffffu, mx0, 1));
        mx0 = fmaxf(mx0, __shfl_xor_sync(0xffffffffu, mx0, 2));
        mx1 = fmaxf(mx1, __shfl_xor_sync(0xffffffffu, mx1, 1));
        mx1 = fmaxf(mx1, __shfl_xor_sync(0xffffffffu, mx1, 2));
        float mn0 = fmaxf(m0, mx0), mn1 = fmaxf(m1, mx1);
        float a0 = __expf(m0 - mn0), a1 = __expf(m1 - mn1);
        m0 = mn0; m1 = mn1;

        float sum0 = 0.f, sum1 = 0.f;
#pragma unroll
        for (int ns = 0; ns < 8; ns++) {
            float p0 = __expf(sacc[ns][0] - mn0);
            float p1 = __expf(sacc[ns][1] - mn0);
            float p2 = __expf(sacc[ns][2] - mn1);
            float p3 = __expf(sacc[ns][3] - mn1);
            sacc[ns][0] = p0; sacc[ns][1] = p1;
            sacc[ns][2] = p2; sacc[ns][3] = p3;
            sum0 += p0 + p1; sum1 += p2 + p3;
        }
        sum0 += __shfl_xor_sync(0xffffffffu, sum0, 1);
        sum0 += __shfl_xor_sync(0xffffffffu, sum0, 2);
        sum1 += __shfl_xor_sync(0xffffffffu, sum1, 1);
        sum1 += __shfl_xor_sync(0xffffffffu, sum1, 2);
        l0 = l0 * a0 + sum0;
        l1 = l1 * a1 + sum1;

#pragma unroll
        for (int nd = 0; nd < 16; nd++) {
            oacc[nd][0] *= a0; oacc[nd][1] *= a0;
            oacc[nd][2] *= a1; oacc[nd][3] *= a1;
        }

        // ---- O += P V (bf16x3; P split in-register) ----
        const __nv_bfloat16* vh = smh + A_VH(buf);
        const __nv_bfloat16* vl = smh + A_VL(buf);
#pragma unroll
        for (int kc = 0; kc < 4; kc++) {
            uint32_t ph[4], pl[4];
#pragma unroll
            for (int j = 0; j < 4; j++) {
                int ns = 2 * kc + (j >> 1);
                int e0 = (j & 1) * 2;
                float c0 = sacc[ns][e0], c1 = sacc[ns][e0 + 1];
                __nv_bfloat162 hb = __floats2bfloat162_rn(c0, c1);
                uint32_t hu = *(uint32_t*)&hb;
                float f0 = __uint_as_float(hu << 16);
                float f1 = __uint_as_float(hu & 0xffff0000u);
                __nv_bfloat162 lb = __floats2bfloat162_rn(c0 - f0, c1 - f1);
                ph[j] = hu;
                pl[j] = *(uint32_t*)&lb;
            }
#pragma unroll
            for (int nd = 0; nd < 16; nd++) {
                int bo = (nd * 8 + gid) * AVS + kc * 16 + 2 * tig;
                uint32_t bh[2] = {lds32(vh + bo), lds32(vh + bo + 8)};
                uint32_t bl[2] = {lds32(vl + bo), lds32(vl + bo + 8)};
                mma_bf16(oacc[nd], ph, bh);
                mma_bf16(oacc[nd], pl, bh);
                mma_bf16(oacc[nd], ph, bl);
            }
        }
        __syncthreads();
        buf ^= 1;
    }

    // ---- normalize + store ----
    float i0 = 1.f / l0, i1 = 1.f / l1;
    size_t r0 = (size_t)(b * SEQ + gr0) * DIM + h * HD;
    size_t r1 = r0 + 8 * DIM;
#pragma unroll
    for (int nd = 0; nd < 16; nd++) {
        int col = nd * 8 + 2 * tig;
        float2 w0 = {oacc[nd][0] * i0, oacc[nd][1] * i0};
        float2 w1 = {oacc[nd][2] * i1, oacc[nd][3] * i1};
        *(float2*)&o[r0 + col] = w0;
        *(float2*)&o[r1 + col] = w1;
    }
}

// ---------------- launcher ---------------------------------------------------
extern "C" void kernel_launch(void* const* d_in, const int* in_sizes, int n_in,
                              void* d_out, int out_size)
{
    const float* x    = (const float*)d_in[0];
    const float* w[4] = {(const float*)d_in[1], (const float*)d_in[2],
                         (const float*)d_in[3], (const float*)d_in[4]};
    const float* fcos = (const float*)d_in[5];
    const float* fsin = (const float*)d_in[6];
    float* out = (float*)d_out;

    float *q, *k, *v, *o;
    cudaGetSymbolAddress((void**)&q, g_q);
    cudaGetSymbolAddress((void**)&k, g_k);
    cudaGetSymbolAddress((void**)&v, g_v);
    cudaGetSymbolAddress((void**)&o, g_o);

    __nv_bfloat16 *xhi, *xlo, *ohi, *olo, *whi, *wlo;
    __nv_bfloat16 *qhi, *qlo, *khi, *klo, *vthi, *vtlo;
    cudaGetSymbolAddress((void**)&xhi, g_xhi);
    cudaGetSymbolAddress((void**)&xlo, g_xlo);
    cudaGetSymbolAddress((void**)&ohi, g_ohi);
    cudaGetSymbolAddress((void**)&olo, g_olo);
    cudaGetSymbolAddress((void**)&whi, g_whi);
    cudaGetSymbolAddress((void**)&wlo, g_wlo);
    cudaGetSymbolAddress((void**)&qhi, g_qhi);
    cudaGetSymbolAddress((void**)&qlo, g_qlo);
    cudaGetSymbolAddress((void**)&khi, g_khi);
    cudaGetSymbolAddress((void**)&klo, g_klo);
    cudaGetSymbolAddress((void**)&vthi, g_vthi);
    cudaGetSymbolAddress((void**)&vtlo, g_vtlo);

    cudaFuncSetAttribute(gemm_bf16x3,
                         cudaFuncAttributeMaxDynamicSharedMemorySize,
                         GEMM_SMEM_BYTES);
    cudaFuncSetAttribute(attn_tc_kernel,
                         cudaFuncAttributeMaxDynamicSharedMemorySize,
                         ATTN_SMEM_BYTES);

    int nx4 = ROWS * DIM / 4;
    int nw4 = DIM * DIM / 4;
    split_kernel<<<nx4 / 256, 256>>>(x, xhi, xlo, nx4);
    for (int i = 0; i < 4; i++)
        split_kernel<<<nw4 / 256, 256>>>(w[i], whi + (size_t)i * DIM * DIM,
                                         wlo + (size_t)i * DIM * DIM, nw4);

    dim3 gg(DIM / BN, ROWS / BM);

    gemm_bf16x3<<<gg, 256, GEMM_SMEM_BYTES>>>(xhi, xlo, whi + 0*(size_t)DIM*DIM,
                                              wlo + 0*(size_t)DIM*DIM, q, ROWS, DIM, DIM);
    gemm_bf16x3<<<gg, 256, GEMM_SMEM_BYTES>>>(xhi, xlo, whi + 1*(size_t)DIM*DIM,
                                              wlo + 1*(size_t)DIM*DIM, k, ROWS, DIM, DIM);
    gemm_bf16x3<<<gg, 256, GEMM_SMEM_BYTES>>>(xhi, xlo, whi + 2*(size_t)DIM*DIM,
                                              wlo + 2*(size_t)DIM*DIM, v, ROWS, DIM, DIM);

    int npairs = ROWS * DIM / 2;
    rope_split_kernel<<<npairs / 256, 256>>>(q, fcos, fsin, qhi, qlo);
    rope_split_kernel<<<npairs / 256, 256>>>(k, fcos, fsin, khi, klo);
    vtrans_split_kernel<<<dim3(DIM / 32, ROWS / 32), dim3(32, 8)>>>(v, vthi, vtlo);

    attn_tc_kernel<<<dim3(SEQ / AQ, NH, BATCH), 256, ATTN_SMEM_BYTES>>>(
        qhi, qlo, khi, klo, vthi, vtlo, o);

    split_kernel<<<nx4 / 256, 256>>>(o, ohi, olo, nx4);
    gemm_bf16x3<<<gg, 256, GEMM_SMEM_BYTES>>>(ohi, olo, whi + 3*(size_t)DIM*DIM,
                                              wlo + 3*(size_t)DIM*DIM, out, ROWS, DIM, DIM);
}

// round 6
// speedup vs baseline: 2.3510x; 1.0785x over previous
#include <cuda_runtime.h>
#include <cuda_bf16.h>
#include <cstdint>

#define BATCH 2
#define SEQ   2048
#define DIM   2048
#define NH    16
#define HD    128
#define ROWS  (BATCH*SEQ)   // 4096

// ---------------- scratch (static device globals; no allocs allowed) --------
__device__ float g_v[ROWS*DIM];

__device__ __nv_bfloat16 g_xhi[ROWS*DIM];
__device__ __nv_bfloat16 g_xlo[ROWS*DIM];
__device__ __nv_bfloat16 g_ohi[ROWS*DIM];
__device__ __nv_bfloat16 g_olo[ROWS*DIM];
__device__ __nv_bfloat16 g_whi[4][DIM*DIM];   // q,k,v,o
__device__ __nv_bfloat16 g_wlo[4][DIM*DIM];

__device__ __nv_bfloat16 g_qhi[ROWS*DIM];
__device__ __nv_bfloat16 g_qlo[ROWS*DIM];
__device__ __nv_bfloat16 g_khi[ROWS*DIM];
__device__ __nv_bfloat16 g_klo[ROWS*DIM];
__device__ __nv_bfloat16 g_vthi[ROWS*DIM];    // per-head transposed [b,h,d,s]
__device__ __nv_bfloat16 g_vtlo[ROWS*DIM];

// ============================================================================
// helpers
// ============================================================================
__device__ __forceinline__ void cp_async16(void* smem, const void* gmem) {
    uint32_t s = (uint32_t)__cvta_generic_to_shared(smem);
    asm volatile("cp.async.cg.shared.global [%0], [%1], 16;\n" :: "r"(s), "l"(gmem));
}
#define CP_COMMIT() asm volatile("cp.async.commit_group;\n" ::: "memory")
#define CP_WAIT2()  asm volatile("cp.async.wait_group 2;\n" ::: "memory")
#define CP_WAIT1()  asm volatile("cp.async.wait_group 1;\n" ::: "memory")
#define CP_WAIT0()  asm volatile("cp.async.wait_group 0;\n" ::: "memory")

__device__ __forceinline__ void mma_bf16(float* c, const uint32_t* a, const uint32_t* b) {
    asm volatile(
        "mma.sync.aligned.m16n8k16.row.col.f32.bf16.bf16.f32 "
        "{%0,%1,%2,%3}, {%4,%5,%6,%7}, {%8,%9}, {%0,%1,%2,%3};\n"
        : "+f"(c[0]), "+f"(c[1]), "+f"(c[2]), "+f"(c[3])
        : "r"(a[0]), "r"(a[1]), "r"(a[2]), "r"(a[3]),
          "r"(b[0]), "r"(b[1]));
}
__device__ __forceinline__ void ldsm_x4(uint32_t* r, uint32_t saddr) {
    asm volatile("ldmatrix.sync.aligned.m8n8.x4.shared.b16 {%0,%1,%2,%3}, [%4];"
        : "=r"(r[0]), "=r"(r[1]), "=r"(r[2]), "=r"(r[3]) : "r"(saddr));
}
__device__ __forceinline__ uint32_t smem_u32(const void* p) {
    return (uint32_t)__cvta_generic_to_shared(p);
}

// ---------------- fp32 -> bf16 hi/lo split ----------------------------------
__global__ void split_kernel(const float* __restrict__ in,
                             __nv_bfloat16* __restrict__ hi,
                             __nv_bfloat16* __restrict__ lo, int n4)
{
    int idx = blockIdx.x * blockDim.x + threadIdx.x;
    if (idx >= n4) return;
    float4 v = ((const float4*)in)[idx];
    __nv_bfloat16 h0 = __float2bfloat16(v.x);
    __nv_bfloat16 h1 = __float2bfloat16(v.y);
    __nv_bfloat16 h2 = __float2bfloat16(v.z);
    __nv_bfloat16 h3 = __float2bfloat16(v.w);
    __nv_bfloat16 l0 = __float2bfloat16(v.x - __bfloat162float(h0));
    __nv_bfloat16 l1 = __float2bfloat16(v.y - __bfloat162float(h1));
    __nv_bfloat16 l2 = __float2bfloat16(v.z - __bfloat162float(h2));
    __nv_bfloat16 l3 = __float2bfloat16(v.w - __bfloat162float(h3));
    ((__nv_bfloat162*)hi)[idx*2+0] = __nv_bfloat162(h0, h1);
    ((__nv_bfloat162*)hi)[idx*2+1] = __nv_bfloat162(h2, h3);
    ((__nv_bfloat162*)lo)[idx*2+0] = __nv_bfloat162(l0, l1);
    ((__nv_bfloat162*)lo)[idx*2+1] = __nv_bfloat162(l2, l3);
}

// ---------------- V transpose + split: [b,s,h,d] -> [b,h,d,s] ----------------
__global__ void vtrans_split_kernel(const float* __restrict__ v,
                                    __nv_bfloat16* __restrict__ vthi,
                                    __nv_bfloat16* __restrict__ vtlo)
{
    __shared__ float tile[32][33];
    int c0 = blockIdx.x * 32, s0 = blockIdx.y * 32;
    int tx = threadIdx.x, ty = threadIdx.y;
#pragma unroll
    for (int i = 0; i < 4; i++)
        tile[ty + 8*i][tx] = v[(size_t)(s0 + ty + 8*i) * DIM + c0 + tx];
    __syncthreads();
    int sg = s0 + tx;
    int b  = sg >> 11;
    int sl = sg & (SEQ - 1);
#pragma unroll
    for (int i = 0; i < 4; i++) {
        int cg = c0 + ty + 8*i;
        int h  = cg >> 7;
        int d  = cg & 127;
        float val = tile[tx][ty + 8*i];
        __nv_bfloat16 hv = __float2bfloat16(val);
        __nv_bfloat16 lv = __float2bfloat16(val - __bfloat162float(hv));
        size_t o = ((size_t)((b * NH + h) * HD + d)) * SEQ + sl;
        vthi[o] = hv;
        vtlo[o] = lv;
    }
}

// ============================================================================
// bf16x3 GEMM, ldmatrix + 3-stage cp.async. C = (Ahi+Alo) (Bhi+Blo)^T
// optional fused RoPE + bf16-split epilogue (for Q/K projections)
// ============================================================================
#define BM 128
#define BN 128
#define BK 32
#define HSTR 40
#define NSTG 3
#define TILE_B (BM*HSTR*2)          // 10240 bytes per tile per stage
#define GEMM_SMEM_BYTES (4*NSTG*TILE_B)   // 122880

template<bool ROPE>
__global__ void __launch_bounds__(256, 1) gemm_ld(
    const __nv_bfloat16* __restrict__ Ahi, const __nv_bfloat16* __restrict__ Alo,
    const __nv_bfloat16* __restrict__ Bhi, const __nv_bfloat16* __restrict__ Blo,
    float* __restrict__ C,
    __nv_bfloat16* __restrict__ Chi, __nv_bfloat16* __restrict__ Clo,
    const float* __restrict__ fc, const float* __restrict__ fs,
    int M, int N, int K)
{
    extern __shared__ char smc[];
    char* sAh = smc;
    char* sAl = smc + NSTG * TILE_B;
    char* sBh = smc + 2 * NSTG * TILE_B;
    char* sBl = smc + 3 * NSTG * TILE_B;
    const uint32_t uAh = smem_u32(sAh), uAl = smem_u32(sAl);
    const uint32_t uBh = smem_u32(sBh), uBl = smem_u32(sBl);

    const int t    = threadIdx.x;
    const int lane = t & 31;
    const int wid  = t >> 5;
    const int gid  = lane >> 2;
    const int tig  = lane & 3;
    const int wm   = (wid & 1) * 64;
    const int wn   = (wid >> 1) * 32;
    const int m0   = blockIdx.y * BM;
    const int n0   = blockIdx.x * BN;

    // ldmatrix address components
    const int arow = (lane & 15);             // row within 16-row tile
    const int acol = (lane >> 4) << 3;        // 0 or 8 (halfs)
    const int brow = ((lane >> 4) << 3) + (lane & 7);
    const int bcol = ((lane >> 3) & 1) << 3;

    // tile-load mapping: 512 16B chunks per tile; thread does chunks t, t+256
    const int lr0 = t >> 2, lc0 = (t & 3) * 8;        // chunk t
    const int lr1 = (t + 256) >> 2;                   // chunk t+256 (same lc)

    float acc[4][4][4];
#pragma unroll
    for (int i = 0; i < 4; i++)
#pragma unroll
        for (int j = 0; j < 4; j++)
#pragma unroll
            for (int e = 0; e < 4; e++) acc[i][j][e] = 0.f;

    const int NK = K / BK;

#define G_LOAD(STG, K0)                                                         \
    {                                                                           \
        size_t ga0 = (size_t)(m0 + lr0) * K + (K0) + lc0;                       \
        size_t ga1 = (size_t)(m0 + lr1) * K + (K0) + lc0;                       \
        size_t gb0 = (size_t)(n0 + lr0) * K + (K0) + lc0;                       \
        size_t gb1 = (size_t)(n0 + lr1) * K + (K0) + lc0;                       \
        int so0 = (STG) * TILE_B + (lr0 * HSTR + lc0) * 2;                      \
        int so1 = (STG) * TILE_B + (lr1 * HSTR + lc0) * 2;                      \
        cp_async16(sAh + so0, Ahi + ga0);  cp_async16(sAh + so1, Ahi + ga1);    \
        cp_async16(sAl + so0, Alo + ga0);  cp_async16(sAl + so1, Alo + ga1);    \
        cp_async16(sBh + so0, Bhi + gb0);  cp_async16(sBh + so1, Bhi + gb1);    \
        cp_async16(sBl + so0, Blo + gb0);  cp_async16(sBl + so1, Blo + gb1);    \
        CP_COMMIT();                                                            \
    }

    G_LOAD(0, 0);
    G_LOAD(1, BK);

    for (int kt = 0; kt < NK; kt++) {
        __syncthreads();   // everyone done with stage being overwritten
        if (kt + 2 < NK) { G_LOAD((kt + 2) % NSTG, (kt + 2) * BK); CP_WAIT2(); }
        else if (kt + 1 < NK) { CP_WAIT1(); }
        else { CP_WAIT0(); }
        __syncthreads();

        const int stb = (kt % NSTG) * TILE_B;
#pragma unroll
        for (int kk = 0; kk < 2; kk++) {
            uint32_t ah[4][4], al[4][4], bh[4][2], bl[4][2];
#pragma unroll
            for (int ms = 0; ms < 4; ms++) {
                uint32_t off = stb + ((wm + ms * 16 + arow) * HSTR + kk * 16 + acol) * 2;
                ldsm_x4(ah[ms], uAh + off);
                ldsm_x4(al[ms], uAl + off);
            }
#pragma unroll
            for (int nsp = 0; nsp < 2; nsp++) {
                uint32_t off = stb + ((wn + nsp * 16 + brow) * HSTR + kk * 16 + bcol) * 2;
                uint32_t r[4];
                ldsm_x4(r, uBh + off);
                bh[2*nsp][0] = r[0]; bh[2*nsp][1] = r[1];
                bh[2*nsp+1][0] = r[2]; bh[2*nsp+1][1] = r[3];
                ldsm_x4(r, uBl + off);
                bl[2*nsp][0] = r[0]; bl[2*nsp][1] = r[1];
                bl[2*nsp+1][0] = r[2]; bl[2*nsp+1][1] = r[3];
            }
#pragma unroll
            for (int ms = 0; ms < 4; ms++)
#pragma unroll
                for (int ns = 0; ns < 4; ns++) {
                    mma_bf16(acc[ms][ns], ah[ms], bh[ns]);
                    mma_bf16(acc[ms][ns], al[ms], bh[ns]);
                    mma_bf16(acc[ms][ns], ah[ms], bl[ns]);
                }
        }
    }

    // ---- epilogue ----
#pragma unroll
    for (int ms = 0; ms < 4; ms++) {
#pragma unroll
        for (int ns = 0; ns < 4; ns++) {
            int row0 = m0 + wm + ms * 16 + gid;
            int col  = n0 + wn + ns * 8 + tig * 2;
            if (!ROPE) {
                float2 c0 = {acc[ms][ns][0], acc[ms][ns][1]};
                float2 c1 = {acc[ms][ns][2], acc[ms][ns][3]};
                *(float2*)&C[(size_t)row0 * N + col]       = c0;
                *(float2*)&C[(size_t)(row0 + 8) * N + col] = c1;
            } else {
                int i = (col & 127) >> 1;   // rope pair index
#pragma unroll
                for (int half = 0; half < 2; half++) {
                    int row = row0 + half * 8;
                    int s   = row & (SEQ - 1);
                    float cs = __ldg(fc + s * 64 + i);
                    float sn = __ldg(fs + s * 64 + i);
                    float re = acc[ms][ns][half * 2];
                    float im = acc[ms][ns][half * 2 + 1];
                    float rx = re * cs - im * sn;
                    float ry = re * sn + im * cs;
                    __nv_bfloat16 hx = __float2bfloat16(rx);
                    __nv_bfloat16 hy = __float2bfloat16(ry);
                    __nv_bfloat16 lx = __float2bfloat16(rx - __bfloat162float(hx));
                    __nv_bfloat16 ly = __float2bfloat16(ry - __bfloat162float(hy));
                    size_t idx = ((size_t)row * N + col) >> 1;
                    ((__nv_bfloat162*)Chi)[idx] = __nv_bfloat162(hx, hy);
                    ((__nv_bfloat162*)Clo)[idx] = __nv_bfloat162(lx, ly);
                }
            }
        }
    }
}

// ============================================================================
// tensor-core flash attention, bf16x3, causal; ldmatrix fragment loads;
// epilogue writes bf16 hi/lo split directly.
// ============================================================================
#define AQ  128
#define AK  64
#define AHS 136
#define AVS 72
#define A_QH        0
#define A_QL        17408
#define A_KH(bf)    (34816 + (bf)*8704)
#define A_KL(bf)    (52224 + (bf)*8704)
#define A_VH(bf)    (69632 + (bf)*9216)
#define A_VL(bf)    (88064 + (bf)*9216)
#define ATTN_SMEM_BYTES (106496*2)

__global__ void __launch_bounds__(256) attn_tc_kernel(
    const __nv_bfloat16* __restrict__ qhi, const __nv_bfloat16* __restrict__ qlo,
    const __nv_bfloat16* __restrict__ khi, const __nv_bfloat16* __restrict__ klo,
    const __nv_bfloat16* __restrict__ vthi, const __nv_bfloat16* __restrict__ vtlo,
    __nv_bfloat16* __restrict__ ohi, __nv_bfloat16* __restrict__ olo)
{
    extern __shared__ __nv_bfloat16 smh[];
    const uint32_t ubase = smem_u32(smh);

    const int t    = threadIdx.x;
    const int lane = t & 31;
    const int wid  = t >> 5;
    const int gid  = lane >> 2;
    const int tig  = lane & 3;
    const int qt = blockIdx.x, h = blockIdx.y, b = blockIdx.z;

    const int arow = (lane & 15);
    const int acol = (lane >> 4) << 3;
    const int brow = ((lane >> 4) << 3) + (lane & 7);
    const int bcol = ((lane >> 3) & 1) << 3;

    {
        int row = t >> 1;
        int cb  = (t & 1) * 8;
        size_t g = (size_t)(b * SEQ + qt * AQ + row) * DIM + h * HD + cb * 8;
        int so = row * AHS + cb * 8;
#pragma unroll
        for (int c = 0; c < 8; c++) {
            cp_async16(smh + A_QH + so + c * 8, qhi + g + c * 8);
            cp_async16(smh + A_QL + so + c * 8, qlo + g + c * 8);
        }
    }

#define LOAD_KV(BUFI, KT)                                                       \
    {                                                                           \
        int row = t >> 2;                                                       \
        int cb  = (t & 3) * 4;                                                  \
        size_t g = (size_t)(b * SEQ + (KT) * AK + row) * DIM + h * HD + cb * 8; \
        int so = row * AHS + cb * 8;                                            \
        _Pragma("unroll")                                                       \
        for (int c = 0; c < 4; c++) {                                           \
            cp_async16(smh + A_KH(BUFI) + so + c * 8, khi + g + c * 8);         \
            cp_async16(smh + A_KL(BUFI) + so + c * 8, klo + g + c * 8);         \
        }                                                                       \
        int vrow = t >> 1;                                                      \
        int vcb  = (t & 1) * 4;                                                 \
        size_t gv = (size_t)((b * NH + h) * HD + vrow) * SEQ + (KT) * AK + vcb * 8; \
        int sv = vrow * AVS + vcb * 8;                                          \
        _Pragma("unroll")                                                       \
        for (int c = 0; c < 4; c++) {                                           \
            cp_async16(smh + A_VH(BUFI) + sv + c * 8, vthi + gv + c * 8);       \
            cp_async16(smh + A_VL(BUFI) + sv + c * 8, vtlo + gv + c * 8);       \
        }                                                                       \
    }

    LOAD_KV(0, 0);
    CP_COMMIT();

    float sacc[8][4];
    float oacc[16][4];
#pragma unroll
    for (int i = 0; i < 16; i++)
#pragma unroll
        for (int e = 0; e < 4; e++) oacc[i][e] = 0.f;
    float m0 = -1e30f, m1 = -1e30f, l0 = 0.f, l1 = 0.f;

    const float scale = 0.08838834764831845f;
    const int gr0 = qt * AQ + wid * 16 + gid;
    const int ktmax = 2 * qt + 1;
    int buf = 0;

    for (int kt = 0; kt <= ktmax; kt++) {
        if (kt < ktmax) {
            LOAD_KV(buf ^ 1, kt + 1);
            CP_COMMIT();
            CP_WAIT1();
        } else {
            CP_WAIT0();
        }
        __syncthreads();

#pragma unroll
        for (int ns = 0; ns < 8; ns++)
#pragma unroll
            for (int e = 0; e < 4; e++) sacc[ns][e] = 0.f;

        const uint32_t ukh = ubase + A_KH(buf) * 2;
        const uint32_t ukl = ubase + A_KL(buf) * 2;
#pragma unroll
        for (int kk = 0; kk < 8; kk++) {
            uint32_t aoff = ((wid * 16 + arow) * AHS + kk * 16 + acol) * 2;
            uint32_t ah[4], al[4];
            ldsm_x4(ah, ubase + A_QH * 2 + aoff);
            ldsm_x4(al, ubase + A_QL * 2 + aoff);
#pragma unroll
            for (int nsp = 0; nsp < 4; nsp++) {
                uint32_t boff = ((nsp * 16 + brow) * AHS + kk * 16 + bcol) * 2;
                uint32_t rh[4], rl[4];
                ldsm_x4(rh, ukh + boff);
                ldsm_x4(rl, ukl + boff);
                uint32_t b0h[2] = {rh[0], rh[1]}, b1h[2] = {rh[2], rh[3]};
                uint32_t b0l[2] = {rl[0], rl[1]}, b1l[2] = {rl[2], rl[3]};
                mma_bf16(sacc[2*nsp],   ah, b0h);
                mma_bf16(sacc[2*nsp],   al, b0h);
                mma_bf16(sacc[2*nsp],   ah, b0l);
                mma_bf16(sacc[2*nsp+1], ah, b1h);
                mma_bf16(sacc[2*nsp+1], al, b1h);
                mma_bf16(sacc[2*nsp+1], ah, b1l);
            }
        }

        if (kt * AK + 63 > qt * AQ + wid * 16) {
            int rl0 = gr0 - kt * AK;
            int rl1 = rl0 + 8;
#pragma unroll
            for (int ns = 0; ns < 8; ns++) {
#pragma unroll
                for (int e = 0; e < 4; e++) {
                    float v = sacc[ns][e] * scale;
                    int cl = ns * 8 + 2 * tig + (e & 1);
                    int rl = (e < 2) ? rl0 : rl1;
                    sacc[ns][e] = (cl > rl) ? -1e30f : v;
                }
            }
        } else {
#pragma unroll
            for (int ns = 0; ns < 8; ns++)
#pragma unroll
                for (int e = 0; e < 4; e++) sacc[ns][e] *= scale;
        }

        float mx0 = -1e30f, mx1 = -1e30f;
#pragma unroll
        for (int ns = 0; ns < 8; ns++) {
            mx0 = fmaxf(mx0, fmaxf(sacc[ns][0], sacc[ns][1]));
            mx1 = fmaxf(mx1, fmaxf(sacc[ns][2], sacc[ns][3]));
        }
        mx0 = fmaxf(mx0, __shfl_xor_sync(0xffffffffu, mx0, 1));
        mx0 = fmaxf(mx0, __shfl_xor_sync(0xffffffffu, mx0, 2));
        mx1 = fmaxf(mx1, __shfl_xor_sync(0xffffffffu, mx1, 1));
        mx1 = fmaxf(mx1, __shfl_xor_sync(0xffffffffu, mx1, 2));
        float mn0 = fmaxf(m0, mx0), mn1 = fmaxf(m1, mx1);
        float a0 = __expf(m0 - mn0), a1 = __expf(m1 - mn1);
        m0 = mn0; m1 = mn1;

        float sum0 = 0.f, sum1 = 0.f;
#pragma unroll
        for (int ns = 0; ns < 8; ns++) {
            float p0 = __expf(sacc[ns][0] - mn0);
            float p1 = __expf(sacc[ns][1] - mn0);
            float p2 = __expf(sacc[ns][2] - mn1);
            float p3 = __expf(sacc[ns][3] - mn1);
            sacc[ns][0] = p0; sacc[ns][1] = p1;
            sacc[ns][2] = p2; sacc[ns][3] = p3;
            sum0 += p0 + p1; sum1 += p2 + p3;
        }
        sum0 += __shfl_xor_sync(0xffffffffu, sum0, 1);
        sum0 += __shfl_xor_sync(0xffffffffu, sum0, 2);
        sum1 += __shfl_xor_sync(0xffffffffu, sum1, 1);
        sum1 += __shfl_xor_sync(0xffffffffu, sum1, 2);
        l0 = l0 * a0 + sum0;
        l1 = l1 * a1 + sum1;

#pragma unroll
        for (int nd = 0; nd < 16; nd++) {
            oacc[nd][0] *= a0; oacc[nd][1] *= a0;
            oacc[nd][2] *= a1; oacc[nd][3] *= a1;
        }

        const uint32_t uvh = ubase + A_VH(buf) * 2;
        const uint32_t uvl = ubase + A_VL(buf) * 2;
#pragma unroll
        for (int kc = 0; kc < 4; kc++) {
            uint32_t ph[4], pl[4];
#pragma unroll
            for (int j = 0; j < 4; j++) {
                int ns = 2 * kc + (j >> 1);
                int e0 = (j & 1) * 2;
                float c0 = sacc[ns][e0], c1 = sacc[ns][e0 + 1];
                __nv_bfloat162 hb = __floats2bfloat162_rn(c0, c1);
                uint32_t hu = *(uint32_t*)&hb;
                float f0 = __uint_as_float(hu << 16);
                float f1 = __uint_as_float(hu & 0xffff0000u);
                __nv_bfloat162 lb = __floats2bfloat162_rn(c0 - f0, c1 - f1);
                ph[j] = hu;
                pl[j] = *(uint32_t*)&lb;
            }
#pragma unroll
            for (int ndp = 0; ndp < 8; ndp++) {
                uint32_t boff = ((ndp * 16 + brow) * AVS + kc * 16 + bcol) * 2;
                uint32_t rh[4], rl[4];
                ldsm_x4(rh, uvh + boff);
                ldsm_x4(rl, uvl + boff);
                uint32_t b0h[2] = {rh[0], rh[1]}, b1h[2] = {rh[2], rh[3]};
                uint32_t b0l[2] = {rl[0], rl[1]}, b1l[2] = {rl[2], rl[3]};
                mma_bf16(oacc[2*ndp],   ph, b0h);
                mma_bf16(oacc[2*ndp],   pl, b0h);
                mma_bf16(oacc[2*ndp],   ph, b0l);
                mma_bf16(oacc[2*ndp+1], ph, b1h);
                mma_bf16(oacc[2*ndp+1], pl, b1h);
                mma_bf16(oacc[2*ndp+1], ph, b1l);
            }
        }
        __syncthreads();
        buf ^= 1;
    }

    // ---- normalize + split-store ----
    float i0 = 1.f / l0, i1 = 1.f / l1;
    size_t r0 = (size_t)(b * SEQ + gr0) * DIM + h * HD;
    size_t r1 = r0 + 8 * DIM;
#pragma unroll
    for (int nd = 0; nd < 16; nd++) {
        int col = nd * 8 + 2 * tig;
        float w0x = oacc[nd][0] * i0, w0y = oacc[nd][1] * i0;
        float w1x = oacc[nd][2] * i1, w1y = oacc[nd][3] * i1;
        __nv_bfloat16 h0x = __float2bfloat16(w0x);
        __nv_bfloat16 h0y = __float2bfloat16(w0y);
        __nv_bfloat16 h1x = __float2bfloat16(w1x);
        __nv_bfloat16 h1y = __float2bfloat16(w1y);
        ((__nv_bfloat162*)&ohi[r0 + col])[0] = __nv_bfloat162(h0x, h0y);
        ((__nv_bfloat162*)&ohi[r1 + col])[0] = __nv_bfloat162(h1x, h1y);
        ((__nv_bfloat162*)&olo[r0 + col])[0] = __nv_bfloat162(
            __float2bfloat16(w0x - __bfloat162float(h0x)),
            __float2bfloat16(w0y - __bfloat162float(h0y)));
        ((__nv_bfloat162*)&olo[r1 + col])[0] = __nv_bfloat162(
            __float2bfloat16(w1x - __bfloat162float(h1x)),
            __float2bfloat16(w1y - __bfloat162float(h1y)));
    }
}

// ---------------- launcher ---------------------------------------------------
extern "C" void kernel_launch(void* const* d_in, const int* in_sizes, int n_in,
                              void* d_out, int out_size)
{
    const float* x    = (const float*)d_in[0];
    const float* w[4] = {(const float*)d_in[1], (const float*)d_in[2],
                         (const float*)d_in[3], (const float*)d_in[4]};
    const float* fcos = (const float*)d_in[5];
    const float* fsin = (const float*)d_in[6];
    float* out = (float*)d_out;

    float *v;
    cudaGetSymbolAddress((void**)&v, g_v);

    __nv_bfloat16 *xhi, *xlo, *ohi, *olo, *whi, *wlo;
    __nv_bfloat16 *qhi, *qlo, *khi, *klo, *vthi, *vtlo;
    cudaGetSymbolAddress((void**)&xhi, g_xhi);
    cudaGetSymbolAddress((void**)&xlo, g_xlo);
    cudaGetSymbolAddress((void**)&ohi, g_ohi);
    cudaGetSymbolAddress((void**)&olo, g_olo);
    cudaGetSymbolAddress((void**)&whi, g_whi);
    cudaGetSymbolAddress((void**)&wlo, g_wlo);
    cudaGetSymbolAddress((void**)&qhi, g_qhi);
    cudaGetSymbolAddress((void**)&qlo, g_qlo);
    cudaGetSymbolAddress((void**)&khi, g_khi);
    cudaGetSymbolAddress((void**)&klo, g_klo);
    cudaGetSymbolAddress((void**)&vthi, g_vthi);
    cudaGetSymbolAddress((void**)&vtlo, g_vtlo);

    cudaFuncSetAttribute(gemm_ld<false>,
                         cudaFuncAttributeMaxDynamicSharedMemorySize, GEMM_SMEM_BYTES);
    cudaFuncSetAttribute(gemm_ld<true>,
                         cudaFuncAttributeMaxDynamicSharedMemorySize, GEMM_SMEM_BYTES);
    cudaFuncSetAttribute(attn_tc_kernel,
                         cudaFuncAttributeMaxDynamicSharedMemorySize, ATTN_SMEM_BYTES);

    int nx4 = ROWS * DIM / 4;
    int nw4 = DIM * DIM / 4;
    split_kernel<<<nx4 / 256, 256>>>(x, xhi, xlo, nx4);
    for (int i = 0; i < 4; i++)
        split_kernel<<<nw4 / 256, 256>>>(w[i], whi + (size_t)i * DIM * DIM,
                                         wlo + (size_t)i * DIM * DIM, nw4);

    dim3 gg(DIM / BN, ROWS / BM);   // (16, 32)

    // Q projection: fused RoPE + split
    gemm_ld<true><<<gg, 256, GEMM_SMEM_BYTES>>>(
        xhi, xlo, whi + 0*(size_t)DIM*DIM, wlo + 0*(size_t)DIM*DIM,
        nullptr, qhi, qlo, fcos, fsin, ROWS, DIM, DIM);
    // K projection: fused RoPE + split
    gemm_ld<true><<<gg, 256, GEMM_SMEM_BYTES>>>(
        xhi, xlo, whi + 1*(size_t)DIM*DIM, wlo + 1*(size_t)DIM*DIM,
        nullptr, khi, klo, fcos, fsin, ROWS, DIM, DIM);
    // V projection: fp32 out (feeds transpose)
    gemm_ld<false><<<gg, 256, GEMM_SMEM_BYTES>>>(
        xhi, xlo, whi + 2*(size_t)DIM*DIM, wlo + 2*(size_t)DIM*DIM,
        v, nullptr, nullptr, nullptr, nullptr, ROWS, DIM, DIM);

    vtrans_split_kernel<<<dim3(DIM / 32, ROWS / 32), dim3(32, 8)>>>(v, vthi, vtlo);

    attn_tc_kernel<<<dim3(SEQ / AQ, NH, BATCH), 256, ATTN_SMEM_BYTES>>>(
        qhi, qlo, khi, klo, vthi, vtlo, ohi, olo);

    // output projection
    gemm_ld<false><<<gg, 256, GEMM_SMEM_BYTES>>>(
        ohi, olo, whi + 3*(size_t)DIM*DIM, wlo + 3*(size_t)DIM*DIM,
        out, nullptr, nullptr, nullptr, nullptr, ROWS, DIM, DIM);
}

// round 7
// speedup vs baseline: 2.7612x; 1.1745x over previous
#include <cuda_runtime.h>
#include <cuda_bf16.h>
#include <cstdint>

#define BATCH 2
#define SEQ   2048
#define DIM   2048
#define NH    16
#define HD    128
#define ROWS  (BATCH*SEQ)   // 4096

// ---------------- scratch (static device globals; no allocs allowed) --------
__device__ float g_v[ROWS*DIM];

__device__ __nv_bfloat16 g_xhi[ROWS*DIM];
__device__ __nv_bfloat16 g_xlo[ROWS*DIM];
__device__ __nv_bfloat16 g_ohi[ROWS*DIM];
__device__ __nv_bfloat16 g_olo[ROWS*DIM];
__device__ __nv_bfloat16 g_whi[4][DIM*DIM];   // q,k,v,o
__device__ __nv_bfloat16 g_wlo[4][DIM*DIM];

__device__ __nv_bfloat16 g_qhi[ROWS*DIM];
__device__ __nv_bfloat16 g_qlo[ROWS*DIM];
__device__ __nv_bfloat16 g_khi[ROWS*DIM];
__device__ __nv_bfloat16 g_klo[ROWS*DIM];
__device__ __nv_bfloat16 g_vthi[ROWS*DIM];    // per-head transposed [b,h,d,s]
__device__ __nv_bfloat16 g_vtlo[ROWS*DIM];

// ============================================================================
// helpers
// ============================================================================
__device__ __forceinline__ void cp_async16(void* smem, const void* gmem) {
    uint32_t s = (uint32_t)__cvta_generic_to_shared(smem);
    asm volatile("cp.async.cg.shared.global [%0], [%1], 16;\n" :: "r"(s), "l"(gmem));
}
#define CP_COMMIT() asm volatile("cp.async.commit_group;\n" ::: "memory")
#define CP_WAIT1()  asm volatile("cp.async.wait_group 1;\n" ::: "memory")
#define CP_WAIT0()  asm volatile("cp.async.wait_group 0;\n" ::: "memory")

__device__ __forceinline__ void mma_bf16(float* c, const uint32_t* a, const uint32_t* b) {
    asm volatile(
        "mma.sync.aligned.m16n8k16.row.col.f32.bf16.bf16.f32 "
        "{%0,%1,%2,%3}, {%4,%5,%6,%7}, {%8,%9}, {%0,%1,%2,%3};\n"
        : "+f"(c[0]), "+f"(c[1]), "+f"(c[2]), "+f"(c[3])
        : "r"(a[0]), "r"(a[1]), "r"(a[2]), "r"(a[3]),
          "r"(b[0]), "r"(b[1]));
}
__device__ __forceinline__ void ldsm_x4(uint32_t* r, uint32_t saddr) {
    asm volatile("ldmatrix.sync.aligned.m8n8.x4.shared.b16 {%0,%1,%2,%3}, [%4];"
        : "=r"(r[0]), "=r"(r[1]), "=r"(r[2]), "=r"(r[3]) : "r"(saddr));
}
__device__ __forceinline__ uint32_t smem_u32(const void* p) {
    return (uint32_t)__cvta_generic_to_shared(p);
}

// ---------------- fp32 -> bf16 hi/lo split ----------------------------------
__global__ void split_kernel(const float* __restrict__ in,
                             __nv_bfloat16* __restrict__ hi,
                             __nv_bfloat16* __restrict__ lo, int n4)
{
    int idx = blockIdx.x * blockDim.x + threadIdx.x;
    if (idx >= n4) return;
    float4 v = ((const float4*)in)[idx];
    __nv_bfloat16 h0 = __float2bfloat16(v.x);
    __nv_bfloat16 h1 = __float2bfloat16(v.y);
    __nv_bfloat16 h2 = __float2bfloat16(v.z);
    __nv_bfloat16 h3 = __float2bfloat16(v.w);
    __nv_bfloat16 l0 = __float2bfloat16(v.x - __bfloat162float(h0));
    __nv_bfloat16 l1 = __float2bfloat16(v.y - __bfloat162float(h1));
    __nv_bfloat16 l2 = __float2bfloat16(v.z - __bfloat162float(h2));
    __nv_bfloat16 l3 = __float2bfloat16(v.w - __bfloat162float(h3));
    ((__nv_bfloat162*)hi)[idx*2+0] = __nv_bfloat162(h0, h1);
    ((__nv_bfloat162*)hi)[idx*2+1] = __nv_bfloat162(h2, h3);
    ((__nv_bfloat162*)lo)[idx*2+0] = __nv_bfloat162(l0, l1);
    ((__nv_bfloat162*)lo)[idx*2+1] = __nv_bfloat162(l2, l3);
}

// ---------------- V transpose + split: [b,s,h,d] -> [b,h,d,s] ----------------
__global__ void vtrans_split_kernel(const float* __restrict__ v,
                                    __nv_bfloat16* __restrict__ vthi,
                                    __nv_bfloat16* __restrict__ vtlo)
{
    __shared__ float tile[32][33];
    int c0 = blockIdx.x * 32, s0 = blockIdx.y * 32;
    int tx = threadIdx.x, ty = threadIdx.y;
#pragma unroll
    for (int i = 0; i < 4; i++)
        tile[ty + 8*i][tx] = v[(size_t)(s0 + ty + 8*i) * DIM + c0 + tx];
    __syncthreads();
    int sg = s0 + tx;
    int b  = sg >> 11;
    int sl = sg & (SEQ - 1);
#pragma unroll
    for (int i = 0; i < 4; i++) {
        int cg = c0 + ty + 8*i;
        int h  = cg >> 7;
        int d  = cg & 127;
        float val = tile[tx][ty + 8*i];
        __nv_bfloat16 hv = __float2bfloat16(val);
        __nv_bfloat16 lv = __float2bfloat16(val - __bfloat162float(hv));
        size_t o = ((size_t)((b * NH + h) * HD + d)) * SEQ + sl;
        vthi[o] = hv;
        vtlo[o] = lv;
    }
}

// ============================================================================
// bf16x3 GEMM, ldmatrix, 2-stage cp.async, 2 CTAs/SM.
// gridDim.z selects projection: 0=Q(rope), 1=K(rope), 2=V(fp32 out)
// Separate entry for the output projection (plain fp32 out).
// ============================================================================
#define BM 128
#define BN 128
#define BK 32
#define HSTR 40
#define NSTG 2
#define TILE_B (BM*HSTR*2)          // 10240 bytes per tile per stage
#define GEMM_SMEM_BYTES (4*NSTG*TILE_B)   // 81920

struct GemmCore {
    uint32_t uAh, uAl, uBh, uBl;
    int t, lane, wid, gid, tig, wm, wn, m0, n0;
    int arow, acol, brow, bcol;
    int lr0, lc0, lr1;
    float acc[4][4][4];

    __device__ __forceinline__ void init(char* smc, int bx, int by, int tid) {
        uAh = smem_u32(smc);
        uAl = uAh + NSTG * TILE_B;
        uBh = uAh + 2 * NSTG * TILE_B;
        uBl = uAh + 3 * NSTG * TILE_B;
        t = tid; lane = t & 31; wid = t >> 5;
        gid = lane >> 2; tig = lane & 3;
        wm = (wid & 1) * 64; wn = (wid >> 1) * 32;
        m0 = by * BM; n0 = bx * BN;
        arow = lane & 15; acol = (lane >> 4) << 3;
        brow = ((lane >> 4) << 3) + (lane & 7);
        bcol = ((lane >> 3) & 1) << 3;
        lr0 = t >> 2; lc0 = (t & 3) * 8; lr1 = lr0 + 64;
#pragma unroll
        for (int i = 0; i < 4; i++)
#pragma unroll
            for (int j = 0; j < 4; j++)
#pragma unroll
                for (int e = 0; e < 4; e++) acc[i][j][e] = 0.f;
    }

    __device__ __forceinline__ void load_stage(
        char* smc, int stg, int k0,
        const __nv_bfloat16* Ahi, const __nv_bfloat16* Alo,
        const __nv_bfloat16* Bhi, const __nv_bfloat16* Blo, int K)
    {
        char* sAh = smc;
        char* sAl = smc + NSTG * TILE_B;
        char* sBh = smc + 2 * NSTG * TILE_B;
        char* sBl = smc + 3 * NSTG * TILE_B;
        size_t ga0 = (size_t)(m0 + lr0) * K + k0 + lc0;
        size_t ga1 = (size_t)(m0 + lr1) * K + k0 + lc0;
        size_t gb0 = (size_t)(n0 + lr0) * K + k0 + lc0;
        size_t gb1 = (size_t)(n0 + lr1) * K + k0 + lc0;
        int so0 = stg * TILE_B + (lr0 * HSTR + lc0) * 2;
        int so1 = stg * TILE_B + (lr1 * HSTR + lc0) * 2;
        cp_async16(sAh + so0, Ahi + ga0);  cp_async16(sAh + so1, Ahi + ga1);
        cp_async16(sAl + so0, Alo + ga0);  cp_async16(sAl + so1, Alo + ga1);
        cp_async16(sBh + so0, Bhi + gb0);  cp_async16(sBh + so1, Bhi + gb1);
        cp_async16(sBl + so0, Blo + gb0);  cp_async16(sBl + so1, Blo + gb1);
        CP_COMMIT();
    }

    __device__ __forceinline__ void consume_stage(int stg) {
        const int stb = stg * TILE_B;
#pragma unroll
        for (int kk = 0; kk < 2; kk++) {
            uint32_t ah[4][4], al[4][4], bh[4][2], bl[4][2];
#pragma unroll
            for (int ms = 0; ms < 4; ms++) {
                uint32_t off = stb + ((wm + ms * 16 + arow) * HSTR + kk * 16 + acol) * 2;
                ldsm_x4(ah[ms], uAh + off);
                ldsm_x4(al[ms], uAl + off);
            }
#pragma unroll
            for (int nsp = 0; nsp < 2; nsp++) {
                uint32_t off = stb + ((wn + nsp * 16 + brow) * HSTR + kk * 16 + bcol) * 2;
                uint32_t r[4];
                ldsm_x4(r, uBh + off);
                bh[2*nsp][0] = r[0]; bh[2*nsp][1] = r[1];
                bh[2*nsp+1][0] = r[2]; bh[2*nsp+1][1] = r[3];
                ldsm_x4(r, uBl + off);
                bl[2*nsp][0] = r[0]; bl[2*nsp][1] = r[1];
                bl[2*nsp+1][0] = r[2]; bl[2*nsp+1][1] = r[3];
            }
#pragma unroll
            for (int ms = 0; ms < 4; ms++)
#pragma unroll
                for (int ns = 0; ns < 4; ns++) {
                    mma_bf16(acc[ms][ns], ah[ms], bh[ns]);
                    mma_bf16(acc[ms][ns], al[ms], bh[ns]);
                    mma_bf16(acc[ms][ns], ah[ms], bl[ns]);
                }
        }
    }

    __device__ __forceinline__ void mainloop(
        char* smc,
        const __nv_bfloat16* Ahi, const __nv_bfloat16* Alo,
        const __nv_bfloat16* Bhi, const __nv_bfloat16* Blo, int K)
    {
        const int NK = K / BK;
        load_stage(smc, 0, 0, Ahi, Alo, Bhi, Blo, K);
        for (int kt = 0; kt < NK; kt++) {
            if (kt + 1 < NK) {
                load_stage(smc, (kt + 1) & 1, (kt + 1) * BK, Ahi, Alo, Bhi, Blo, K);
                CP_WAIT1();
            } else {
                CP_WAIT0();
            }
            __syncthreads();
            consume_stage(kt & 1);
            __syncthreads();
        }
    }
};

__global__ void __launch_bounds__(256, 2) gemm_qkv(
    const __nv_bfloat16* __restrict__ xhi, const __nv_bfloat16* __restrict__ xlo,
    const __nv_bfloat16* __restrict__ whi, const __nv_bfloat16* __restrict__ wlo,
    __nv_bfloat16* __restrict__ qhi, __nv_bfloat16* __restrict__ qlo,
    __nv_bfloat16* __restrict__ khi, __nv_bfloat16* __restrict__ klo,
    float* __restrict__ v,
    const float* __restrict__ fc, const float* __restrict__ fs)
{
    extern __shared__ char smc[];
    const int proj = blockIdx.z;
    GemmCore g;
    g.init(smc, blockIdx.x, blockIdx.y, threadIdx.x);
    g.mainloop(smc, xhi, xlo,
               whi + (size_t)proj * DIM * DIM, wlo + (size_t)proj * DIM * DIM, DIM);

    const int N = DIM;
    if (proj == 2) {
#pragma unroll
        for (int ms = 0; ms < 4; ms++)
#pragma unroll
            for (int ns = 0; ns < 4; ns++) {
                int row = g.m0 + g.wm + ms * 16 + g.gid;
                int col = g.n0 + g.wn + ns * 8 + g.tig * 2;
                float2 c0 = {g.acc[ms][ns][0], g.acc[ms][ns][1]};
                float2 c1 = {g.acc[ms][ns][2], g.acc[ms][ns][3]};
                *(float2*)&v[(size_t)row * N + col]       = c0;
                *(float2*)&v[(size_t)(row + 8) * N + col] = c1;
            }
    } else {
        __nv_bfloat16* Chi = proj ? khi : qhi;
        __nv_bfloat16* Clo = proj ? klo : qlo;
#pragma unroll
        for (int ms = 0; ms < 4; ms++)
#pragma unroll
            for (int ns = 0; ns < 4; ns++) {
                int row0 = g.m0 + g.wm + ms * 16 + g.gid;
                int col  = g.n0 + g.wn + ns * 8 + g.tig * 2;
                int i = (col & 127) >> 1;
#pragma unroll
                for (int half = 0; half < 2; half++) {
                    int row = row0 + half * 8;
                    int s   = row & (SEQ - 1);
                    float cs = __ldg(fc + s * 64 + i);
                    float sn = __ldg(fs + s * 64 + i);
                    float re = g.acc[ms][ns][half * 2];
                    float im = g.acc[ms][ns][half * 2 + 1];
                    float rx = re * cs - im * sn;
                    float ry = re * sn + im * cs;
                    __nv_bfloat16 hx = __float2bfloat16(rx);
                    __nv_bfloat16 hy = __float2bfloat16(ry);
                    __nv_bfloat16 lx = __float2bfloat16(rx - __bfloat162float(hx));
                    __nv_bfloat16 ly = __float2bfloat16(ry - __bfloat162float(hy));
                    size_t idx = ((size_t)row * N + col) >> 1;
                    ((__nv_bfloat162*)Chi)[idx] = __nv_bfloat162(hx, hy);
                    ((__nv_bfloat162*)Clo)[idx] = __nv_bfloat162(lx, ly);
                }
            }
    }
}

__global__ void __launch_bounds__(256, 2) gemm_out(
    const __nv_bfloat16* __restrict__ Ahi, const __nv_bfloat16* __restrict__ Alo,
    const __nv_bfloat16* __restrict__ Bhi, const __nv_bfloat16* __restrict__ Blo,
    float* __restrict__ C)
{
    extern __shared__ char smc[];
    GemmCore g;
    g.init(smc, blockIdx.x, blockIdx.y, threadIdx.x);
    g.mainloop(smc, Ahi, Alo, Bhi, Blo, DIM);
    const int N = DIM;
#pragma unroll
    for (int ms = 0; ms < 4; ms++)
#pragma unroll
        for (int ns = 0; ns < 4; ns++) {
            int row = g.m0 + g.wm + ms * 16 + g.gid;
            int col = g.n0 + g.wn + ns * 8 + g.tig * 2;
            float2 c0 = {g.acc[ms][ns][0], g.acc[ms][ns][1]};
            float2 c1 = {g.acc[ms][ns][2], g.acc[ms][ns][3]};
            *(float2*)&C[(size_t)row * N + col]       = c0;
            *(float2*)&C[(size_t)(row + 8) * N + col] = c1;
        }
}

// ============================================================================
// tensor-core flash attention, bf16x3, causal; ldmatrix fragment loads;
// epilogue writes bf16 hi/lo split directly.   (unchanged from R6)
// ============================================================================
#define AQ  128
#define AK  64
#define AHS 136
#define AVS 72
#define A_QH        0
#define A_QL        17408
#define A_KH(bf)    (34816 + (bf)*8704)
#define A_KL(bf)    (52224 + (bf)*8704)
#define A_VH(bf)    (69632 + (bf)*9216)
#define A_VL(bf)    (88064 + (bf)*9216)
#define ATTN_SMEM_BYTES (106496*2)

__global__ void __launch_bounds__(256) attn_tc_kernel(
    const __nv_bfloat16* __restrict__ qhi, const __nv_bfloat16* __restrict__ qlo,
    const __nv_bfloat16* __restrict__ khi, const __nv_bfloat16* __restrict__ klo,
    const __nv_bfloat16* __restrict__ vthi, const __nv_bfloat16* __restrict__ vtlo,
    __nv_bfloat16* __restrict__ ohi, __nv_bfloat16* __restrict__ olo)
{
    extern __shared__ __nv_bfloat16 smh[];
    const uint32_t ubase = smem_u32(smh);

    const int t    = threadIdx.x;
    const int lane = t & 31;
    const int wid  = t >> 5;
    const int gid  = lane >> 2;
    const int tig  = lane & 3;
    const int qt = blockIdx.x, h = blockIdx.y, b = blockIdx.z;

    const int arow = (lane & 15);
    const int acol = (lane >> 4) << 3;
    const int brow = ((lane >> 4) << 3) + (lane & 7);
    const int bcol = ((lane >> 3) & 1) << 3;

    {
        int row = t >> 1;
        int cb  = (t & 1) * 8;
        size_t g = (size_t)(b * SEQ + qt * AQ + row) * DIM + h * HD + cb * 8;
        int so = row * AHS + cb * 8;
#pragma unroll
        for (int c = 0; c < 8; c++) {
            cp_async16(smh + A_QH + so + c * 8, qhi + g + c * 8);
            cp_async16(smh + A_QL + so + c * 8, qlo + g + c * 8);
        }
    }

#define LOAD_KV(BUFI, KT)                                                       \
    {                                                                           \
        int row = t >> 2;                                                       \
        int cb  = (t & 3) * 4;                                                  \
        size_t g = (size_t)(b * SEQ + (KT) * AK + row) * DIM + h * HD + cb * 8; \
        int so = row * AHS + cb * 8;                                            \
        _Pragma("unroll")                                                       \
        for (int c = 0; c < 4; c++) {                                           \
            cp_async16(smh + A_KH(BUFI) + so + c * 8, khi + g + c * 8);         \
            cp_async16(smh + A_KL(BUFI) + so + c * 8, klo + g + c * 8);         \
        }                                                                       \
        int vrow = t >> 1;                                                      \
        int vcb  = (t & 1) * 4;                                                 \
        size_t gv = (size_t)((b * NH + h) * HD + vrow) * SEQ + (KT) * AK + vcb * 8; \
        int sv = vrow * AVS + vcb * 8;                                          \
        _Pragma("unroll")                                                       \
        for (int c = 0; c < 4; c++) {                                           \
            cp_async16(smh + A_VH(BUFI) + sv + c * 8, vthi + gv + c * 8);       \
            cp_async16(smh + A_VL(BUFI) + sv + c * 8, vtlo + gv + c * 8);       \
        }                                                                       \
    }

    LOAD_KV(0, 0);
    CP_COMMIT();

    float sacc[8][4];
    float oacc[16][4];
#pragma unroll
    for (int i = 0; i < 16; i++)
#pragma unroll
        for (int e = 0; e < 4; e++) oacc[i][e] = 0.f;
    float m0 = -1e30f, m1 = -1e30f, l0 = 0.f, l1 = 0.f;

    const float scale = 0.08838834764831845f;
    const int gr0 = qt * AQ + wid * 16 + gid;
    const int ktmax = 2 * qt + 1;
    int buf = 0;

    for (int kt = 0; kt <= ktmax; kt++) {
        if (kt < ktmax) {
            LOAD_KV(buf ^ 1, kt + 1);
            CP_COMMIT();
            CP_WAIT1();
        } else {
            CP_WAIT0();
        }
        __syncthreads();

#pragma unroll
        for (int ns = 0; ns < 8; ns++)
#pragma unroll
            for (int e = 0; e < 4; e++) sacc[ns][e] = 0.f;

        const uint32_t ukh = ubase + A_KH(buf) * 2;
        const uint32_t ukl = ubase + A_KL(buf) * 2;
#pragma unroll
        for (int kk = 0; kk < 8; kk++) {
            uint32_t aoff = ((wid * 16 + arow) * AHS + kk * 16 + acol) * 2;
            uint32_t ah[4], al[4];
            ldsm_x4(ah, ubase + A_QH * 2 + aoff);
            ldsm_x4(al, ubase + A_QL * 2 + aoff);
#pragma unroll
            for (int nsp = 0; nsp < 4; nsp++) {
                uint32_t boff = ((nsp * 16 + brow) * AHS + kk * 16 + bcol) * 2;
                uint32_t rh[4], rl[4];
                ldsm_x4(rh, ukh + boff);
                ldsm_x4(rl, ukl + boff);
                uint32_t b0h[2] = {rh[0], rh[1]}, b1h[2] = {rh[2], rh[3]};
                uint32_t b0l[2] = {rl[0], rl[1]}, b1l[2] = {rl[2], rl[3]};
                mma_bf16(sacc[2*nsp],   ah, b0h);
                mma_bf16(sacc[2*nsp],   al, b0h);
                mma_bf16(sacc[2*nsp],   ah, b0l);
                mma_bf16(sacc[2*nsp+1], ah, b1h);
                mma_bf16(sacc[2*nsp+1], al, b1h);
                mma_bf16(sacc[2*nsp+1], ah, b1l);
            }
        }

        if (kt * AK + 63 > qt * AQ + wid * 16) {
            int rl0 = gr0 - kt * AK;
            int rl1 = rl0 + 8;
#pragma unroll
            for (int ns = 0; ns < 8; ns++) {
#pragma unroll
                for (int e = 0; e < 4; e++) {
                    float v = sacc[ns][e] * scale;
                    int cl = ns * 8 + 2 * tig + (e & 1);
                    int rl = (e < 2) ? rl0 : rl1;
                    sacc[ns][e] = (cl > rl) ? -1e30f : v;
                }
            }
        } else {
#pragma unroll
            for (int ns = 0; ns < 8; ns++)
#pragma unroll
                for (int e = 0; e < 4; e++) sacc[ns][e] *= scale;
        }

        float mx0 = -1e30f, mx1 = -1e30f;
#pragma unroll
        for (int ns = 0; ns < 8; ns++) {
            mx0 = fmaxf(mx0, fmaxf(sacc[ns][0], sacc[ns][1]));
            mx1 = fmaxf(mx1, fmaxf(sacc[ns][2], sacc[ns][3]));
        }
        mx0 = fmaxf(mx0, __shfl_xor_sync(0xffffffffu, mx0, 1));
        mx0 = fmaxf(mx0, __shfl_xor_sync(0xffffffffu, mx0, 2));
        mx1 = fmaxf(mx1, __shfl_xor_sync(0xffffffffu, mx1, 1));
        mx1 = fmaxf(mx1, __shfl_xor_sync(0xffffffffu, mx1, 2));
        float mn0 = fmaxf(m0, mx0), mn1 = fmaxf(m1, mx1);
        float a0 = __expf(m0 - mn0), a1 = __expf(m1 - mn1);
        m0 = mn0; m1 = mn1;

        float sum0 = 0.f, sum1 = 0.f;
#pragma unroll
        for (int ns = 0; ns < 8; ns++) {
            float p0 = __expf(sacc[ns][0] - mn0);
            float p1 = __expf(sacc[ns][1] - mn0);
            float p2 = __expf(sacc[ns][2] - mn1);
            float p3 = __expf(sacc[ns][3] - mn1);
            sacc[ns][0] = p0; sacc[ns][1] = p1;
            sacc[ns][2] = p2; sacc[ns][3] = p3;
            sum0 += p0 + p1; sum1 += p2 + p3;
        }
        sum0 += __shfl_xor_sync(0xffffffffu, sum0, 1);
        sum0 += __shfl_xor_sync(0xffffffffu, sum0, 2);
        sum1 += __shfl_xor_sync(0xffffffffu, sum1, 1);
        sum1 += __shfl_xor_sync(0xffffffffu, sum1, 2);
        l0 = l0 * a0 + sum0;
        l1 = l1 * a1 + sum1;

#pragma unroll
        for (int nd = 0; nd < 16; nd++) {
            oacc[nd][0] *= a0; oacc[nd][1] *= a0;
            oacc[nd][2] *= a1; oacc[nd][3] *= a1;
        }

        const uint32_t uvh = ubase + A_VH(buf) * 2;
        const uint32_t uvl = ubase + A_VL(buf) * 2;
#pragma unroll
        for (int kc = 0; kc < 4; kc++) {
            uint32_t ph[4], pl[4];
#pragma unroll
            for (int j = 0; j < 4; j++) {
                int ns = 2 * kc + (j >> 1);
                int e0 = (j & 1) * 2;
                float c0 = sacc[ns][e0], c1 = sacc[ns][e0 + 1];
                __nv_bfloat162 hb = __floats2bfloat162_rn(c0, c1);
                uint32_t hu = *(uint32_t*)&hb;
                float f0 = __uint_as_float(hu << 16);
                float f1 = __uint_as_float(hu & 0xffff0000u);
                __nv_bfloat162 lb = __floats2bfloat162_rn(c0 - f0, c1 - f1);
                ph[j] = hu;
                pl[j] = *(uint32_t*)&lb;
            }
#pragma unroll
            for (int ndp = 0; ndp < 8; ndp++) {
                uint32_t boff = ((ndp * 16 + brow) * AVS + kc * 16 + bcol) * 2;
                uint32_t rh[4], rl[4];
                ldsm_x4(rh, uvh + boff);
                ldsm_x4(rl, uvl + boff);
                uint32_t b0h[2] = {rh[0], rh[1]}, b1h[2] = {rh[2], rh[3]};
                uint32_t b0l[2] = {rl[0], rl[1]}, b1l[2] = {rl[2], rl[3]};
                mma_bf16(oacc[2*ndp],   ph, b0h);
                mma_bf16(oacc[2*ndp],   pl, b0h);
                mma_bf16(oacc[2*ndp],   ph, b0l);
                mma_bf16(oacc[2*ndp+1], ph, b1h);
                mma_bf16(oacc[2*ndp+1], pl, b1h);
                mma_bf16(oacc[2*ndp+1], ph, b1l);
            }
        }
        __syncthreads();
        buf ^= 1;
    }

    // ---- normalize + split-store ----
    float i0 = 1.f / l0, i1 = 1.f / l1;
    size_t r0 = (size_t)(b * SEQ + gr0) * DIM + h * HD;
    size_t r1 = r0 + 8 * DIM;
#pragma unroll
    for (int nd = 0; nd < 16; nd++) {
        int col = nd * 8 + 2 * tig;
        float w0x = oacc[nd][0] * i0, w0y = oacc[nd][1] * i0;
        float w1x = oacc[nd][2] * i1, w1y = oacc[nd][3] * i1;
        __nv_bfloat16 h0x = __float2bfloat16(w0x);
        __nv_bfloat16 h0y = __float2bfloat16(w0y);
        __nv_bfloat16 h1x = __float2bfloat16(w1x);
        __nv_bfloat16 h1y = __float2bfloat16(w1y);
        ((__nv_bfloat162*)&ohi[r0 + col])[0] = __nv_bfloat162(h0x, h0y);
        ((__nv_bfloat162*)&ohi[r1 + col])[0] = __nv_bfloat162(h1x, h1y);
        ((__nv_bfloat162*)&olo[r0 + col])[0] = __nv_bfloat162(
            __float2bfloat16(w0x - __bfloat162float(h0x)),
            __float2bfloat16(w0y - __bfloat162float(h0y)));
        ((__nv_bfloat162*)&olo[r1 + col])[0] = __nv_bfloat162(
            __float2bfloat16(w1x - __bfloat162float(h1x)),
            __float2bfloat16(w1y - __bfloat162float(h1y)));
    }
}

// ---------------- launcher ---------------------------------------------------
extern "C" void kernel_launch(void* const* d_in, const int* in_sizes, int n_in,
                              void* d_out, int out_size)
{
    const float* x    = (const float*)d_in[0];
    const float* w[4] = {(const float*)d_in[1], (const float*)d_in[2],
                         (const float*)d_in[3], (const float*)d_in[4]};
    const float* fcos = (const float*)d_in[5];
    const float* fsin = (const float*)d_in[6];
    float* out = (float*)d_out;

    float *v;
    cudaGetSymbolAddress((void**)&v, g_v);

    __nv_bfloat16 *xhi, *xlo, *ohi, *olo, *whi, *wlo;
    __nv_bfloat16 *qhi, *qlo, *khi, *klo, *vthi, *vtlo;
    cudaGetSymbolAddress((void**)&xhi, g_xhi);
    cudaGetSymbolAddress((void**)&xlo, g_xlo);
    cudaGetSymbolAddress((void**)&ohi, g_ohi);
    cudaGetSymbolAddress((void**)&olo, g_olo);
    cudaGetSymbolAddress((void**)&whi, g_whi);
    cudaGetSymbolAddress((void**)&wlo, g_wlo);
    cudaGetSymbolAddress((void**)&qhi, g_qhi);
    cudaGetSymbolAddress((void**)&qlo, g_qlo);
    cudaGetSymbolAddress((void**)&khi, g_khi);
    cudaGetSymbolAddress((void**)&klo, g_klo);
    cudaGetSymbolAddress((void**)&vthi, g_vthi);
    cudaGetSymbolAddress((void**)&vtlo, g_vtlo);

    cudaFuncSetAttribute(gemm_qkv,
                         cudaFuncAttributeMaxDynamicSharedMemorySize, GEMM_SMEM_BYTES);
    cudaFuncSetAttribute(gemm_out,
                         cudaFuncAttributeMaxDynamicSharedMemorySize, GEMM_SMEM_BYTES);
    cudaFuncSetAttribute(attn_tc_kernel,
                         cudaFuncAttributeMaxDynamicSharedMemorySize, ATTN_SMEM_BYTES);

    int nx4 = ROWS * DIM / 4;
    int nw4 = DIM * DIM / 4;
    split_kernel<<<nx4 / 256, 256>>>(x, xhi, xlo, nx4);
    for (int i = 0; i < 4; i++)
        split_kernel<<<nw4 / 256, 256>>>(w[i], whi + (size_t)i * DIM * DIM,
                                         wlo + (size_t)i * DIM * DIM, nw4);

    dim3 gqkv(DIM / BN, ROWS / BM, 3);   // (16, 32, 3)
    gemm_qkv<<<gqkv, 256, GEMM_SMEM_BYTES>>>(
        xhi, xlo, whi, wlo, qhi, qlo, khi, klo, v, fcos, fsin);

    vtrans_split_kernel<<<dim3(DIM / 32, ROWS / 32), dim3(32, 8)>>>(v, vthi, vtlo);

    attn_tc_kernel<<<dim3(SEQ / AQ, NH, BATCH), 256, ATTN_SMEM_BYTES>>>(
        qhi, qlo, khi, klo, vthi, vtlo, ohi, olo);

    gemm_out<<<dim3(DIM / BN, ROWS / BM), 256, GEMM_SMEM_BYTES>>>(
        ohi, olo, whi + 3*(size_t)DIM*DIM, wlo + 3*(size_t)DIM*DIM, out);
}

// round 8
// speedup vs baseline: 3.0677x; 1.1110x over previous
#include <cuda_runtime.h>
#include <cuda_bf16.h>
#include <cstdint>

#define BATCH 2
#define SEQ   2048
#define DIM   2048
#define NH    16
#define HD    128
#define ROWS  (BATCH*SEQ)   // 4096

// ---------------- scratch (static device globals; no allocs allowed) --------
__device__ float g_v[ROWS*DIM];

__device__ __nv_bfloat16 g_xhi[ROWS*DIM];
__device__ __nv_bfloat16 g_xlo[ROWS*DIM];
__device__ __nv_bfloat16 g_ohi[ROWS*DIM];
__device__ __nv_bfloat16 g_olo[ROWS*DIM];
__device__ __nv_bfloat16 g_whi[4][DIM*DIM];   // q,k,v,o
__device__ __nv_bfloat16 g_wlo[4][DIM*DIM];

__device__ __nv_bfloat16 g_qhi[ROWS*DIM];
__device__ __nv_bfloat16 g_qlo[ROWS*DIM];
__device__ __nv_bfloat16 g_khi[ROWS*DIM];
__device__ __nv_bfloat16 g_klo[ROWS*DIM];
__device__ __nv_bfloat16 g_vthi[ROWS*DIM];    // per-head transposed [b,h,d,s]
__device__ __nv_bfloat16 g_vtlo[ROWS*DIM];

// ============================================================================
// helpers
// ============================================================================
__device__ __forceinline__ void cp_async16(void* smem, const void* gmem) {
    uint32_t s = (uint32_t)__cvta_generic_to_shared(smem);
    asm volatile("cp.async.cg.shared.global [%0], [%1], 16;\n" :: "r"(s), "l"(gmem));
}
__device__ __forceinline__ void cp_async16_s(uint32_t saddr, const void* gmem) {
    asm volatile("cp.async.cg.shared.global [%0], [%1], 16;\n" :: "r"(saddr), "l"(gmem));
}
#define CP_COMMIT() asm volatile("cp.async.commit_group;\n" ::: "memory")
#define CP_WAIT1()  asm volatile("cp.async.wait_group 1;\n" ::: "memory")
#define CP_WAIT0()  asm volatile("cp.async.wait_group 0;\n" ::: "memory")

__device__ __forceinline__ void mma_bf16(float* c, const uint32_t* a, const uint32_t* b) {
    asm volatile(
        "mma.sync.aligned.m16n8k16.row.col.f32.bf16.bf16.f32 "
        "{%0,%1,%2,%3}, {%4,%5,%6,%7}, {%8,%9}, {%0,%1,%2,%3};\n"
        : "+f"(c[0]), "+f"(c[1]), "+f"(c[2]), "+f"(c[3])
        : "r"(a[0]), "r"(a[1]), "r"(a[2]), "r"(a[3]),
          "r"(b[0]), "r"(b[1]));
}
__device__ __forceinline__ void ldsm_x4(uint32_t* r, uint32_t saddr) {
    asm volatile("ldmatrix.sync.aligned.m8n8.x4.shared.b16 {%0,%1,%2,%3}, [%4];"
        : "=r"(r[0]), "=r"(r[1]), "=r"(r[2]), "=r"(r[3]) : "r"(saddr));
}
__device__ __forceinline__ uint32_t smem_u32(const void* p) {
    return (uint32_t)__cvta_generic_to_shared(p);
}

// ---------------- fp32 -> bf16 hi/lo split ----------------------------------
__global__ void split_kernel(const float* __restrict__ in,
                             __nv_bfloat16* __restrict__ hi,
                             __nv_bfloat16* __restrict__ lo, int n4)
{
    int idx = blockIdx.x * blockDim.x + threadIdx.x;
    if (idx >= n4) return;
    float4 v = ((const float4*)in)[idx];
    __nv_bfloat16 h0 = __float2bfloat16(v.x);
    __nv_bfloat16 h1 = __float2bfloat16(v.y);
    __nv_bfloat16 h2 = __float2bfloat16(v.z);
    __nv_bfloat16 h3 = __float2bfloat16(v.w);
    __nv_bfloat16 l0 = __float2bfloat16(v.x - __bfloat162float(h0));
    __nv_bfloat16 l1 = __float2bfloat16(v.y - __bfloat162float(h1));
    __nv_bfloat16 l2 = __float2bfloat16(v.z - __bfloat162float(h2));
    __nv_bfloat16 l3 = __float2bfloat16(v.w - __bfloat162float(h3));
    ((__nv_bfloat162*)hi)[idx*2+0] = __nv_bfloat162(h0, h1);
    ((__nv_bfloat162*)hi)[idx*2+1] = __nv_bfloat162(h2, h3);
    ((__nv_bfloat162*)lo)[idx*2+0] = __nv_bfloat162(l0, l1);
    ((__nv_bfloat162*)lo)[idx*2+1] = __nv_bfloat162(l2, l3);
}

// ---------------- V transpose + split: [b,s,h,d] -> [b,h,d,s] ----------------
__global__ void vtrans_split_kernel(const float* __restrict__ v,
                                    __nv_bfloat16* __restrict__ vthi,
                                    __nv_bfloat16* __restrict__ vtlo)
{
    __shared__ float tile[32][33];
    int c0 = blockIdx.x * 32, s0 = blockIdx.y * 32;
    int tx = threadIdx.x, ty = threadIdx.y;
#pragma unroll
    for (int i = 0; i < 4; i++)
        tile[ty + 8*i][tx] = v[(size_t)(s0 + ty + 8*i) * DIM + c0 + tx];
    __syncthreads();
    int sg = s0 + tx;
    int b  = sg >> 11;
    int sl = sg & (SEQ - 1);
#pragma unroll
    for (int i = 0; i < 4; i++) {
        int cg = c0 + ty + 8*i;
        int h  = cg >> 7;
        int d  = cg & 127;
        float val = tile[tx][ty + 8*i];
        __nv_bfloat16 hv = __float2bfloat16(val);
        __nv_bfloat16 lv = __float2bfloat16(val - __bfloat162float(hv));
        size_t o = ((size_t)((b * NH + h) * HD + d)) * SEQ + sl;
        vthi[o] = hv;
        vtlo[o] = lv;
    }
}

// ============================================================================
// bf16x3 GEMM: ldmatrix + XOR-swizzled smem, 3-stage cp.async, 1 sync/iter,
// 2 CTAs/SM.  C = (Ahi+Alo) (Bhi+Blo)^T
// ============================================================================
#define BM 128
#define BN 128
#define BK 32
#define NSTG 3
#define TILE_B (BM*BK*2)            // 8192 bytes per tile per stage
#define GEMM_SMEM_BYTES (4*NSTG*TILE_B)   // 98304

// swizzled byte offset for (row, 16B-chunk) within a tile; chunk in 0..3
__device__ __forceinline__ uint32_t swz(int row, int chunk) {
    return (uint32_t)(row * 64 + ((chunk ^ ((row >> 1) & 3)) << 4));
}

struct GemmCore {
    uint32_t uAh, uAl, uBh, uBl;
    int t, lane, wid, gid, tig, wm, wn, m0, n0;
    int arow, achk, brow, bchk;
    int lr0, lc0, lr1;
    uint32_t so0, so1;       // swizzled in-tile store offsets for the 2 chunks
    float acc[4][4][4];

    __device__ __forceinline__ void init(char* smc, int bx, int by, int tid) {
        uAh = smem_u32(smc);
        uAl = uAh + NSTG * TILE_B;
        uBh = uAh + 2 * NSTG * TILE_B;
        uBl = uAh + 3 * NSTG * TILE_B;
        t = tid; lane = t & 31; wid = t >> 5;
        gid = lane >> 2; tig = lane & 3;
        wm = (wid & 1) * 64; wn = (wid >> 1) * 32;
        m0 = by * BM; n0 = bx * BN;
        arow = lane & 15; achk = lane >> 4;              // A: 0/1 chunk within k-slice
        brow = ((lane >> 4) << 3) + (lane & 7);
        bchk = (lane >> 3) & 1;
        lr0 = t >> 2; lc0 = (t & 3) * 8; lr1 = lr0 + 64;
        so0 = swz(lr0, t & 3);
        so1 = swz(lr1, t & 3);
#pragma unroll
        for (int i = 0; i < 4; i++)
#pragma unroll
            for (int j = 0; j < 4; j++)
#pragma unroll
                for (int e = 0; e < 4; e++) acc[i][j][e] = 0.f;
    }

    __device__ __forceinline__ void load_stage(
        int stg, int k0,
        const __nv_bfloat16* Ahi, const __nv_bfloat16* Alo,
        const __nv_bfloat16* Bhi, const __nv_bfloat16* Blo, int K)
    {
        const uint32_t sb = stg * TILE_B;
        size_t ga0 = (size_t)(m0 + lr0) * K + k0 + lc0;
        size_t ga1 = (size_t)(m0 + lr1) * K + k0 + lc0;
        size_t gb0 = (size_t)(n0 + lr0) * K + k0 + lc0;
        size_t gb1 = (size_t)(n0 + lr1) * K + k0 + lc0;
        cp_async16_s(uAh + sb + so0, Ahi + ga0);  cp_async16_s(uAh + sb + so1, Ahi + ga1);
        cp_async16_s(uAl + sb + so0, Alo + ga0);  cp_async16_s(uAl + sb + so1, Alo + ga1);
        cp_async16_s(uBh + sb + so0, Bhi + gb0);  cp_async16_s(uBh + sb + so1, Bhi + gb1);
        cp_async16_s(uBl + sb + so0, Blo + gb0);  cp_async16_s(uBl + sb + so1, Blo + gb1);
        CP_COMMIT();
    }

    __device__ __forceinline__ void consume_stage(int stg) {
        const uint32_t stb = stg * TILE_B;
#pragma unroll
        for (int kk = 0; kk < 2; kk++) {
            uint32_t ah[4][4], al[4][4], bh[4][2], bl[4][2];
#pragma unroll
            for (int ms = 0; ms < 4; ms++) {
                int row = wm + ms * 16 + arow;
                uint32_t off = stb + swz(row, 2 * kk + achk);
                ldsm_x4(ah[ms], uAh + off);
                ldsm_x4(al[ms], uAl + off);
            }
#pragma unroll
            for (int nsp = 0; nsp < 2; nsp++) {
                int row = wn + nsp * 16 + brow;
                uint32_t off = stb + swz(row, 2 * kk + bchk);
                uint32_t r[4];
                ldsm_x4(r, uBh + off);
                bh[2*nsp][0] = r[0]; bh[2*nsp][1] = r[1];
                bh[2*nsp+1][0] = r[2]; bh[2*nsp+1][1] = r[3];
                ldsm_x4(r, uBl + off);
                bl[2*nsp][0] = r[0]; bl[2*nsp][1] = r[1];
                bl[2*nsp+1][0] = r[2]; bl[2*nsp+1][1] = r[3];
            }
#pragma unroll
            for (int ms = 0; ms < 4; ms++)
#pragma unroll
                for (int ns = 0; ns < 4; ns++) {
                    mma_bf16(acc[ms][ns], ah[ms], bh[ns]);
                    mma_bf16(acc[ms][ns], al[ms], bh[ns]);
                    mma_bf16(acc[ms][ns], ah[ms], bl[ns]);
                }
        }
    }

    __device__ __forceinline__ void mainloop(
        const __nv_bfloat16* Ahi, const __nv_bfloat16* Alo,
        const __nv_bfloat16* Bhi, const __nv_bfloat16* Blo, int K)
    {
        const int NK = K / BK;
        load_stage(0, 0, Ahi, Alo, Bhi, Blo, K);
        load_stage(1, BK, Ahi, Alo, Bhi, Blo, K);
        int s2 = 2;   // stage for kt+2 loads, cycles 2,0,1,...
        for (int kt = 0; kt < NK; kt++) {
            if (kt + 1 < NK) { CP_WAIT1(); } else { CP_WAIT0(); }
            __syncthreads();
            if (kt + 2 < NK) {
                load_stage(s2, (kt + 2) * BK, Ahi, Alo, Bhi, Blo, K);
            }
            int sc = s2 + 1; if (sc >= NSTG) sc -= NSTG;   // = kt % 3
            consume_stage(sc);
            s2 = sc;
        }
    }
};

__global__ void __launch_bounds__(256, 2) gemm_qkv(
    const __nv_bfloat16* __restrict__ xhi, const __nv_bfloat16* __restrict__ xlo,
    const __nv_bfloat16* __restrict__ whi, const __nv_bfloat16* __restrict__ wlo,
    __nv_bfloat16* __restrict__ qhi, __nv_bfloat16* __restrict__ qlo,
    __nv_bfloat16* __restrict__ khi, __nv_bfloat16* __restrict__ klo,
    float* __restrict__ v,
    const float* __restrict__ fc, const float* __restrict__ fs)
{
    extern __shared__ char smc[];
    const int proj = blockIdx.z;
    GemmCore g;
    g.init(smc, blockIdx.x, blockIdx.y, threadIdx.x);
    g.mainloop(xhi, xlo,
               whi + (size_t)proj * DIM * DIM, wlo + (size_t)proj * DIM * DIM, DIM);

    const int N = DIM;
    if (proj == 2) {
#pragma unroll
        for (int ms = 0; ms < 4; ms++)
#pragma unroll
            for (int ns = 0; ns < 4; ns++) {
                int row = g.m0 + g.wm + ms * 16 + g.gid;
                int col = g.n0 + g.wn + ns * 8 + g.tig * 2;
                float2 c0 = {g.acc[ms][ns][0], g.acc[ms][ns][1]};
                float2 c1 = {g.acc[ms][ns][2], g.acc[ms][ns][3]};
                *(float2*)&v[(size_t)row * N + col]       = c0;
                *(float2*)&v[(size_t)(row + 8) * N + col] = c1;
            }
    } else {
        __nv_bfloat16* Chi = proj ? khi : qhi;
        __nv_bfloat16* Clo = proj ? klo : qlo;
#pragma unroll
        for (int ms = 0; ms < 4; ms++)
#pragma unroll
            for (int ns = 0; ns < 4; ns++) {
                int row0 = g.m0 + g.wm + ms * 16 + g.gid;
                int col  = g.n0 + g.wn + ns * 8 + g.tig * 2;
                int i = (col & 127) >> 1;
#pragma unroll
                for (int half = 0; half < 2; half++) {
                    int row = row0 + half * 8;
                    int s   = row & (SEQ - 1);
                    float cs = __ldg(fc + s * 64 + i);
                    float sn = __ldg(fs + s * 64 + i);
                    float re = g.acc[ms][ns][half * 2];
                    float im = g.acc[ms][ns][half * 2 + 1];
                    float rx = re * cs - im * sn;
                    float ry = re * sn + im * cs;
                    __nv_bfloat16 hx = __float2bfloat16(rx);
                    __nv_bfloat16 hy = __float2bfloat16(ry);
                    __nv_bfloat16 lx = __float2bfloat16(rx - __bfloat162float(hx));
                    __nv_bfloat16 ly = __float2bfloat16(ry - __bfloat162float(hy));
                    size_t idx = ((size_t)row * N + col) >> 1;
                    ((__nv_bfloat162*)Chi)[idx] = __nv_bfloat162(hx, hy);
                    ((__nv_bfloat162*)Clo)[idx] = __nv_bfloat162(lx, ly);
                }
            }
    }
}

__global__ void __launch_bounds__(256, 2) gemm_out(
    const __nv_bfloat16* __restrict__ Ahi, const __nv_bfloat16* __restrict__ Alo,
    const __nv_bfloat16* __restrict__ Bhi, const __nv_bfloat16* __restrict__ Blo,
    float* __restrict__ C)
{
    extern __shared__ char smc[];
    GemmCore g;
    g.init(smc, blockIdx.x, blockIdx.y, threadIdx.x);
    g.mainloop(Ahi, Alo, Bhi, Blo, DIM);
    const int N = DIM;
#pragma unroll
    for (int ms = 0; ms < 4; ms++)
#pragma unroll
        for (int ns = 0; ns < 4; ns++) {
            int row = g.m0 + g.wm + ms * 16 + g.gid;
            int col = g.n0 + g.wn + ns * 8 + g.tig * 2;
            float2 c0 = {g.acc[ms][ns][0], g.acc[ms][ns][1]};
            float2 c1 = {g.acc[ms][ns][2], g.acc[ms][ns][3]};
            *(float2*)&C[(size_t)row * N + col]       = c0;
            *(float2*)&C[(size_t)(row + 8) * N + col] = c1;
        }
}

// ============================================================================
// tensor-core flash attention, bf16x3, causal (unchanged from R7)
// ============================================================================
#define AQ  128
#define AK  64
#define AHS 136
#define AVS 72
#define A_QH        0
#define A_QL        17408
#define A_KH(bf)    (34816 + (bf)*8704)
#define A_KL(bf)    (52224 + (bf)*8704)
#define A_VH(bf)    (69632 + (bf)*9216)
#define A_VL(bf)    (88064 + (bf)*9216)
#define ATTN_SMEM_BYTES (106496*2)

__global__ void __launch_bounds__(256) attn_tc_kernel(
    const __nv_bfloat16* __restrict__ qhi, const __nv_bfloat16* __restrict__ qlo,
    const __nv_bfloat16* __restrict__ khi, const __nv_bfloat16* __restrict__ klo,
    const __nv_bfloat16* __restrict__ vthi, const __nv_bfloat16* __restrict__ vtlo,
    __nv_bfloat16* __restrict__ ohi, __nv_bfloat16* __restrict__ olo)
{
    extern __shared__ __nv_bfloat16 smh[];
    const uint32_t ubase = smem_u32(smh);

    const int t    = threadIdx.x;
    const int lane = t & 31;
    const int wid  = t >> 5;
    const int gid  = lane >> 2;
    const int tig  = lane & 3;
    const int qt = blockIdx.x, h = blockIdx.y, b = blockIdx.z;

    const int arow = (lane & 15);
    const int acol = (lane >> 4) << 3;
    const int brow = ((lane >> 4) << 3) + (lane & 7);
    const int bcol = ((lane >> 3) & 1) << 3;

    {
        int row = t >> 1;
        int cb  = (t & 1) * 8;
        size_t g = (size_t)(b * SEQ + qt * AQ + row) * DIM + h * HD + cb * 8;
        int so = row * AHS + cb * 8;
#pragma unroll
        for (int c = 0; c < 8; c++) {
            cp_async16(smh + A_QH + so + c * 8, qhi + g + c * 8);
            cp_async16(smh + A_QL + so + c * 8, qlo + g + c * 8);
        }
    }

#define LOAD_KV(BUFI, KT)                                                       \
    {                                                                           \
        int row = t >> 2;                                                       \
        int cb  = (t & 3) * 4;                                                  \
        size_t g = (size_t)(b * SEQ + (KT) * AK + row) * DIM + h * HD + cb * 8; \
        int so = row * AHS + cb * 8;                                            \
        _Pragma("unroll")                                                       \
        for (int c = 0; c < 4; c++) {                                           \
            cp_async16(smh + A_KH(BUFI) + so + c * 8, khi + g + c * 8);         \
            cp_async16(smh + A_KL(BUFI) + so + c * 8, klo + g + c * 8);         \
        }                                                                       \
        int vrow = t >> 1;                                                      \
        int vcb  = (t & 1) * 4;                                                 \
        size_t gv = (size_t)((b * NH + h) * HD + vrow) * SEQ + (KT) * AK + vcb * 8; \
        int sv = vrow * AVS + vcb * 8;                                          \
        _Pragma("unroll")                                                       \
        for (int c = 0; c < 4; c++) {                                           \
            cp_async16(smh + A_VH(BUFI) + sv + c * 8, vthi + gv + c * 8);       \
            cp_async16(smh + A_VL(BUFI) + sv + c * 8, vtlo + gv + c * 8);       \
        }                                                                       \
    }

    LOAD_KV(0, 0);
    CP_COMMIT();

    float sacc[8][4];
    float oacc[16][4];
#pragma unroll
    for (int i = 0; i < 16; i++)
#pragma unroll
        for (int e = 0; e < 4; e++) oacc[i][e] = 0.f;
    float m0 = -1e30f, m1 = -1e30f, l0 = 0.f, l1 = 0.f;

    const float scale = 0.08838834764831845f;
    const int gr0 = qt * AQ + wid * 16 + gid;
    const int ktmax = 2 * qt + 1;
    int buf = 0;

    for (int kt = 0; kt <= ktmax; kt++) {
        if (kt < ktmax) {
            LOAD_KV(buf ^ 1, kt + 1);
            CP_COMMIT();
            CP_WAIT1();
        } else {
            CP_WAIT0();
        }
        __syncthreads();

#pragma unroll
        for (int ns = 0; ns < 8; ns++)
#pragma unroll
            for (int e = 0; e < 4; e++) sacc[ns][e] = 0.f;

        const uint32_t ukh = ubase + A_KH(buf) * 2;
        const uint32_t ukl = ubase + A_KL(buf) * 2;
#pragma unroll
        for (int kk = 0; kk < 8; kk++) {
            uint32_t aoff = ((wid * 16 + arow) * AHS + kk * 16 + acol) * 2;
            uint32_t ah[4], al[4];
            ldsm_x4(ah, ubase + A_QH * 2 + aoff);
            ldsm_x4(al, ubase + A_QL * 2 + aoff);
#pragma unroll
            for (int nsp = 0; nsp < 4; nsp++) {
                uint32_t boff = ((nsp * 16 + brow) * AHS + kk * 16 + bcol) * 2;
                uint32_t rh[4], rl[4];
                ldsm_x4(rh, ukh + boff);
                ldsm_x4(rl, ukl + boff);
                uint32_t b0h[2] = {rh[0], rh[1]}, b1h[2] = {rh[2], rh[3]};
                uint32_t b0l[2] = {rl[0], rl[1]}, b1l[2] = {rl[2], rl[3]};
                mma_bf16(sacc[2*nsp],   ah, b0h);
                mma_bf16(sacc[2*nsp],   al, b0h);
                mma_bf16(sacc[2*nsp],   ah, b0l);
                mma_bf16(sacc[2*nsp+1], ah, b1h);
                mma_bf16(sacc[2*nsp+1], al, b1h);
                mma_bf16(sacc[2*nsp+1], ah, b1l);
            }
        }

        if (kt * AK + 63 > qt * AQ + wid * 16) {
            int rl0 = gr0 - kt * AK;
            int rl1 = rl0 + 8;
#pragma unroll
            for (int ns = 0; ns < 8; ns++) {
#pragma unroll
                for (int e = 0; e < 4; e++) {
                    float v = sacc[ns][e] * scale;
                    int cl = ns * 8 + 2 * tig + (e & 1);
                    int rl = (e < 2) ? rl0 : rl1;
                    sacc[ns][e] = (cl > rl) ? -1e30f : v;
                }
            }
        } else {
#pragma unroll
            for (int ns = 0; ns < 8; ns++)
#pragma unroll
                for (int e = 0; e < 4; e++) sacc[ns][e] *= scale;
        }

        float mx0 = -1e30f, mx1 = -1e30f;
#pragma unroll
        for (int ns = 0; ns < 8; ns++) {
            mx0 = fmaxf(mx0, fmaxf(sacc[ns][0], sacc[ns][1]));
            mx1 = fmaxf(mx1, fmaxf(sacc[ns][2], sacc[ns][3]));
        }
        mx0 = fmaxf(mx0, __shfl_xor_sync(0xffffffffu, mx0, 1));
        mx0 = fmaxf(mx0, __shfl_xor_sync(0xffffffffu, mx0, 2));
        mx1 = fmaxf(mx1, __shfl_xor_sync(0xffffffffu, mx1, 1));
        mx1 = fmaxf(mx1, __shfl_xor_sync(0xffffffffu, mx1, 2));
        float mn0 = fmaxf(m0, mx0), mn1 = fmaxf(m1, mx1);
        float a0 = __expf(m0 - mn0), a1 = __expf(m1 - mn1);
        m0 = mn0; m1 = mn1;

        float sum0 = 0.f, sum1 = 0.f;
#pragma unroll
        for (int ns = 0; ns < 8; ns++) {
            float p0 = __expf(sacc[ns][0] - mn0);
            float p1 = __expf(sacc[ns][1] - mn0);
            float p2 = __expf(sacc[ns][2] - mn1);
            float p3 = __expf(sacc[ns][3] - mn1);
            sacc[ns][0] = p0; sacc[ns][1] = p1;
            sacc[ns][2] = p2; sacc[ns][3] = p3;
            sum0 += p0 + p1; sum1 += p2 + p3;
        }
        sum0 += __shfl_xor_sync(0xffffffffu, sum0, 1);
        sum0 += __shfl_xor_sync(0xffffffffu, sum0, 2);
        sum1 += __shfl_xor_sync(0xffffffffu, sum1, 1);
        sum1 += __shfl_xor_sync(0xffffffffu, sum1, 2);
        l0 = l0 * a0 + sum0;
        l1 = l1 * a1 + sum1;

#pragma unroll
        for (int nd = 0; nd < 16; nd++) {
            oacc[nd][0] *= a0; oacc[nd][1] *= a0;
            oacc[nd][2] *= a1; oacc[nd][3] *= a1;
        }

        const uint32_t uvh = ubase + A_VH(buf) * 2;
        const uint32_t uvl = ubase + A_VL(buf) * 2;
#pragma unroll
        for (int kc = 0; kc < 4; kc++) {
            uint32_t ph[4], pl[4];
#pragma unroll
            for (int j = 0; j < 4; j++) {
                int ns = 2 * kc + (j >> 1);
                int e0 = (j & 1) * 2;
                float c0 = sacc[ns][e0], c1 = sacc[ns][e0 + 1];
                __nv_bfloat162 hb = __floats2bfloat162_rn(c0, c1);
                uint32_t hu = *(uint32_t*)&hb;
                float f0 = __uint_as_float(hu << 16);
                float f1 = __uint_as_float(hu & 0xffff0000u);
                __nv_bfloat162 lb = __floats2bfloat162_rn(c0 - f0, c1 - f1);
                ph[j] = hu;
                pl[j] = *(uint32_t*)&lb;
            }
#pragma unroll
            for (int ndp = 0; ndp < 8; ndp++) {
                uint32_t boff = ((ndp * 16 + brow) * AVS + kc * 16 + bcol) * 2;
                uint32_t rh[4], rl[4];
                ldsm_x4(rh, uvh + boff);
                ldsm_x4(rl, uvl + boff);
                uint32_t b0h[2] = {rh[0], rh[1]}, b1h[2] = {rh[2], rh[3]};
                uint32_t b0l[2] = {rl[0], rl[1]}, b1l[2] = {rl[2], rl[3]};
                mma_bf16(oacc[2*ndp],   ph, b0h);
                mma_bf16(oacc[2*ndp],   pl, b0h);
                mma_bf16(oacc[2*ndp],   ph, b0l);
                mma_bf16(oacc[2*ndp+1], ph, b1h);
                mma_bf16(oacc[2*ndp+1], pl, b1h);
                mma_bf16(oacc[2*ndp+1], ph, b1l);
            }
        }
        __syncthreads();
        buf ^= 1;
    }

    // ---- normalize + split-store ----
    float i0 = 1.f / l0, i1 = 1.f / l1;
    size_t r0 = (size_t)(b * SEQ + gr0) * DIM + h * HD;
    size_t r1 = r0 + 8 * DIM;
#pragma unroll
    for (int nd = 0; nd < 16; nd++) {
        int col = nd * 8 + 2 * tig;
        float w0x = oacc[nd][0] * i0, w0y = oacc[nd][1] * i0;
        float w1x = oacc[nd][2] * i1, w1y = oacc[nd][3] * i1;
        __nv_bfloat16 h0x = __float2bfloat16(w0x);
        __nv_bfloat16 h0y = __float2bfloat16(w0y);
        __nv_bfloat16 h1x = __float2bfloat16(w1x);
        __nv_bfloat16 h1y = __float2bfloat16(w1y);
        ((__nv_bfloat162*)&ohi[r0 + col])[0] = __nv_bfloat162(h0x, h0y);
        ((__nv_bfloat162*)&ohi[r1 + col])[0] = __nv_bfloat162(h1x, h1y);
        ((__nv_bfloat162*)&olo[r0 + col])[0] = __nv_bfloat162(
            __float2bfloat16(w0x - __bfloat162float(h0x)),
            __float2bfloat16(w0y - __bfloat162float(h0y)));
        ((__nv_bfloat162*)&olo[r1 + col])[0] = __nv_bfloat162(
            __float2bfloat16(w1x - __bfloat162float(h1x)),
            __float2bfloat16(w1y - __bfloat162float(h1y)));
    }
}

// ---------------- launcher ---------------------------------------------------
extern "C" void kernel_launch(void* const* d_in, const int* in_sizes, int n_in,
                              void* d_out, int out_size)
{
    const float* x    = (const float*)d_in[0];
    const float* w[4] = {(const float*)d_in[1], (const float*)d_in[2],
                         (const float*)d_in[3], (const float*)d_in[4]};
    const float* fcos = (const float*)d_in[5];
    const float* fsin = (const float*)d_in[6];
    float* out = (float*)d_out;

    float *v;
    cudaGetSymbolAddress((void**)&v, g_v);

    __nv_bfloat16 *xhi, *xlo, *ohi, *olo, *whi, *wlo;
    __nv_bfloat16 *qhi, *qlo, *khi, *klo, *vthi, *vtlo;
    cudaGetSymbolAddress((void**)&xhi, g_xhi);
    cudaGetSymbolAddress((void**)&xlo, g_xlo);
    cudaGetSymbolAddress((void**)&ohi, g_ohi);
    cudaGetSymbolAddress((void**)&olo, g_olo);
    cudaGetSymbolAddress((void**)&whi, g_whi);
    cudaGetSymbolAddress((void**)&wlo, g_wlo);
    cudaGetSymbolAddress((void**)&qhi, g_qhi);
    cudaGetSymbolAddress((void**)&qlo, g_qlo);
    cudaGetSymbolAddress((void**)&khi, g_khi);
    cudaGetSymbolAddress((void**)&klo, g_klo);
    cudaGetSymbolAddress((void**)&vthi, g_vthi);
    cudaGetSymbolAddress((void**)&vtlo, g_vtlo);

    cudaFuncSetAttribute(gemm_qkv,
                         cudaFuncAttributeMaxDynamicSharedMemorySize, GEMM_SMEM_BYTES);
    cudaFuncSetAttribute(gemm_out,
                         cudaFuncAttributeMaxDynamicSharedMemorySize, GEMM_SMEM_BYTES);
    cudaFuncSetAttribute(attn_tc_kernel,
                         cudaFuncAttributeMaxDynamicSharedMemorySize, ATTN_SMEM_BYTES);

    int nx4 = ROWS * DIM / 4;
    int nw4 = DIM * DIM / 4;
    split_kernel<<<nx4 / 256, 256>>>(x, xhi, xlo, nx4);
    for (int i = 0; i < 4; i++)
        split_kernel<<<nw4 / 256, 256>>>(w[i], whi + (size_t)i * DIM * DIM,
                                         wlo + (size_t)i * DIM * DIM, nw4);

    dim3 gqkv(DIM / BN, ROWS / BM, 3);   // (16, 32, 3)
    gemm_qkv<<<gqkv, 256, GEMM_SMEM_BYTES>>>(
        xhi, xlo, whi, wlo, qhi, qlo, khi, klo, v, fcos, fsin);

    vtrans_split_kernel<<<dim3(DIM / 32, ROWS / 32), dim3(32, 8)>>>(v, vthi, vtlo);

    attn_tc_kernel<<<dim3(SEQ / AQ, NH, BATCH), 256, ATTN_SMEM_BYTES>>>(
        qhi, qlo, khi, klo, vthi, vtlo, ohi, olo);

    gemm_out<<<dim3(DIM / BN, ROWS / BM), 256, GEMM_SMEM_BYTES>>>(
        ohi, olo, whi + 3*(size_t)DIM*DIM, wlo + 3*(size_t)DIM*DIM, out);
}

// round 9
// speedup vs baseline: 3.0928x; 1.0082x over previous
#include <cuda_runtime.h>
#include <cuda_bf16.h>
#include <cstdint>

#define BATCH 2
#define SEQ   2048
#define DIM   2048
#define NH    16
#define HD    128
#define ROWS  (BATCH*SEQ)   // 4096

// ---------------- scratch (static device globals; no allocs allowed) --------
__device__ __nv_bfloat16 g_xhi[ROWS*DIM];
__device__ __nv_bfloat16 g_xlo[ROWS*DIM];
__device__ __nv_bfloat16 g_ohi[ROWS*DIM];
__device__ __nv_bfloat16 g_olo[ROWS*DIM];
__device__ __nv_bfloat16 g_whi[4][DIM*DIM];   // q,k,v,o
__device__ __nv_bfloat16 g_wlo[4][DIM*DIM];

__device__ __nv_bfloat16 g_qhi[ROWS*DIM];
__device__ __nv_bfloat16 g_qlo[ROWS*DIM];
__device__ __nv_bfloat16 g_khi[ROWS*DIM];
__device__ __nv_bfloat16 g_klo[ROWS*DIM];
__device__ __nv_bfloat16 g_vthi[ROWS*DIM];    // per-head transposed [b,h,d,s]
__device__ __nv_bfloat16 g_vtlo[ROWS*DIM];

// ============================================================================
// helpers
// ============================================================================
__device__ __forceinline__ void cp_async16(void* smem, const void* gmem) {
    uint32_t s = (uint32_t)__cvta_generic_to_shared(smem);
    asm volatile("cp.async.cg.shared.global [%0], [%1], 16;\n" :: "r"(s), "l"(gmem));
}
__device__ __forceinline__ void cp_async16_s(uint32_t saddr, const void* gmem) {
    asm volatile("cp.async.cg.shared.global [%0], [%1], 16;\n" :: "r"(saddr), "l"(gmem));
}
#define CP_COMMIT() asm volatile("cp.async.commit_group;\n" ::: "memory")
#define CP_WAIT1()  asm volatile("cp.async.wait_group 1;\n" ::: "memory")
#define CP_WAIT0()  asm volatile("cp.async.wait_group 0;\n" ::: "memory")

__device__ __forceinline__ void mma_bf16(float* c, const uint32_t* a, const uint32_t* b) {
    asm volatile(
        "mma.sync.aligned.m16n8k16.row.col.f32.bf16.bf16.f32 "
        "{%0,%1,%2,%3}, {%4,%5,%6,%7}, {%8,%9}, {%0,%1,%2,%3};\n"
        : "+f"(c[0]), "+f"(c[1]), "+f"(c[2]), "+f"(c[3])
        : "r"(a[0]), "r"(a[1]), "r"(a[2]), "r"(a[3]),
          "r"(b[0]), "r"(b[1]));
}
__device__ __forceinline__ void ldsm_x4(uint32_t* r, uint32_t saddr) {
    asm volatile("ldmatrix.sync.aligned.m8n8.x4.shared.b16 {%0,%1,%2,%3}, [%4];"
        : "=r"(r[0]), "=r"(r[1]), "=r"(r[2]), "=r"(r[3]) : "r"(saddr));
}
__device__ __forceinline__ uint32_t smem_u32(const void* p) {
    return (uint32_t)__cvta_generic_to_shared(p);
}

// ---------------- fp32 -> bf16 hi/lo split (x) -------------------------------
__global__ void split_kernel(const float* __restrict__ in,
                             __nv_bfloat16* __restrict__ hi,
                             __nv_bfloat16* __restrict__ lo, int n4)
{
    int idx = blockIdx.x * blockDim.x + threadIdx.x;
    if (idx >= n4) return;
    float4 v = ((const float4*)in)[idx];
    __nv_bfloat16 h0 = __float2bfloat16(v.x);
    __nv_bfloat16 h1 = __float2bfloat16(v.y);
    __nv_bfloat16 h2 = __float2bfloat16(v.z);
    __nv_bfloat16 h3 = __float2bfloat16(v.w);
    __nv_bfloat16 l0 = __float2bfloat16(v.x - __bfloat162float(h0));
    __nv_bfloat16 l1 = __float2bfloat16(v.y - __bfloat162float(h1));
    __nv_bfloat16 l2 = __float2bfloat16(v.z - __bfloat162float(h2));
    __nv_bfloat16 l3 = __float2bfloat16(v.w - __bfloat162float(h3));
    ((__nv_bfloat162*)hi)[idx*2+0] = __nv_bfloat162(h0, h1);
    ((__nv_bfloat162*)hi)[idx*2+1] = __nv_bfloat162(h2, h3);
    ((__nv_bfloat162*)lo)[idx*2+0] = __nv_bfloat162(l0, l1);
    ((__nv_bfloat162*)lo)[idx*2+1] = __nv_bfloat162(l2, l3);
}

// ---------------- fused 4-weight split (grid.y selects weight) ---------------
__global__ void split4_kernel(const float* __restrict__ w0,
                              const float* __restrict__ w1,
                              const float* __restrict__ w2,
                              const float* __restrict__ w3,
                              __nv_bfloat16* __restrict__ hib,
                              __nv_bfloat16* __restrict__ lob, int n4)
{
    int idx = blockIdx.x * blockDim.x + threadIdx.x;
    if (idx >= n4) return;
    int wsel = blockIdx.y;
    const float* in = (wsel == 0) ? w0 : (wsel == 1) ? w1 : (wsel == 2) ? w2 : w3;
    __nv_bfloat16* hi = hib + (size_t)wsel * DIM * DIM;
    __nv_bfloat16* lo = lob + (size_t)wsel * DIM * DIM;
    float4 v = ((const float4*)in)[idx];
    __nv_bfloat16 h0 = __float2bfloat16(v.x);
    __nv_bfloat16 h1 = __float2bfloat16(v.y);
    __nv_bfloat16 h2 = __float2bfloat16(v.z);
    __nv_bfloat16 h3 = __float2bfloat16(v.w);
    __nv_bfloat16 l0 = __float2bfloat16(v.x - __bfloat162float(h0));
    __nv_bfloat16 l1 = __float2bfloat16(v.y - __bfloat162float(h1));
    __nv_bfloat16 l2 = __float2bfloat16(v.z - __bfloat162float(h2));
    __nv_bfloat16 l3 = __float2bfloat16(v.w - __bfloat162float(h3));
    ((__nv_bfloat162*)hi)[idx*2+0] = __nv_bfloat162(h0, h1);
    ((__nv_bfloat162*)hi)[idx*2+1] = __nv_bfloat162(h2, h3);
    ((__nv_bfloat162*)lo)[idx*2+0] = __nv_bfloat162(l0, l1);
    ((__nv_bfloat162*)lo)[idx*2+1] = __nv_bfloat162(l2, l3);
}

// ============================================================================
// bf16x3 GEMM: ldmatrix + XOR-swizzled smem, 3-stage cp.async, 1 sync/iter,
// 2 CTAs/SM.  C = (Ahi+Alo) (Bhi+Blo)^T
// ============================================================================
#define BM 128
#define BN 128
#define BK 32
#define NSTG 3
#define TILE_B (BM*BK*2)            // 8192 bytes per tile per stage
#define GEMM_SMEM_BYTES (4*NSTG*TILE_B)   // 98304

// swizzled byte offset for (row, 16B-chunk) within a tile; chunk in 0..3
__device__ __forceinline__ uint32_t swz(int row, int chunk) {
    return (uint32_t)(row * 64 + ((chunk ^ ((row >> 1) & 3)) << 4));
}

struct GemmCore {
    uint32_t uAh, uAl, uBh, uBl;
    int t, lane, wid, gid, tig, wm, wn, m0, n0;
    int arow, achk, brow, bchk;
    int lr0, lc0, lr1;
    uint32_t so0, so1;
    float acc[4][4][4];

    __device__ __forceinline__ void init(char* smc, int bx, int by, int tid) {
        uAh = smem_u32(smc);
        uAl = uAh + NSTG * TILE_B;
        uBh = uAh + 2 * NSTG * TILE_B;
        uBl = uAh + 3 * NSTG * TILE_B;
        t = tid; lane = t & 31; wid = t >> 5;
        gid = lane >> 2; tig = lane & 3;
        wm = (wid & 1) * 64; wn = (wid >> 1) * 32;
        m0 = by * BM; n0 = bx * BN;
        arow = lane & 15; achk = lane >> 4;
        brow = ((lane >> 4) << 3) + (lane & 7);
        bchk = (lane >> 3) & 1;
        lr0 = t >> 2; lc0 = (t & 3) * 8; lr1 = lr0 + 64;
        so0 = swz(lr0, t & 3);
        so1 = swz(lr1, t & 3);
#pragma unroll
        for (int i = 0; i < 4; i++)
#pragma unroll
            for (int j = 0; j < 4; j++)
#pragma unroll
                for (int e = 0; e < 4; e++) acc[i][j][e] = 0.f;
    }

    __device__ __forceinline__ void load_stage(
        int stg, int k0,
        const __nv_bfloat16* Ahi, const __nv_bfloat16* Alo,
        const __nv_bfloat16* Bhi, const __nv_bfloat16* Blo, int K)
    {
        const uint32_t sb = stg * TILE_B;
        size_t ga0 = (size_t)(m0 + lr0) * K + k0 + lc0;
        size_t ga1 = (size_t)(m0 + lr1) * K + k0 + lc0;
        size_t gb0 = (size_t)(n0 + lr0) * K + k0 + lc0;
        size_t gb1 = (size_t)(n0 + lr1) * K + k0 + lc0;
        cp_async16_s(uAh + sb + so0, Ahi + ga0);  cp_async16_s(uAh + sb + so1, Ahi + ga1);
        cp_async16_s(uAl + sb + so0, Alo + ga0);  cp_async16_s(uAl + sb + so1, Alo + ga1);
        cp_async16_s(uBh + sb + so0, Bhi + gb0);  cp_async16_s(uBh + sb + so1, Bhi + gb1);
        cp_async16_s(uBl + sb + so0, Blo + gb0);  cp_async16_s(uBl + sb + so1, Blo + gb1);
        CP_COMMIT();
    }

    __device__ __forceinline__ void consume_stage(int stg) {
        const uint32_t stb = stg * TILE_B;
#pragma unroll
        for (int kk = 0; kk < 2; kk++) {
            uint32_t ah[4][4], al[4][4], bh[4][2], bl[4][2];
#pragma unroll
            for (int ms = 0; ms < 4; ms++) {
                int row = wm + ms * 16 + arow;
                uint32_t off = stb + swz(row, 2 * kk + achk);
                ldsm_x4(ah[ms], uAh + off);
                ldsm_x4(al[ms], uAl + off);
            }
#pragma unroll
            for (int nsp = 0; nsp < 2; nsp++) {
                int row = wn + nsp * 16 + brow;
                uint32_t off = stb + swz(row, 2 * kk + bchk);
                uint32_t r[4];
                ldsm_x4(r, uBh + off);
                bh[2*nsp][0] = r[0]; bh[2*nsp][1] = r[1];
                bh[2*nsp+1][0] = r[2]; bh[2*nsp+1][1] = r[3];
                ldsm_x4(r, uBl + off);
                bl[2*nsp][0] = r[0]; bl[2*nsp][1] = r[1];
                bl[2*nsp+1][0] = r[2]; bl[2*nsp+1][1] = r[3];
            }
#pragma unroll
            for (int ms = 0; ms < 4; ms++)
#pragma unroll
                for (int ns = 0; ns < 4; ns++) {
                    mma_bf16(acc[ms][ns], ah[ms], bh[ns]);
                    mma_bf16(acc[ms][ns], al[ms], bh[ns]);
                    mma_bf16(acc[ms][ns], ah[ms], bl[ns]);
                }
        }
    }

    __device__ __forceinline__ void mainloop(
        const __nv_bfloat16* Ahi, const __nv_bfloat16* Alo,
        const __nv_bfloat16* Bhi, const __nv_bfloat16* Blo, int K)
    {
        const int NK = K / BK;
        load_stage(0, 0, Ahi, Alo, Bhi, Blo, K);
        load_stage(1, BK, Ahi, Alo, Bhi, Blo, K);
        int s2 = 2;
        for (int kt = 0; kt < NK; kt++) {
            if (kt + 1 < NK) { CP_WAIT1(); } else { CP_WAIT0(); }
            __syncthreads();
            if (kt + 2 < NK) {
                load_stage(s2, (kt + 2) * BK, Ahi, Alo, Bhi, Blo, K);
            }
            int sc = s2 + 1; if (sc >= NSTG) sc -= NSTG;
            consume_stage(sc);
            s2 = sc;
        }
    }
};

__device__ __forceinline__ void split_store2(
    __nv_bfloat16* hi, __nv_bfloat16* lo, size_t idx2, float x, float y)
{
    __nv_bfloat16 hx = __float2bfloat16(x);
    __nv_bfloat16 hy = __float2bfloat16(y);
    ((__nv_bfloat162*)hi)[idx2] = __nv_bfloat162(hx, hy);
    ((__nv_bfloat162*)lo)[idx2] = __nv_bfloat162(
        __float2bfloat16(x - __bfloat162float(hx)),
        __float2bfloat16(y - __bfloat162float(hy)));
}

// proj 0=Q(rope), 1=K(rope), 2=V^T (A/B swapped, scatter to [b,h,d,s])
__global__ void __launch_bounds__(256, 2) gemm_qkv(
    const __nv_bfloat16* __restrict__ xhi, const __nv_bfloat16* __restrict__ xlo,
    const __nv_bfloat16* __restrict__ whi, const __nv_bfloat16* __restrict__ wlo,
    __nv_bfloat16* __restrict__ qhi, __nv_bfloat16* __restrict__ qlo,
    __nv_bfloat16* __restrict__ khi, __nv_bfloat16* __restrict__ klo,
    __nv_bfloat16* __restrict__ vthi, __nv_bfloat16* __restrict__ vtlo,
    const float* __restrict__ fc, const float* __restrict__ fs)
{
    extern __shared__ char smc[];
    const int proj = blockIdx.z;
    GemmCore g;
    const __nv_bfloat16* Whi = whi + (size_t)proj * DIM * DIM;
    const __nv_bfloat16* Wlo = wlo + (size_t)proj * DIM * DIM;

    if (proj == 2) {
        // C[e][s] = sum_k Wv[e,k] x[s,k]  (A=Wv rows e:DIM, B=x rows s:ROWS)
        g.init(smc, blockIdx.y, blockIdx.x, threadIdx.x);   // m over DIM, n over ROWS
        g.mainloop(Whi, Wlo, xhi, xlo, DIM);
#pragma unroll
        for (int ms = 0; ms < 4; ms++)
#pragma unroll
            for (int ns = 0; ns < 4; ns++) {
                int e0 = g.m0 + g.wm + ms * 16 + g.gid;
                int sg = g.n0 + g.wn + ns * 8 + g.tig * 2;
                int b  = sg >> 11;
                int sl = sg & (SEQ - 1);
#pragma unroll
                for (int half = 0; half < 2; half++) {
                    int e = e0 + half * 8;
                    size_t off = (size_t)b * DIM * SEQ + (size_t)e * SEQ + sl;
                    split_store2(vthi, vtlo, off >> 1,
                                 g.acc[ms][ns][half * 2], g.acc[ms][ns][half * 2 + 1]);
                }
            }
        return;
    }

    g.init(smc, blockIdx.x, blockIdx.y, threadIdx.x);
    g.mainloop(xhi, xlo, Whi, Wlo, DIM);
    const int N = DIM;
    __nv_bfloat16* Chi = proj ? khi : qhi;
    __nv_bfloat16* Clo = proj ? klo : qlo;
#pragma unroll
    for (int ms = 0; ms < 4; ms++)
#pragma unroll
        for (int ns = 0; ns < 4; ns++) {
            int row0 = g.m0 + g.wm + ms * 16 + g.gid;
            int col  = g.n0 + g.wn + ns * 8 + g.tig * 2;
            int i = (col & 127) >> 1;
#pragma unroll
            for (int half = 0; half < 2; half++) {
                int row = row0 + half * 8;
                int s   = row & (SEQ - 1);
                float cs = __ldg(fc + s * 64 + i);
                float sn = __ldg(fs + s * 64 + i);
                float re = g.acc[ms][ns][half * 2];
                float im = g.acc[ms][ns][half * 2 + 1];
                float rx = re * cs - im * sn;
                float ry = re * sn + im * cs;
                split_store2(Chi, Clo, ((size_t)row * N + col) >> 1, rx, ry);
            }
        }
}

__global__ void __launch_bounds__(256, 2) gemm_out(
    const __nv_bfloat16* __restrict__ Ahi, const __nv_bfloat16* __restrict__ Alo,
    const __nv_bfloat16* __restrict__ Bhi, const __nv_bfloat16* __restrict__ Blo,
    float* __restrict__ C)
{
    extern __shared__ char smc[];
    GemmCore g;
    g.init(smc, blockIdx.x, blockIdx.y, threadIdx.x);
    g.mainloop(Ahi, Alo, Bhi, Blo, DIM);
    const int N = DIM;
#pragma unroll
    for (int ms = 0; ms < 4; ms++)
#pragma unroll
        for (int ns = 0; ns < 4; ns++) {
            int row = g.m0 + g.wm + ms * 16 + g.gid;
            int col = g.n0 + g.wn + ns * 8 + g.tig * 2;
            float2 c0 = {g.acc[ms][ns][0], g.acc[ms][ns][1]};
            float2 c1 = {g.acc[ms][ns][2], g.acc[ms][ns][3]};
            *(float2*)&C[(size_t)row * N + col]       = c0;
            *(float2*)&C[(size_t)(row + 8) * N + col] = c1;
        }
}

// ============================================================================
// tensor-core flash attention, bf16x3, causal (unchanged from R8)
// ============================================================================
#define AQ  128
#define AK  64
#define AHS 136
#define AVS 72
#define A_QH        0
#define A_QL        17408
#define A_KH(bf)    (34816 + (bf)*8704)
#define A_KL(bf)    (52224 + (bf)*8704)
#define A_VH(bf)    (69632 + (bf)*9216)
#define A_VL(bf)    (88064 + (bf)*9216)
#define ATTN_SMEM_BYTES (106496*2)

__global__ void __launch_bounds__(256) attn_tc_kernel(
    const __nv_bfloat16* __restrict__ qhi, const __nv_bfloat16* __restrict__ qlo,
    const __nv_bfloat16* __restrict__ khi, const __nv_bfloat16* __restrict__ klo,
    const __nv_bfloat16* __restrict__ vthi, const __nv_bfloat16* __restrict__ vtlo,
    __nv_bfloat16* __restrict__ ohi, __nv_bfloat16* __restrict__ olo)
{
    extern __shared__ __nv_bfloat16 smh[];
    const uint32_t ubase = smem_u32(smh);

    const int t    = threadIdx.x;
    const int lane = t & 31;
    const int wid  = t >> 5;
    const int gid  = lane >> 2;
    const int tig  = lane & 3;
    const int qt = blockIdx.x, h = blockIdx.y, b = blockIdx.z;

    const int arow = (lane & 15);
    const int acol = (lane >> 4) << 3;
    const int brow = ((lane >> 4) << 3) + (lane & 7);
    const int bcol = ((lane >> 3) & 1) << 3;

    {
        int row = t >> 1;
        int cb  = (t & 1) * 8;
        size_t g = (size_t)(b * SEQ + qt * AQ + row) * DIM + h * HD + cb * 8;
        int so = row * AHS + cb * 8;
#pragma unroll
        for (int c = 0; c < 8; c++) {
            cp_async16(smh + A_QH + so + c * 8, qhi + g + c * 8);
            cp_async16(smh + A_QL + so + c * 8, qlo + g + c * 8);
        }
    }

#define LOAD_KV(BUFI, KT)                                                       \
    {                                                                           \
        int row = t >> 2;                                                       \
        int cb  = (t & 3) * 4;                                                  \
        size_t g = (size_t)(b * SEQ + (KT) * AK + row) * DIM + h * HD + cb * 8; \
        int so = row * AHS + cb * 8;                                            \
        _Pragma("unroll")                                                       \
        for (int c = 0; c < 4; c++) {                                           \
            cp_async16(smh + A_KH(BUFI) + so + c * 8, khi + g + c * 8);         \
            cp_async16(smh + A_KL(BUFI) + so + c * 8, klo + g + c * 8);         \
        }                                                                       \
        int vrow = t >> 1;                                                      \
        int vcb  = (t & 1) * 4;                                                 \
        size_t gv = (size_t)((b * NH + h) * HD + vrow) * SEQ + (KT) * AK + vcb * 8; \
        int sv = vrow * AVS + vcb * 8;                                          \
        _Pragma("unroll")                                                       \
        for (int c = 0; c < 4; c++) {                                           \
            cp_async16(smh + A_VH(BUFI) + sv + c * 8, vthi + gv + c * 8);       \
            cp_async16(smh + A_VL(BUFI) + sv + c * 8, vtlo + gv + c * 8);       \
        }                                                                       \
    }

    LOAD_KV(0, 0);
    CP_COMMIT();

    float sacc[8][4];
    float oacc[16][4];
#pragma unroll
    for (int i = 0; i < 16; i++)
#pragma unroll
        for (int e = 0; e < 4; e++) oacc[i][e] = 0.f;
    float m0 = -1e30f, m1 = -1e30f, l0 = 0.f, l1 = 0.f;

    const float scale = 0.08838834764831845f;
    const int gr0 = qt * AQ + wid * 16 + gid;
    const int ktmax = 2 * qt + 1;
    int buf = 0;

    for (int kt = 0; kt <= ktmax; kt++) {
        if (kt < ktmax) {
            LOAD_KV(buf ^ 1, kt + 1);
            CP_COMMIT();
            CP_WAIT1();
        } else {
            CP_WAIT0();
        }
        __syncthreads();

#pragma unroll
        for (int ns = 0; ns < 8; ns++)
#pragma unroll
            for (int e = 0; e < 4; e++) sacc[ns][e] = 0.f;

        const uint32_t ukh = ubase + A_KH(buf) * 2;
        const uint32_t ukl = ubase + A_KL(buf) * 2;
#pragma unroll
        for (int kk = 0; kk < 8; kk++) {
            uint32_t aoff = ((wid * 16 + arow) * AHS + kk * 16 + acol) * 2;
            uint32_t ah[4], al[4];
            ldsm_x4(ah, ubase + A_QH * 2 + aoff);
            ldsm_x4(al, ubase + A_QL * 2 + aoff);
#pragma unroll
            for (int nsp = 0; nsp < 4; nsp++) {
                uint32_t boff = ((nsp * 16 + brow) * AHS + kk * 16 + bcol) * 2;
                uint32_t rh[4], rl[4];
                ldsm_x4(rh, ukh + boff);
                ldsm_x4(rl, ukl + boff);
                uint32_t b0h[2] = {rh[0], rh[1]}, b1h[2] = {rh[2], rh[3]};
                uint32_t b0l[2] = {rl[0], rl[1]}, b1l[2] = {rl[2], rl[3]};
                mma_bf16(sacc[2*nsp],   ah, b0h);
                mma_bf16(sacc[2*nsp],   al, b0h);
                mma_bf16(sacc[2*nsp],   ah, b0l);
                mma_bf16(sacc[2*nsp+1], ah, b1h);
                mma_bf16(sacc[2*nsp+1], al, b1h);
                mma_bf16(sacc[2*nsp+1], ah, b1l);
            }
        }

        if (kt * AK + 63 > qt * AQ + wid * 16) {
            int rl0 = gr0 - kt * AK;
            int rl1 = rl0 + 8;
#pragma unroll
            for (int ns = 0; ns < 8; ns++) {
#pragma unroll
                for (int e = 0; e < 4; e++) {
                    float v = sacc[ns][e] * scale;
                    int cl = ns * 8 + 2 * tig + (e & 1);
                    int rl = (e < 2) ? rl0 : rl1;
                    sacc[ns][e] = (cl > rl) ? -1e30f : v;
                }
            }
        } else {
#pragma unroll
            for (int ns = 0; ns < 8; ns++)
#pragma unroll
                for (int e = 0; e < 4; e++) sacc[ns][e] *= scale;
        }

        float mx0 = -1e30f, mx1 = -1e30f;
#pragma unroll
        for (int ns = 0; ns < 8; ns++) {
            mx0 = fmaxf(mx0, fmaxf(sacc[ns][0], sacc[ns][1]));
            mx1 = fmaxf(mx1, fmaxf(sacc[ns][2], sacc[ns][3]));
        }
        mx0 = fmaxf(mx0, __shfl_xor_sync(0xffffffffu, mx0, 1));
        mx0 = fmaxf(mx0, __shfl_xor_sync(0xffffffffu, mx0, 2));
        mx1 = fmaxf(mx1, __shfl_xor_sync(0xffffffffu, mx1, 1));
        mx1 = fmaxf(mx1, __shfl_xor_sync(0xffffffffu, mx1, 2));
        float mn0 = fmaxf(m0, mx0), mn1 = fmaxf(m1, mx1);
        float a0 = __expf(m0 - mn0), a1 = __expf(m1 - mn1);
        m0 = mn0; m1 = mn1;

        float sum0 = 0.f, sum1 = 0.f;
#pragma unroll
        for (int ns = 0; ns < 8; ns++) {
            float p0 = __expf(sacc[ns][0] - mn0);
            float p1 = __expf(sacc[ns][1] - mn0);
            float p2 = __expf(sacc[ns][2] - mn1);
            float p3 = __expf(sacc[ns][3] - mn1);
            sacc[ns][0] = p0; sacc[ns][1] = p1;
            sacc[ns][2] = p2; sacc[ns][3] = p3;
            sum0 += p0 + p1; sum1 += p2 + p3;
        }
        sum0 += __shfl_xor_sync(0xffffffffu, sum0, 1);
        sum0 += __shfl_xor_sync(0xffffffffu, sum0, 2);
        sum1 += __shfl_xor_sync(0xffffffffu, sum1, 1);
        sum1 += __shfl_xor_sync(0xffffffffu, sum1, 2);
        l0 = l0 * a0 + sum0;
        l1 = l1 * a1 + sum1;

#pragma unroll
        for (int nd = 0; nd < 16; nd++) {
            oacc[nd][0] *= a0; oacc[nd][1] *= a0;
            oacc[nd][2] *= a1; oacc[nd][3] *= a1;
        }

        const uint32_t uvh = ubase + A_VH(buf) * 2;
        const uint32_t uvl = ubase + A_VL(buf) * 2;
#pragma unroll
        for (int kc = 0; kc < 4; kc++) {
            uint32_t ph[4], pl[4];
#pragma unroll
            for (int j = 0; j < 4; j++) {
                int ns = 2 * kc + (j >> 1);
                int e0 = (j & 1) * 2;
                float c0 = sacc[ns][e0], c1 = sacc[ns][e0 + 1];
                __nv_bfloat162 hb = __floats2bfloat162_rn(c0, c1);
                uint32_t hu = *(uint32_t*)&hb;
                float f0 = __uint_as_float(hu << 16);
                float f1 = __uint_as_float(hu & 0xffff0000u);
                __nv_bfloat162 lb = __floats2bfloat162_rn(c0 - f0, c1 - f1);
                ph[j] = hu;
                pl[j] = *(uint32_t*)&lb;
            }
#pragma unroll
            for (int ndp = 0; ndp < 8; ndp++) {
                uint32_t boff = ((ndp * 16 + brow) * AVS + kc * 16 + bcol) * 2;
                uint32_t rh[4], rl[4];
                ldsm_x4(rh, uvh + boff);
                ldsm_x4(rl, uvl + boff);
                uint32_t b0h[2] = {rh[0], rh[1]}, b1h[2] = {rh[2], rh[3]};
                uint32_t b0l[2] = {rl[0], rl[1]}, b1l[2] = {rl[2], rl[3]};
                mma_bf16(oacc[2*ndp],   ph, b0h);
                mma_bf16(oacc[2*ndp],   pl, b0h);
                mma_bf16(oacc[2*ndp],   ph, b0l);
                mma_bf16(oacc[2*ndp+1], ph, b1h);
                mma_bf16(oacc[2*ndp+1], pl, b1h);
                mma_bf16(oacc[2*ndp+1], ph, b1l);
            }
        }
        __syncthreads();
        buf ^= 1;
    }

    // ---- normalize + split-store ----
    float i0 = 1.f / l0, i1 = 1.f / l1;
    size_t r0 = (size_t)(b * SEQ + gr0) * DIM + h * HD;
    size_t r1 = r0 + 8 * DIM;
#pragma unroll
    for (int nd = 0; nd < 16; nd++) {
        int col = nd * 8 + 2 * tig;
        split_store2(ohi, olo, (r0 + col) >> 1, oacc[nd][0] * i0, oacc[nd][1] * i0);
        split_store2(ohi, olo, (r1 + col) >> 1, oacc[nd][2] * i1, oacc[nd][3] * i1);
    }
}

// ---------------- launcher ---------------------------------------------------
extern "C" void kernel_launch(void* const* d_in, const int* in_sizes, int n_in,
                              void* d_out, int out_size)
{
    const float* x    = (const float*)d_in[0];
    const float* w[4] = {(const float*)d_in[1], (const float*)d_in[2],
                         (const float*)d_in[3], (const float*)d_in[4]};
    const float* fcos = (const float*)d_in[5];
    const float* fsin = (const float*)d_in[6];
    float* out = (float*)d_out;

    __nv_bfloat16 *xhi, *xlo, *ohi, *olo, *whi, *wlo;
    __nv_bfloat16 *qhi, *qlo, *khi, *klo, *vthi, *vtlo;
    cudaGetSymbolAddress((void**)&xhi, g_xhi);
    cudaGetSymbolAddress((void**)&xlo, g_xlo);
    cudaGetSymbolAddress((void**)&ohi, g_ohi);
    cudaGetSymbolAddress((void**)&olo, g_olo);
    cudaGetSymbolAddress((void**)&whi, g_whi);
    cudaGetSymbolAddress((void**)&wlo, g_wlo);
    cudaGetSymbolAddress((void**)&qhi, g_qhi);
    cudaGetSymbolAddress((void**)&qlo, g_qlo);
    cudaGetSymbolAddress((void**)&khi, g_khi);
    cudaGetSymbolAddress((void**)&klo, g_klo);
    cudaGetSymbolAddress((void**)&vthi, g_vthi);
    cudaGetSymbolAddress((void**)&vtlo, g_vtlo);

    cudaFuncSetAttribute(gemm_qkv,
                         cudaFuncAttributeMaxDynamicSharedMemorySize, GEMM_SMEM_BYTES);
    cudaFuncSetAttribute(gemm_out,
                         cudaFuncAttributeMaxDynamicSharedMemorySize, GEMM_SMEM_BYTES);
    cudaFuncSetAttribute(attn_tc_kernel,
                         cudaFuncAttributeMaxDynamicSharedMemorySize, ATTN_SMEM_BYTES);

    int nx4 = ROWS * DIM / 4;
    int nw4 = DIM * DIM / 4;
    split_kernel<<<nx4 / 256, 256>>>(x, xhi, xlo, nx4);
    split4_kernel<<<dim3(nw4 / 256, 4), 256>>>(w[0], w[1], w[2], w[3], whi, wlo, nw4);

    dim3 gqkv(DIM / BN, ROWS / BM, 3);   // (16, 32, 3)
    gemm_qkv<<<gqkv, 256, GEMM_SMEM_BYTES>>>(
        xhi, xlo, whi, wlo, qhi, qlo, khi, klo, vthi, vtlo, fcos, fsin);

    attn_tc_kernel<<<dim3(SEQ / AQ, NH, BATCH), 256, ATTN_SMEM_BYTES>>>(
        qhi, qlo, khi, klo, vthi, vtlo, ohi, olo);

    gemm_out<<<dim3(DIM / BN, ROWS / BM), 256, GEMM_SMEM_BYTES>>>(
        ohi, olo, whi + 3*(size_t)DIM*DIM, wlo + 3*(size_t)DIM*DIM, out);
}

// round 14
// speedup vs baseline: 3.1519x; 1.0191x over previous
#include <cuda_runtime.h>
#include <cuda_bf16.h>
#include <cstdint>

#define BATCH 2
#define SEQ   2048
#define DIM   2048
#define NH    16
#define HD    128
#define ROWS  (BATCH*SEQ)   // 4096

// ---------------- scratch (static device globals; no allocs allowed) --------
__device__ __nv_bfloat16 g_xhi[ROWS*DIM];
__device__ __nv_bfloat16 g_xlo[ROWS*DIM];
__device__ __nv_bfloat16 g_ohi[ROWS*DIM];
__device__ __nv_bfloat16 g_olo[ROWS*DIM];
__device__ __nv_bfloat16 g_whi[4][DIM*DIM];   // q,k,v,o
__device__ __nv_bfloat16 g_wlo[4][DIM*DIM];

__device__ __nv_bfloat16 g_qhi[ROWS*DIM];
__device__ __nv_bfloat16 g_qlo[ROWS*DIM];
__device__ __nv_bfloat16 g_khi[ROWS*DIM];
__device__ __nv_bfloat16 g_klo[ROWS*DIM];
__device__ __nv_bfloat16 g_vthi[ROWS*DIM];    // per-head transposed [b,h,d,s]
__device__ __nv_bfloat16 g_vtlo[ROWS*DIM];

// ============================================================================
// helpers
// ============================================================================
__device__ __forceinline__ void cp_async16(void* smem, const void* gmem) {
    uint32_t s = (uint32_t)__cvta_generic_to_shared(smem);
    asm volatile("cp.async.cg.shared.global [%0], [%1], 16;\n" :: "r"(s), "l"(gmem));
}
__device__ __forceinline__ void cp_async16_s(uint32_t saddr, const void* gmem) {
    asm volatile("cp.async.cg.shared.global [%0], [%1], 16;\n" :: "r"(saddr), "l"(gmem));
}
#define CP_COMMIT() asm volatile("cp.async.commit_group;\n" ::: "memory")
#define CP_WAIT1()  asm volatile("cp.async.wait_group 1;\n" ::: "memory")
#define CP_WAIT0()  asm volatile("cp.async.wait_group 0;\n" ::: "memory")

__device__ __forceinline__ void mma_bf16(float* c, const uint32_t* a, const uint32_t* b) {
    asm volatile(
        "mma.sync.aligned.m16n8k16.row.col.f32.bf16.bf16.f32 "
        "{%0,%1,%2,%3}, {%4,%5,%6,%7}, {%8,%9}, {%0,%1,%2,%3};\n"
        : "+f"(c[0]), "+f"(c[1]), "+f"(c[2]), "+f"(c[3])
        : "r"(a[0]), "r"(a[1]), "r"(a[2]), "r"(a[3]),
          "r"(b[0]), "r"(b[1]));
}
__device__ __forceinline__ void ldsm_x4(uint32_t* r, uint32_t saddr) {
    asm volatile("ldmatrix.sync.aligned.m8n8.x4.shared.b16 {%0,%1,%2,%3}, [%4];"
        : "=r"(r[0]), "=r"(r[1]), "=r"(r[2]), "=r"(r[3]) : "r"(saddr));
}
__device__ __forceinline__ uint32_t smem_u32(const void* p) {
    return (uint32_t)__cvta_generic_to_shared(p);
}

// ---- mbarrier (sm_90-era PTX; valid on this sm_100 target) -----------------
#define MBAR_INIT(addr, cnt) \
    asm volatile("mbarrier.init.shared.b64 [%0], %1;" :: "r"(addr), "r"(cnt) : "memory")
#define MBAR_ARRIVE(addr) \
    asm volatile("{\n\t.reg .b64 st;\n\tmbarrier.arrive.shared.b64 st, [%0];\n\t}" \
                 :: "r"(addr) : "memory")
// .noinc: the async arrive counts against the initialized expected count.
// (Default form self-balances: +1 expect then -1 arrive => phase never
// completes on its own. That was the R12 deadlock.)
#define CP_ASYNC_MBAR_ARRIVE(addr) \
    asm volatile("cp.async.mbarrier.arrive.noinc.shared.b64 [%0];" :: "r"(addr) : "memory")
// Bounded spin: legit waits need O(1e3) polls; 16M polls (~0.4s) means a
// protocol bug produces a FAST wrong-answer failure instead of a container-
// killing 120s hang. Never triggers when the protocol is correct.
#define MBAR_WAIT(addr, parity) do {                                            \
    uint32_t _done = 0; uint32_t _spin = 0;                                     \
    while (!_done && _spin < (1u << 24)) {                                      \
        asm volatile(                                                           \
            "{\n\t.reg .pred p;\n\t"                                            \
            "mbarrier.try_wait.parity.shared.b64 p, [%1], %2;\n\t"              \
            "selp.b32 %0, 1, 0, p;\n\t}"                                        \
            : "=r"(_done) : "r"(addr), "r"(parity) : "memory");                 \
        _spin++;                                                                \
    }                                                                           \
} while (0)

// ---------------- fp32 -> bf16 hi/lo split (x) -------------------------------
__global__ void split_kernel(const float* __restrict__ in,
                             __nv_bfloat16* __restrict__ hi,
                             __nv_bfloat16* __restrict__ lo, int n4)
{
    int idx = blockIdx.x * blockDim.x + threadIdx.x;
    if (idx >= n4) return;
    float4 v = ((const float4*)in)[idx];
    __nv_bfloat16 h0 = __float2bfloat16(v.x);
    __nv_bfloat16 h1 = __float2bfloat16(v.y);
    __nv_bfloat16 h2 = __float2bfloat16(v.z);
    __nv_bfloat16 h3 = __float2bfloat16(v.w);
    __nv_bfloat16 l0 = __float2bfloat16(v.x - __bfloat162float(h0));
    __nv_bfloat16 l1 = __float2bfloat16(v.y - __bfloat162float(h1));
    __nv_bfloat16 l2 = __float2bfloat16(v.z - __bfloat162float(h2));
    __nv_bfloat16 l3 = __float2bfloat16(v.w - __bfloat162float(h3));
    ((__nv_bfloat162*)hi)[idx*2+0] = __nv_bfloat162(h0, h1);
    ((__nv_bfloat162*)hi)[idx*2+1] = __nv_bfloat162(h2, h3);
    ((__nv_bfloat162*)lo)[idx*2+0] = __nv_bfloat162(l0, l1);
    ((__nv_bfloat162*)lo)[idx*2+1] = __nv_bfloat162(l2, l3);
}

// ---------------- fused 4-weight split (grid.y selects weight) ---------------
__global__ void split4_kernel(const float* __restrict__ w0,
                              const float* __restrict__ w1,
                              const float* __restrict__ w2,
                              const float* __restrict__ w3,
                              __nv_bfloat16* __restrict__ hib,
                              __nv_bfloat16* __restrict__ lob, int n4)
{
    int idx = blockIdx.x * blockDim.x + threadIdx.x;
    if (idx >= n4) return;
    int wsel = blockIdx.y;
    const float* in = (wsel == 0) ? w0 : (wsel == 1) ? w1 : (wsel == 2) ? w2 : w3;
    __nv_bfloat16* hi = hib + (size_t)wsel * DIM * DIM;
    __nv_bfloat16* lo = lob + (size_t)wsel * DIM * DIM;
    float4 v = ((const float4*)in)[idx];
    __nv_bfloat16 h0 = __float2bfloat16(v.x);
    __nv_bfloat16 h1 = __float2bfloat16(v.y);
    __nv_bfloat16 h2 = __float2bfloat16(v.z);
    __nv_bfloat16 h3 = __float2bfloat16(v.w);
    __nv_bfloat16 l0 = __float2bfloat16(v.x - __bfloat162float(h0));
    __nv_bfloat16 l1 = __float2bfloat16(v.y - __bfloat162float(h1));
    __nv_bfloat16 l2 = __float2bfloat16(v.z - __bfloat162float(h2));
    __nv_bfloat16 l3 = __float2bfloat16(v.w - __bfloat162float(h3));
    ((__nv_bfloat162*)hi)[idx*2+0] = __nv_bfloat162(h0, h1);
    ((__nv_bfloat162*)hi)[idx*2+1] = __nv_bfloat162(h2, h3);
    ((__nv_bfloat162*)lo)[idx*2+0] = __nv_bfloat162(l0, l1);
    ((__nv_bfloat162*)lo)[idx*2+1] = __nv_bfloat162(l2, l3);
}

// ============================================================================
// bf16x3 GEMM: ldmatrix + XOR-swizzled smem, 3-stage cp.async, 1 sync/iter,
// 2 CTAs/SM.  C = (Ahi+Alo) (Bhi+Blo)^T
// ============================================================================
#define BM 128
#define BN 128
#define BK 32
#define NSTG 3
#define TILE_B (BM*BK*2)            // 8192 bytes per tile per stage
#define GEMM_SMEM_BYTES (4*NSTG*TILE_B)   // 98304

__device__ __forceinline__ uint32_t swz(int row, int chunk) {
    return (uint32_t)(row * 64 + ((chunk ^ ((row >> 1) & 3)) << 4));
}

struct GemmCore {
    uint32_t uAh, uAl, uBh, uBl;
    int t, lane, wid, gid, tig, wm, wn, m0, n0;
    int arow, achk, brow, bchk;
    int lr0, lc0, lr1;
    uint32_t so0, so1;
    float acc[4][4][4];

    __device__ __forceinline__ void init(char* smc, int bx, int by, int tid) {
        uAh = smem_u32(smc);
        uAl = uAh + NSTG * TILE_B;
        uBh = uAh + 2 * NSTG * TILE_B;
        uBl = uAh + 3 * NSTG * TILE_B;
        t = tid; lane = t & 31; wid = t >> 5;
        gid = lane >> 2; tig = lane & 3;
        wm = (wid & 1) * 64; wn = (wid >> 1) * 32;
        m0 = by * BM; n0 = bx * BN;
        arow = lane & 15; achk = lane >> 4;
        brow = ((lane >> 4) << 3) + (lane & 7);
        bchk = (lane >> 3) & 1;
        lr0 = t >> 2; lc0 = (t & 3) * 8; lr1 = lr0 + 64;
        so0 = swz(lr0, t & 3);
        so1 = swz(lr1, t & 3);
#pragma unroll
        for (int i = 0; i < 4; i++)
#pragma unroll
            for (int j = 0; j < 4; j++)
#pragma unroll
                for (int e = 0; e < 4; e++) acc[i][j][e] = 0.f;
    }

    __device__ __forceinline__ void load_stage(
        int stg, int k0,
        const __nv_bfloat16* Ahi, const __nv_bfloat16* Alo,
        const __nv_bfloat16* Bhi, const __nv_bfloat16* Blo, int K)
    {
        const uint32_t sb = stg * TILE_B;
        size_t ga0 = (size_t)(m0 + lr0) * K + k0 + lc0;
        size_t ga1 = (size_t)(m0 + lr1) * K + k0 + lc0;
        size_t gb0 = (size_t)(n0 + lr0) * K + k0 + lc0;
        size_t gb1 = (size_t)(n0 + lr1) * K + k0 + lc0;
        cp_async16_s(uAh + sb + so0, Ahi + ga0);  cp_async16_s(uAh + sb + so1, Ahi + ga1);
        cp_async16_s(uAl + sb + so0, Alo + ga0);  cp_async16_s(uAl + sb + so1, Alo + ga1);
        cp_async16_s(uBh + sb + so0, Bhi + gb0);  cp_async16_s(uBh + sb + so1, Bhi + gb1);
        cp_async16_s(uBl + sb + so0, Blo + gb0);  cp_async16_s(uBl + sb + so1, Blo + gb1);
        CP_COMMIT();
    }

    __device__ __forceinline__ void consume_stage(int stg) {
        const uint32_t stb = stg * TILE_B;
#pragma unroll
        for (int kk = 0; kk < 2; kk++) {
            uint32_t ah[4][4], al[4][4], bh[4][2], bl[4][2];
#pragma unroll
            for (int ms = 0; ms < 4; ms++) {
                int row = wm + ms * 16 + arow;
                uint32_t off = stb + swz(row, 2 * kk + achk);
                ldsm_x4(ah[ms], uAh + off);
                ldsm_x4(al[ms], uAl + off);
            }
#pragma unroll
            for (int nsp = 0; nsp < 2; nsp++) {
                int row = wn + nsp * 16 + brow;
                uint32_t off = stb + swz(row, 2 * kk + bchk);
                uint32_t r[4];
                ldsm_x4(r, uBh + off);
                bh[2*nsp][0] = r[0]; bh[2*nsp][1] = r[1];
                bh[2*nsp+1][0] = r[2]; bh[2*nsp+1][1] = r[3];
                ldsm_x4(r, uBl + off);
                bl[2*nsp][0] = r[0]; bl[2*nsp][1] = r[1];
                bl[2*nsp+1][0] = r[2]; bl[2*nsp+1][1] = r[3];
            }
#pragma unroll
            for (int ms = 0; ms < 4; ms++)
#pragma unroll
                for (int ns = 0; ns < 4; ns++) {
                    mma_bf16(acc[ms][ns], ah[ms], bh[ns]);
                    mma_bf16(acc[ms][ns], al[ms], bh[ns]);
                    mma_bf16(acc[ms][ns], ah[ms], bl[ns]);
                }
        }
    }

    __device__ __forceinline__ void mainloop(
        const __nv_bfloat16* Ahi, const __nv_bfloat16* Alo,
        const __nv_bfloat16* Bhi, const __nv_bfloat16* Blo, int K)
    {
        const int NK = K / BK;
        load_stage(0, 0, Ahi, Alo, Bhi, Blo, K);
        load_stage(1, BK, Ahi, Alo, Bhi, Blo, K);
        int s2 = 2;
        for (int kt = 0; kt < NK; kt++) {
            if (kt + 1 < NK) { CP_WAIT1(); } else { CP_WAIT0(); }
            __syncthreads();
            if (kt + 2 < NK) {
                load_stage(s2, (kt + 2) * BK, Ahi, Alo, Bhi, Blo, K);
            }
            int sc = s2 + 1; if (sc >= NSTG) sc -= NSTG;
            consume_stage(sc);
            s2 = sc;
        }
    }
};

__device__ __forceinline__ void split_store2(
    __nv_bfloat16* hi, __nv_bfloat16* lo, size_t idx2, float x, float y)
{
    __nv_bfloat16 hx = __float2bfloat16(x);
    __nv_bfloat16 hy = __float2bfloat16(y);
    ((__nv_bfloat162*)hi)[idx2] = __nv_bfloat162(hx, hy);
    ((__nv_bfloat162*)lo)[idx2] = __nv_bfloat162(
        __float2bfloat16(x - __bfloat162float(hx)),
        __float2bfloat16(y - __bfloat162float(hy)));
}

// proj 0=Q(rope), 1=K(rope), 2=V^T (A/B swapped, scatter to [b,h,d,s])
__global__ void __launch_bounds__(256, 2) gemm_qkv(
    const __nv_bfloat16* __restrict__ xhi, const __nv_bfloat16* __restrict__ xlo,
    const __nv_bfloat16* __restrict__ whi, const __nv_bfloat16* __restrict__ wlo,
    __nv_bfloat16* __restrict__ qhi, __nv_bfloat16* __restrict__ qlo,
    __nv_bfloat16* __restrict__ khi, __nv_bfloat16* __restrict__ klo,
    __nv_bfloat16* __restrict__ vthi, __nv_bfloat16* __restrict__ vtlo,
    const float* __restrict__ fc, const float* __restrict__ fs)
{
    extern __shared__ char smc[];
    const int proj = blockIdx.z;
    GemmCore g;
    const __nv_bfloat16* Whi = whi + (size_t)proj * DIM * DIM;
    const __nv_bfloat16* Wlo = wlo + (size_t)proj * DIM * DIM;

    if (proj == 2) {
        g.init(smc, blockIdx.y, blockIdx.x, threadIdx.x);
        g.mainloop(Whi, Wlo, xhi, xlo, DIM);
#pragma unroll
        for (int ms = 0; ms < 4; ms++)
#pragma unroll
            for (int ns = 0; ns < 4; ns++) {
                int e0 = g.m0 + g.wm + ms * 16 + g.gid;
                int sg = g.n0 + g.wn + ns * 8 + g.tig * 2;
                int b  = sg >> 11;
                int sl = sg & (SEQ - 1);
#pragma unroll
                for (int half = 0; half < 2; half++) {
                    int e = e0 + half * 8;
                    size_t off = (size_t)b * DIM * SEQ + (size_t)e * SEQ + sl;
                    split_store2(vthi, vtlo, off >> 1,
                                 g.acc[ms][ns][half * 2], g.acc[ms][ns][half * 2 + 1]);
                }
            }
        return;
    }

    g.init(smc, blockIdx.x, blockIdx.y, threadIdx.x);
    g.mainloop(xhi, xlo, Whi, Wlo, DIM);
    const int N = DIM;
    __nv_bfloat16* Chi = proj ? khi : qhi;
    __nv_bfloat16* Clo = proj ? klo : qlo;
#pragma unroll
    for (int ms = 0; ms < 4; ms++)
#pragma unroll
        for (int ns = 0; ns < 4; ns++) {
            int row0 = g.m0 + g.wm + ms * 16 + g.gid;
            int col  = g.n0 + g.wn + ns * 8 + g.tig * 2;
            int i = (col & 127) >> 1;
#pragma unroll
            for (int half = 0; half < 2; half++) {
                int row = row0 + half * 8;
                int s   = row & (SEQ - 1);
                float cs = __ldg(fc + s * 64 + i);
                float sn = __ldg(fs + s * 64 + i);
                float re = g.acc[ms][ns][half * 2];
                float im = g.acc[ms][ns][half * 2 + 1];
                float rx = re * cs - im * sn;
                float ry = re * sn + im * cs;
                split_store2(Chi, Clo, ((size_t)row * N + col) >> 1, rx, ry);
            }
        }
}

__global__ void __launch_bounds__(256, 2) gemm_out(
    const __nv_bfloat16* __restrict__ Ahi, const __nv_bfloat16* __restrict__ Alo,
    const __nv_bfloat16* __restrict__ Bhi, const __nv_bfloat16* __restrict__ Blo,
    float* __restrict__ C)
{
    extern __shared__ char smc[];
    GemmCore g;
    g.init(smc, blockIdx.x, blockIdx.y, threadIdx.x);
    g.mainloop(Ahi, Alo, Bhi, Blo, DIM);
    const int N = DIM;
#pragma unroll
    for (int ms = 0; ms < 4; ms++)
#pragma unroll
        for (int ns = 0; ns < 4; ns++) {
            int row = g.m0 + g.wm + ms * 16 + g.gid;
            int col = g.n0 + g.wn + ns * 8 + g.tig * 2;
            float2 c0 = {g.acc[ms][ns][0], g.acc[ms][ns][1]};
            float2 c1 = {g.acc[ms][ns][2], g.acc[ms][ns][3]};
            *(float2*)&C[(size_t)row * N + col]       = c0;
            *(float2*)&C[(size_t)(row + 8) * N + col] = c1;
        }
}

// ============================================================================
// tensor-core flash attention, bf16x3, causal.
// mbarrier producer/consumer K/V pipeline (.noinc async arrives, bounded
// waits) — no __syncthreads in mainloop; warps de-phase so softmax overlaps
// other warps' HMMA.
// ============================================================================
#define AQ  128
#define AK  64
#define AHS 136
#define AVS 72
#define A_QH        0
#define A_QL        17408
#define A_KH(bf)    (34816 + (bf)*8704)
#define A_KL(bf)    (52224 + (bf)*8704)
#define A_VH(bf)    (69632 + (bf)*9216)
#define A_VL(bf)    (88064 + (bf)*9216)
#define A_MBAR_B    212992                 // byte offset of mbarriers
#define ATTN_SMEM_BYTES (212992 + 64)

__global__ void __launch_bounds__(256) attn_tc_kernel(
    const __nv_bfloat16* __restrict__ qhi, const __nv_bfloat16* __restrict__ qlo,
    const __nv_bfloat16* __restrict__ khi, const __nv_bfloat16* __restrict__ klo,
    const __nv_bfloat16* __restrict__ vthi, const __nv_bfloat16* __restrict__ vtlo,
    __nv_bfloat16* __restrict__ ohi, __nv_bfloat16* __restrict__ olo)
{
    extern __shared__ __nv_bfloat16 smh[];
    const uint32_t ubase = smem_u32(smh);
    const uint32_t mb_full0  = ubase + A_MBAR_B;
    const uint32_t mb_full1  = ubase + A_MBAR_B + 8;
    const uint32_t mb_empty0 = ubase + A_MBAR_B + 16;
    const uint32_t mb_empty1 = ubase + A_MBAR_B + 24;

    const int t    = threadIdx.x;
    const int lane = t & 31;
    const int wid  = t >> 5;
    const int gid  = lane >> 2;
    const int tig  = lane & 3;
    const int qt = blockIdx.x, h = blockIdx.y, b = blockIdx.z;

    const int arow = (lane & 15);
    const int acol = (lane >> 4) << 3;
    const int brow = ((lane >> 4) << 3) + (lane & 7);
    const int bcol = ((lane >> 3) & 1) << 3;

    if (t == 0) {
        MBAR_INIT(mb_full0, 256);
        MBAR_INIT(mb_full1, 256);
        MBAR_INIT(mb_empty0, 256);
        MBAR_INIT(mb_empty1, 256);
    }
    __syncthreads();

    // ---- Q load (covered by full0's cp.async arrive) ----
    {
        int row = t >> 1;
        int cb  = (t & 1) * 8;
        size_t g = (size_t)(b * SEQ + qt * AQ + row) * DIM + h * HD + cb * 8;
        int so = row * AHS + cb * 8;
#pragma unroll
        for (int c = 0; c < 8; c++) {
            cp_async16(smh + A_QH + so + c * 8, qhi + g + c * 8);
            cp_async16(smh + A_QL + so + c * 8, qlo + g + c * 8);
        }
    }

#define LOAD_KV(BUFI, KT)                                                       \
    {                                                                           \
        int row = t >> 2;                                                       \
        int cb  = (t & 3) * 4;                                                  \
        size_t g = (size_t)(b * SEQ + (KT) * AK + row) * DIM + h * HD + cb * 8; \
        int so = row * AHS + cb * 8;                                            \
        _Pragma("unroll")                                                       \
        for (int c = 0; c < 4; c++) {                                           \
            cp_async16(smh + A_KH(BUFI) + so + c * 8, khi + g + c * 8);         \
            cp_async16(smh + A_KL(BUFI) + so + c * 8, klo + g + c * 8);         \
        }                                                                       \
        int vrow = t >> 1;                                                      \
        int vcb  = (t & 1) * 4;                                                 \
        size_t gv = (size_t)((b * NH + h) * HD + vrow) * SEQ + (KT) * AK + vcb * 8; \
        int sv = vrow * AVS + vcb * 8;                                          \
        _Pragma("unroll")                                                       \
        for (int c = 0; c < 4; c++) {                                           \
            cp_async16(smh + A_VH(BUFI) + sv + c * 8, vthi + gv + c * 8);       \
            cp_async16(smh + A_VL(BUFI) + sv + c * 8, vtlo + gv + c * 8);       \
        }                                                                       \
    }

    const int ktmax = 2 * qt + 1;
    LOAD_KV(0, 0);
    CP_ASYNC_MBAR_ARRIVE(mb_full0);      // trips when Q + stage0 copies land
    LOAD_KV(1, 1);
    CP_ASYNC_MBAR_ARRIVE(mb_full1);

    float sacc[8][4];
    float oacc[16][4];
#pragma unroll
    for (int i = 0; i < 16; i++)
#pragma unroll
        for (int e = 0; e < 4; e++) oacc[i][e] = 0.f;
    float m0 = -1e30f, m1 = -1e30f, l0 = 0.f, l1 = 0.f;

    const float scale = 0.08838834764831845f;
    const int gr0 = qt * AQ + wid * 16 + gid;
    int fph0 = 0, fph1 = 0, eph0 = 0, eph1 = 0;

    for (int kt = 0; kt <= ktmax; kt++) {
        const int s = kt & 1;

        // ---- wait stage data ready ----
        if (s == 0) { MBAR_WAIT(mb_full0, fph0); fph0 ^= 1; }
        else        { MBAR_WAIT(mb_full1, fph1); fph1 ^= 1; }

#pragma unroll
        for (int ns = 0; ns < 8; ns++)
#pragma unroll
            for (int e = 0; e < 4; e++) sacc[ns][e] = 0.f;

        const uint32_t ukh = ubase + A_KH(s) * 2;
        const uint32_t ukl = ubase + A_KL(s) * 2;
#pragma unroll
        for (int kk = 0; kk < 8; kk++) {
            uint32_t aoff = ((wid * 16 + arow) * AHS + kk * 16 + acol) * 2;
            uint32_t ah[4], al[4];
            ldsm_x4(ah, ubase + A_QH * 2 + aoff);
            ldsm_x4(al, ubase + A_QL * 2 + aoff);
#pragma unroll
            for (int nsp = 0; nsp < 4; nsp++) {
                uint32_t boff = ((nsp * 16 + brow) * AHS + kk * 16 + bcol) * 2;
                uint32_t rh[4], rl[4];
                ldsm_x4(rh, ukh + boff);
                ldsm_x4(rl, ukl + boff);
                uint32_t b0h[2] = {rh[0], rh[1]}, b1h[2] = {rh[2], rh[3]};
                uint32_t b0l[2] = {rl[0], rl[1]}, b1l[2] = {rl[2], rl[3]};
                mma_bf16(sacc[2*nsp],   ah, b0h);
                mma_bf16(sacc[2*nsp],   al, b0h);
                mma_bf16(sacc[2*nsp],   ah, b0l);
                mma_bf16(sacc[2*nsp+1], ah, b1h);
                mma_bf16(sacc[2*nsp+1], al, b1h);
                mma_bf16(sacc[2*nsp+1], ah, b1l);
            }
        }

        if (kt * AK + 63 > qt * AQ + wid * 16) {
            int rl0 = gr0 - kt * AK;
            int rl1 = rl0 + 8;
#pragma unroll
            for (int ns = 0; ns < 8; ns++) {
#pragma unroll
                for (int e = 0; e < 4; e++) {
                    float v = sacc[ns][e] * scale;
                    int cl = ns * 8 + 2 * tig + (e & 1);
                    int rl = (e < 2) ? rl0 : rl1;
                    sacc[ns][e] = (cl > rl) ? -1e30f : v;
                }
            }
        } else {
#pragma unroll
            for (int ns = 0; ns < 8; ns++)
#pragma unroll
                for (int e = 0; e < 4; e++) sacc[ns][e] *= scale;
        }

        float mx0 = -1e30f, mx1 = -1e30f;
#pragma unroll
        for (int ns = 0; ns < 8; ns++) {
            mx0 = fmaxf(mx0, fmaxf(sacc[ns][0], sacc[ns][1]));
            mx1 = fmaxf(mx1, fmaxf(sacc[ns][2], sacc[ns][3]));
        }
        mx0 = fmaxf(mx0, __shfl_xor_sync(0xffffffffu, mx0, 1));
        mx0 = fmaxf(mx0, __shfl_xor_sync(0xffffffffu, mx0, 2));
        mx1 = fmaxf(mx1, __shfl_xor_sync(0xffffffffu, mx1, 1));
        mx1 = fmaxf(mx1, __shfl_xor_sync(0xffffffffu, mx1, 2));
        float mn0 = fmaxf(m0, mx0), mn1 = fmaxf(m1, mx1);
        float a0 = __expf(m0 - mn0), a1 = __expf(m1 - mn1);
        m0 = mn0; m1 = mn1;

        float sum0 = 0.f, sum1 = 0.f;
#pragma unroll
        for (int ns = 0; ns < 8; ns++) {
            float p0 = __expf(sacc[ns][0] - mn0);
            float p1 = __expf(sacc[ns][1] - mn0);
            float p2 = __expf(sacc[ns][2] - mn1);
            float p3 = __expf(sacc[ns][3] - mn1);
            sacc[ns][0] = p0; sacc[ns][1] = p1;
            sacc[ns][2] = p2; sacc[ns][3] = p3;
            sum0 += p0 + p1; sum1 += p2 + p3;
        }
        sum0 += __shfl_xor_sync(0xffffffffu, sum0, 1);
        sum0 += __shfl_xor_sync(0xffffffffu, sum0, 2);
        sum1 += __shfl_xor_sync(0xffffffffu, sum1, 1);
        sum1 += __shfl_xor_sync(0xffffffffu, sum1, 2);
        l0 = l0 * a0 + sum0;
        l1 = l1 * a1 + sum1;

#pragma unroll
        for (int nd = 0; nd < 16; nd++) {
            oacc[nd][0] *= a0; oacc[nd][1] *= a0;
            oacc[nd][2] *= a1; oacc[nd][3] *= a1;
        }

        const uint32_t uvh = ubase + A_VH(s) * 2;
        const uint32_t uvl = ubase + A_VL(s) * 2;
#pragma unroll
        for (int kc = 0; kc < 4; kc++) {
            uint32_t ph[4], pl[4];
#pragma unroll
            for (int j = 0; j < 4; j++) {
                int ns = 2 * kc + (j >> 1);
                int e0 = (j & 1) * 2;
                float c0 = sacc[ns][e0], c1 = sacc[ns][e0 + 1];
                __nv_bfloat162 hb = __floats2bfloat162_rn(c0, c1);
                uint32_t hu = *(uint32_t*)&hb;
                float f0 = __uint_as_float(hu << 16);
                float f1 = __uint_as_float(hu & 0xffff0000u);
                __nv_bfloat162 lb = __floats2bfloat162_rn(c0 - f0, c1 - f1);
                ph[j] = hu;
                pl[j] = *(uint32_t*)&lb;
            }
#pragma unroll
            for (int ndp = 0; ndp < 8; ndp++) {
                uint32_t boff = ((ndp * 16 + brow) * AVS + kc * 16 + bcol) * 2;
                uint32_t rh[4], rl[4];
                ldsm_x4(rh, uvh + boff);
                ldsm_x4(rl, uvl + boff);
                uint32_t b0h[2] = {rh[0], rh[1]}, b1h[2] = {rh[2], rh[3]};
                uint32_t b0l[2] = {rl[0], rl[1]}, b1l[2] = {rl[2], rl[3]};
                mma_bf16(oacc[2*ndp],   ph, b0h);
                mma_bf16(oacc[2*ndp],   pl, b0h);
                mma_bf16(oacc[2*ndp],   ph, b0l);
                mma_bf16(oacc[2*ndp+1], ph, b1h);
                mma_bf16(oacc[2*ndp+1], pl, b1h);
                mma_bf16(oacc[2*ndp+1], ph, b1l);
            }
        }

        // ---- done reading stage s ----
        if (s == 0) MBAR_ARRIVE(mb_empty0); else MBAR_ARRIVE(mb_empty1);

        // ---- refill stage s with tile kt+2 once all warps released it ----
        if (kt + 2 <= ktmax) {
            if (s == 0) { MBAR_WAIT(mb_empty0, eph0); eph0 ^= 1; }
            else        { MBAR_WAIT(mb_empty1, eph1); eph1 ^= 1; }
            LOAD_KV(s, kt + 2);
            CP_ASYNC_MBAR_ARRIVE(s == 0 ? mb_full0 : mb_full1);
        }
    }

    // ---- normalize + split-store ----
    float i0 = 1.f / l0, i1 = 1.f / l1;
    size_t r0 = (size_t)(b * SEQ + gr0) * DIM + h * HD;
    size_t r1 = r0 + 8 * DIM;
#pragma unroll
    for (int nd = 0; nd < 16; nd++) {
        int col = nd * 8 + 2 * tig;
        split_store2(ohi, olo, (r0 + col) >> 1, oacc[nd][0] * i0, oacc[nd][1] * i0);
        split_store2(ohi, olo, (r1 + col) >> 1, oacc[nd][2] * i1, oacc[nd][3] * i1);
    }
}

// ---------------- launcher ---------------------------------------------------
extern "C" void kernel_launch(void* const* d_in, const int* in_sizes, int n_in,
                              void* d_out, int out_size)
{
    const float* x    = (const float*)d_in[0];
    const float* w[4] = {(const float*)d_in[1], (const float*)d_in[2],
                         (const float*)d_in[3], (const float*)d_in[4]};
    const float* fcos = (const float*)d_in[5];
    const float* fsin = (const float*)d_in[6];
    float* out = (float*)d_out;

    __nv_bfloat16 *xhi, *xlo, *ohi, *olo, *whi, *wlo;
    __nv_bfloat16 *qhi, *qlo, *khi, *klo, *vthi, *vtlo;
    cudaGetSymbolAddress((void**)&xhi, g_xhi);
    cudaGetSymbolAddress((void**)&xlo, g_xlo);
    cudaGetSymbolAddress((void**)&ohi, g_ohi);
    cudaGetSymbolAddress((void**)&olo, g_olo);
    cudaGetSymbolAddress((void**)&whi, g_whi);
    cudaGetSymbolAddress((void**)&wlo, g_wlo);
    cudaGetSymbolAddress((void**)&qhi, g_qhi);
    cudaGetSymbolAddress((void**)&qlo, g_qlo);
    cudaGetSymbolAddress((void**)&khi, g_khi);
    cudaGetSymbolAddress((void**)&klo, g_klo);
    cudaGetSymbolAddress((void**)&vthi, g_vthi);
    cudaGetSymbolAddress((void**)&vtlo, g_vtlo);

    cudaFuncSetAttribute(gemm_qkv,
                         cudaFuncAttributeMaxDynamicSharedMemorySize, GEMM_SMEM_BYTES);
    cudaFuncSetAttribute(gemm_out,
                         cudaFuncAttributeMaxDynamicSharedMemorySize, GEMM_SMEM_BYTES);
    cudaFuncSetAttribute(attn_tc_kernel,
                         cudaFuncAttributeMaxDynamicSharedMemorySize, ATTN_SMEM_BYTES);

    int nx4 = ROWS * DIM / 4;
    int nw4 = DIM * DIM / 4;
    split_kernel<<<nx4 / 256, 256>>>(x, xhi, xlo, nx4);
    split4_kernel<<<dim3(nw4 / 256, 4), 256>>>(w[0], w[1], w[2], w[3], whi, wlo, nw4);

    dim3 gqkv(DIM / BN, ROWS / BM, 3);   // (16, 32, 3)
    gemm_qkv<<<gqkv, 256, GEMM_SMEM_BYTES>>>(
        xhi, xlo, whi, wlo, qhi, qlo, khi, klo, vthi, vtlo, fcos, fsin);

    attn_tc_kernel<<<dim3(SEQ / AQ, NH, BATCH), 256, ATTN_SMEM_BYTES>>>(
        qhi, qlo, khi, klo, vthi, vtlo, ohi, olo);

    gemm_out<<<dim3(DIM / BN, ROWS / BM), 256, GEMM_SMEM_BYTES>>>(
        ohi, olo, whi + 3*(size_t)DIM*DIM, wlo + 3*(size_t)DIM*DIM, out);
}

// round 15
// speedup vs baseline: 3.1880x; 1.0114x over previous
#include <cuda_runtime.h>
#include <cuda_bf16.h>
#include <cstdint>

#define BATCH 2
#define SEQ   2048
#define DIM   2048
#define NH    16
#define HD    128
#define ROWS  (BATCH*SEQ)   // 4096

// ---------------- scratch (static device globals; no allocs allowed) --------
__device__ __nv_bfloat16 g_xhi[ROWS*DIM];
__device__ __nv_bfloat16 g_xlo[ROWS*DIM];
__device__ __nv_bfloat16 g_ohi[ROWS*DIM];
__device__ __nv_bfloat16 g_olo[ROWS*DIM];
__device__ __nv_bfloat16 g_whi[4][DIM*DIM];   // q,k,v,o
__device__ __nv_bfloat16 g_wlo[4][DIM*DIM];

__device__ __nv_bfloat16 g_qhi[ROWS*DIM];
__device__ __nv_bfloat16 g_qlo[ROWS*DIM];
__device__ __nv_bfloat16 g_khi[ROWS*DIM];
__device__ __nv_bfloat16 g_klo[ROWS*DIM];
__device__ __nv_bfloat16 g_vthi[ROWS*DIM];    // per-head transposed [b,h,d,s]
__device__ __nv_bfloat16 g_vtlo[ROWS*DIM];

// ============================================================================
// helpers
// ============================================================================
__device__ __forceinline__ void cp_async16(void* smem, const void* gmem) {
    uint32_t s = (uint32_t)__cvta_generic_to_shared(smem);
    asm volatile("cp.async.cg.shared.global [%0], [%1], 16;\n" :: "r"(s), "l"(gmem));
}
__device__ __forceinline__ void cp_async16_s(uint32_t saddr, const void* gmem) {
    asm volatile("cp.async.cg.shared.global [%0], [%1], 16;\n" :: "r"(saddr), "l"(gmem));
}
#define CP_COMMIT() asm volatile("cp.async.commit_group;\n" ::: "memory")
#define CP_WAIT1()  asm volatile("cp.async.wait_group 1;\n" ::: "memory")
#define CP_WAIT0()  asm volatile("cp.async.wait_group 0;\n" ::: "memory")

__device__ __forceinline__ void mma_bf16(float* c, const uint32_t* a, const uint32_t* b) {
    asm volatile(
        "mma.sync.aligned.m16n8k16.row.col.f32.bf16.bf16.f32 "
        "{%0,%1,%2,%3}, {%4,%5,%6,%7}, {%8,%9}, {%0,%1,%2,%3};\n"
        : "+f"(c[0]), "+f"(c[1]), "+f"(c[2]), "+f"(c[3])
        : "r"(a[0]), "r"(a[1]), "r"(a[2]), "r"(a[3]),
          "r"(b[0]), "r"(b[1]));
}
__device__ __forceinline__ void ldsm_x4(uint32_t* r, uint32_t saddr) {
    asm volatile("ldmatrix.sync.aligned.m8n8.x4.shared.b16 {%0,%1,%2,%3}, [%4];"
        : "=r"(r[0]), "=r"(r[1]), "=r"(r[2]), "=r"(r[3]) : "r"(saddr));
}
__device__ __forceinline__ uint32_t smem_u32(const void* p) {
    return (uint32_t)__cvta_generic_to_shared(p);
}

// ---- mbarrier (sm_90-era PTX; valid on this sm_100 target) -----------------
#define MBAR_INIT(addr, cnt) \
    asm volatile("mbarrier.init.shared.b64 [%0], %1;" :: "r"(addr), "r"(cnt) : "memory")
#define MBAR_ARRIVE(addr) \
    asm volatile("{\n\t.reg .b64 st;\n\tmbarrier.arrive.shared.b64 st, [%0];\n\t}" \
                 :: "r"(addr) : "memory")
// .noinc: the async arrive counts against the initialized expected count and
// covers ALL prior cp.asyncs issued by this thread.
#define CP_ASYNC_MBAR_ARRIVE(addr) \
    asm volatile("cp.async.mbarrier.arrive.noinc.shared.b64 [%0];" :: "r"(addr) : "memory")
// Bounded spin: a protocol bug fails fast (wrong answer) instead of a
// container-killing 120s hang. Never triggers when the protocol is correct.
#define MBAR_WAIT(addr, parity) do {                                            \
    uint32_t _done = 0; uint32_t _spin = 0;                                     \
    while (!_done && _spin < (1u << 24)) {                                      \
        asm volatile(                                                           \
            "{\n\t.reg .pred p;\n\t"                                            \
            "mbarrier.try_wait.parity.shared.b64 p, [%1], %2;\n\t"              \
            "selp.b32 %0, 1, 0, p;\n\t}"                                        \
            : "=r"(_done) : "r"(addr), "r"(parity) : "memory");                 \
        _spin++;                                                                \
    }                                                                           \
} while (0)

// ---------------- fp32 -> bf16 hi/lo split (x) -------------------------------
__global__ void split_kernel(const float* __restrict__ in,
                             __nv_bfloat16* __restrict__ hi,
                             __nv_bfloat16* __restrict__ lo, int n4)
{
    int idx = blockIdx.x * blockDim.x + threadIdx.x;
    if (idx >= n4) return;
    float4 v = ((const float4*)in)[idx];
    __nv_bfloat16 h0 = __float2bfloat16(v.x);
    __nv_bfloat16 h1 = __float2bfloat16(v.y);
    __nv_bfloat16 h2 = __float2bfloat16(v.z);
    __nv_bfloat16 h3 = __float2bfloat16(v.w);
    __nv_bfloat16 l0 = __float2bfloat16(v.x - __bfloat162float(h0));
    __nv_bfloat16 l1 = __float2bfloat16(v.y - __bfloat162float(h1));
    __nv_bfloat16 l2 = __float2bfloat16(v.z - __bfloat162float(h2));
    __nv_bfloat16 l3 = __float2bfloat16(v.w - __bfloat162float(h3));
    ((__nv_bfloat162*)hi)[idx*2+0] = __nv_bfloat162(h0, h1);
    ((__nv_bfloat162*)hi)[idx*2+1] = __nv_bfloat162(h2, h3);
    ((__nv_bfloat162*)lo)[idx*2+0] = __nv_bfloat162(l0, l1);
    ((__nv_bfloat162*)lo)[idx*2+1] = __nv_bfloat162(l2, l3);
}

// ---------------- fused 4-weight split (grid.y selects weight) ---------------
__global__ void split4_kernel(const float* __restrict__ w0,
                              const float* __restrict__ w1,
                              const float* __restrict__ w2,
                              const float* __restrict__ w3,
                              __nv_bfloat16* __restrict__ hib,
                              __nv_bfloat16* __restrict__ lob, int n4)
{
    int idx = blockIdx.x * blockDim.x + threadIdx.x;
    if (idx >= n4) return;
    int wsel = blockIdx.y;
    const float* in = (wsel == 0) ? w0 : (wsel == 1) ? w1 : (wsel == 2) ? w2 : w3;
    __nv_bfloat16* hi = hib + (size_t)wsel * DIM * DIM;
    __nv_bfloat16* lo = lob + (size_t)wsel * DIM * DIM;
    float4 v = ((const float4*)in)[idx];
    __nv_bfloat16 h0 = __float2bfloat16(v.x);
    __nv_bfloat16 h1 = __float2bfloat16(v.y);
    __nv_bfloat16 h2 = __float2bfloat16(v.z);
    __nv_bfloat16 h3 = __float2bfloat16(v.w);
    __nv_bfloat16 l0 = __float2bfloat16(v.x - __bfloat162float(h0));
    __nv_bfloat16 l1 = __float2bfloat16(v.y - __bfloat162float(h1));
    __nv_bfloat16 l2 = __float2bfloat16(v.z - __bfloat162float(h2));
    __nv_bfloat16 l3 = __float2bfloat16(v.w - __bfloat162float(h3));
    ((__nv_bfloat162*)hi)[idx*2+0] = __nv_bfloat162(h0, h1);
    ((__nv_bfloat162*)hi)[idx*2+1] = __nv_bfloat162(h2, h3);
    ((__nv_bfloat162*)lo)[idx*2+0] = __nv_bfloat162(l0, l1);
    ((__nv_bfloat162*)lo)[idx*2+1] = __nv_bfloat162(l2, l3);
}

// ============================================================================
// bf16x3 GEMM: ldmatrix + XOR-swizzled smem, 3-stage cp.async, 1 sync/iter,
// 2 CTAs/SM.  C = (Ahi+Alo) (Bhi+Blo)^T   (unchanged from R14)
// ============================================================================
#define BM 128
#define BN 128
#define BK 32
#define NSTG 3
#define TILE_B (BM*BK*2)            // 8192 bytes per tile per stage
#define GEMM_SMEM_BYTES (4*NSTG*TILE_B)   // 98304

__device__ __forceinline__ uint32_t swz(int row, int chunk) {
    return (uint32_t)(row * 64 + ((chunk ^ ((row >> 1) & 3)) << 4));
}

struct GemmCore {
    uint32_t uAh, uAl, uBh, uBl;
    int t, lane, wid, gid, tig, wm, wn, m0, n0;
    int arow, achk, brow, bchk;
    int lr0, lc0, lr1;
    uint32_t so0, so1;
    float acc[4][4][4];

    __device__ __forceinline__ void init(char* smc, int bx, int by, int tid) {
        uAh = smem_u32(smc);
        uAl = uAh + NSTG * TILE_B;
        uBh = uAh + 2 * NSTG * TILE_B;
        uBl = uAh + 3 * NSTG * TILE_B;
        t = tid; lane = t & 31; wid = t >> 5;
        gid = lane >> 2; tig = lane & 3;
        wm = (wid & 1) * 64; wn = (wid >> 1) * 32;
        m0 = by * BM; n0 = bx * BN;
        arow = lane & 15; achk = lane >> 4;
        brow = ((lane >> 4) << 3) + (lane & 7);
        bchk = (lane >> 3) & 1;
        lr0 = t >> 2; lc0 = (t & 3) * 8; lr1 = lr0 + 64;
        so0 = swz(lr0, t & 3);
        so1 = swz(lr1, t & 3);
#pragma unroll
        for (int i = 0; i < 4; i++)
#pragma unroll
            for (int j = 0; j < 4; j++)
#pragma unroll
                for (int e = 0; e < 4; e++) acc[i][j][e] = 0.f;
    }

    __device__ __forceinline__ void load_stage(
        int stg, int k0,
        const __nv_bfloat16* Ahi, const __nv_bfloat16* Alo,
        const __nv_bfloat16* Bhi, const __nv_bfloat16* Blo, int K)
    {
        const uint32_t sb = stg * TILE_B;
        size_t ga0 = (size_t)(m0 + lr0) * K + k0 + lc0;
        size_t ga1 = (size_t)(m0 + lr1) * K + k0 + lc0;
        size_t gb0 = (size_t)(n0 + lr0) * K + k0 + lc0;
        size_t gb1 = (size_t)(n0 + lr1) * K + k0 + lc0;
        cp_async16_s(uAh + sb + so0, Ahi + ga0);  cp_async16_s(uAh + sb + so1, Ahi + ga1);
        cp_async16_s(uAl + sb + so0, Alo + ga0);  cp_async16_s(uAl + sb + so1, Alo + ga1);
        cp_async16_s(uBh + sb + so0, Bhi + gb0);  cp_async16_s(uBh + sb + so1, Bhi + gb1);
        cp_async16_s(uBl + sb + so0, Blo + gb0);  cp_async16_s(uBl + sb + so1, Blo + gb1);
        CP_COMMIT();
    }

    __device__ __forceinline__ void consume_stage(int stg) {
        const uint32_t stb = stg * TILE_B;
#pragma unroll
        for (int kk = 0; kk < 2; kk++) {
            uint32_t ah[4][4], al[4][4], bh[4][2], bl[4][2];
#pragma unroll
            for (int ms = 0; ms < 4; ms++) {
                int row = wm + ms * 16 + arow;
                uint32_t off = stb + swz(row, 2 * kk + achk);
                ldsm_x4(ah[ms], uAh + off);
                ldsm_x4(al[ms], uAl + off);
            }
#pragma unroll
            for (int nsp = 0; nsp < 2; nsp++) {
                int row = wn + nsp * 16 + brow;
                uint32_t off = stb + swz(row, 2 * kk + bchk);
                uint32_t r[4];
                ldsm_x4(r, uBh + off);
                bh[2*nsp][0] = r[0]; bh[2*nsp][1] = r[1];
                bh[2*nsp+1][0] = r[2]; bh[2*nsp+1][1] = r[3];
                ldsm_x4(r, uBl + off);
                bl[2*nsp][0] = r[0]; bl[2*nsp][1] = r[1];
                bl[2*nsp+1][0] = r[2]; bl[2*nsp+1][1] = r[3];
            }
#pragma unroll
            for (int ms = 0; ms < 4; ms++)
#pragma unroll
                for (int ns = 0; ns < 4; ns++) {
                    mma_bf16(acc[ms][ns], ah[ms], bh[ns]);
                    mma_bf16(acc[ms][ns], al[ms], bh[ns]);
                    mma_bf16(acc[ms][ns], ah[ms], bl[ns]);
                }
        }
    }

    __device__ __forceinline__ void mainloop(
        const __nv_bfloat16* Ahi, const __nv_bfloat16* Alo,
        const __nv_bfloat16* Bhi, const __nv_bfloat16* Blo, int K)
    {
        const int NK = K / BK;
        load_stage(0, 0, Ahi, Alo, Bhi, Blo, K);
        load_stage(1, BK, Ahi, Alo, Bhi, Blo, K);
        int s2 = 2;
        for (int kt = 0; kt < NK; kt++) {
            if (kt + 1 < NK) { CP_WAIT1(); } else { CP_WAIT0(); }
            __syncthreads();
            if (kt + 2 < NK) {
                load_stage(s2, (kt + 2) * BK, Ahi, Alo, Bhi, Blo, K);
            }
            int sc = s2 + 1; if (sc >= NSTG) sc -= NSTG;
            consume_stage(sc);
            s2 = sc;
        }
    }
};

__device__ __forceinline__ void split_store2(
    __nv_bfloat16* hi, __nv_bfloat16* lo, size_t idx2, float x, float y)
{
    __nv_bfloat16 hx = __float2bfloat16(x);
    __nv_bfloat16 hy = __float2bfloat16(y);
    ((__nv_bfloat162*)hi)[idx2] = __nv_bfloat162(hx, hy);
    ((__nv_bfloat162*)lo)[idx2] = __nv_bfloat162(
        __float2bfloat16(x - __bfloat162float(hx)),
        __float2bfloat16(y - __bfloat162float(hy)));
}

// proj 0=Q(rope), 1=K(rope), 2=V^T (A/B swapped, scatter to [b,h,d,s])
__global__ void __launch_bounds__(256, 2) gemm_qkv(
    const __nv_bfloat16* __restrict__ xhi, const __nv_bfloat16* __restrict__ xlo,
    const __nv_bfloat16* __restrict__ whi, const __nv_bfloat16* __restrict__ wlo,
    __nv_bfloat16* __restrict__ qhi, __nv_bfloat16* __restrict__ qlo,
    __nv_bfloat16* __restrict__ khi, __nv_bfloat16* __restrict__ klo,
    __nv_bfloat16* __restrict__ vthi, __nv_bfloat16* __restrict__ vtlo,
    const float* __restrict__ fc, const float* __restrict__ fs)
{
    extern __shared__ char smc[];
    const int proj = blockIdx.z;
    GemmCore g;
    const __nv_bfloat16* Whi = whi + (size_t)proj * DIM * DIM;
    const __nv_bfloat16* Wlo = wlo + (size_t)proj * DIM * DIM;

    if (proj == 2) {
        g.init(smc, blockIdx.y, blockIdx.x, threadIdx.x);
        g.mainloop(Whi, Wlo, xhi, xlo, DIM);
#pragma unroll
        for (int ms = 0; ms < 4; ms++)
#pragma unroll
            for (int ns = 0; ns < 4; ns++) {
                int e0 = g.m0 + g.wm + ms * 16 + g.gid;
                int sg = g.n0 + g.wn + ns * 8 + g.tig * 2;
                int b  = sg >> 11;
                int sl = sg & (SEQ - 1);
#pragma unroll
                for (int half = 0; half < 2; half++) {
                    int e = e0 + half * 8;
                    size_t off = (size_t)b * DIM * SEQ + (size_t)e * SEQ + sl;
                    split_store2(vthi, vtlo, off >> 1,
                                 g.acc[ms][ns][half * 2], g.acc[ms][ns][half * 2 + 1]);
                }
            }
        return;
    }

    g.init(smc, blockIdx.x, blockIdx.y, threadIdx.x);
    g.mainloop(xhi, xlo, Whi, Wlo, DIM);
    const int N = DIM;
    __nv_bfloat16* Chi = proj ? khi : qhi;
    __nv_bfloat16* Clo = proj ? klo : qlo;
#pragma unroll
    for (int ms = 0; ms < 4; ms++)
#pragma unroll
        for (int ns = 0; ns < 4; ns++) {
            int row0 = g.m0 + g.wm + ms * 16 + g.gid;
            int col  = g.n0 + g.wn + ns * 8 + g.tig * 2;
            int i = (col & 127) >> 1;
#pragma unroll
            for (int half = 0; half < 2; half++) {
                int row = row0 + half * 8;
                int s   = row & (SEQ - 1);
                float cs = __ldg(fc + s * 64 + i);
                float sn = __ldg(fs + s * 64 + i);
                float re = g.acc[ms][ns][half * 2];
                float im = g.acc[ms][ns][half * 2 + 1];
                float rx = re * cs - im * sn;
                float ry = re * sn + im * cs;
                split_store2(Chi, Clo, ((size_t)row * N + col) >> 1, rx, ry);
            }
        }
}

__global__ void __launch_bounds__(256, 2) gemm_out(
    const __nv_bfloat16* __restrict__ Ahi, const __nv_bfloat16* __restrict__ Alo,
    const __nv_bfloat16* __restrict__ Bhi, const __nv_bfloat16* __restrict__ Blo,
    float* __restrict__ C)
{
    extern __shared__ char smc[];
    GemmCore g;
    g.init(smc, blockIdx.x, blockIdx.y, threadIdx.x);
    g.mainloop(Ahi, Alo, Bhi, Blo, DIM);
    const int N = DIM;
#pragma unroll
    for (int ms = 0; ms < 4; ms++)
#pragma unroll
        for (int ns = 0; ns < 4; ns++) {
            int row = g.m0 + g.wm + ms * 16 + g.gid;
            int col = g.n0 + g.wn + ns * 8 + g.tig * 2;
            float2 c0 = {g.acc[ms][ns][0], g.acc[ms][ns][1]};
            float2 c1 = {g.acc[ms][ns][2], g.acc[ms][ns][3]};
            *(float2*)&C[(size_t)row * N + col]       = c0;
            *(float2*)&C[(size_t)(row + 8) * N + col] = c1;
        }
}

// ============================================================================
// tensor-core flash attention, bf16x3, causal.
// R15: warp-specialized — 8 consumer warps (compute only) + 4 producer warps
// (all cp.async traffic). full=128 producer .noinc arrives; empty=256
// consumer arrives. Long CTAs (large qt) launch first.
// ============================================================================
#define AQ  128
#define AK  64
#define AHS 136
#define AVS 72
#define A_QH        0
#define A_QL        17408
#define A_KH(bf)    (34816 + (bf)*8704)
#define A_KL(bf)    (52224 + (bf)*8704)
#define A_VH(bf)    (69632 + (bf)*9216)
#define A_VL(bf)    (88064 + (bf)*9216)
#define A_MBAR_B    212992                 // byte offset of mbarriers
#define ATTN_SMEM_BYTES (212992 + 64)

__global__ void __launch_bounds__(384) attn_tc_kernel(
    const __nv_bfloat16* __restrict__ qhi, const __nv_bfloat16* __restrict__ qlo,
    const __nv_bfloat16* __restrict__ khi, const __nv_bfloat16* __restrict__ klo,
    const __nv_bfloat16* __restrict__ vthi, const __nv_bfloat16* __restrict__ vtlo,
    __nv_bfloat16* __restrict__ ohi, __nv_bfloat16* __restrict__ olo)
{
    extern __shared__ __nv_bfloat16 smh[];
    const uint32_t ubase = smem_u32(smh);
    const uint32_t mb_full0  = ubase + A_MBAR_B;
    const uint32_t mb_full1  = ubase + A_MBAR_B + 8;
    const uint32_t mb_empty0 = ubase + A_MBAR_B + 16;
    const uint32_t mb_empty1 = ubase + A_MBAR_B + 24;

    const int t    = threadIdx.x;
    const int lane = t & 31;
    const int wid  = t >> 5;            // 0..7 consumer, 8..11 producer
    const int gid  = lane >> 2;
    const int tig  = lane & 3;
    const int qt = gridDim.x - 1 - blockIdx.x;   // long CTAs first
    const int h = blockIdx.y, b = blockIdx.z;

    const int arow = (lane & 15);
    const int acol = (lane >> 4) << 3;
    const int brow = ((lane >> 4) << 3) + (lane & 7);
    const int bcol = ((lane >> 3) & 1) << 3;

    if (t == 0) {
        MBAR_INIT(mb_full0, 128);
        MBAR_INIT(mb_full1, 128);
        MBAR_INIT(mb_empty0, 256);
        MBAR_INIT(mb_empty1, 256);
    }
    __syncthreads();

    const int ktmax = 2 * qt + 1;

    // =================== PRODUCER warps (wid 8..11) ===================
    if (wid >= 8) {
        const int pt = t - 256;   // 0..127

        // Q tile: row = pt, 16 chunks hi + 16 lo
        {
            size_t g = (size_t)(b * SEQ + qt * AQ + pt) * DIM + h * HD;
            int so = pt * AHS;
#pragma unroll
            for (int c = 0; c < 16; c++) {
                cp_async16(smh + A_QH + so + c * 8, qhi + g + c * 8);
                cp_async16(smh + A_QL + so + c * 8, qlo + g + c * 8);
            }
        }

#define LOAD_KV_P(BUFI, KT)                                                     \
        {                                                                       \
            int row = pt >> 1;                                                  \
            int cb  = (pt & 1) * 8;                                             \
            size_t g = (size_t)(b * SEQ + (KT) * AK + row) * DIM + h * HD + cb * 8; \
            int so = row * AHS + cb * 8;                                        \
            _Pragma("unroll")                                                   \
            for (int c = 0; c < 8; c++) {                                       \
                cp_async16(smh + A_KH(BUFI) + so + c * 8, khi + g + c * 8);     \
                cp_async16(smh + A_KL(BUFI) + so + c * 8, klo + g + c * 8);     \
            }                                                                   \
            size_t gv = (size_t)((b * NH + h) * HD + pt) * SEQ + (KT) * AK;     \
            int sv = pt * AVS;                                                  \
            _Pragma("unroll")                                                   \
            for (int c = 0; c < 8; c++) {                                       \
                cp_async16(smh + A_VH(BUFI) + sv + c * 8, vthi + gv + c * 8);   \
                cp_async16(smh + A_VL(BUFI) + sv + c * 8, vtlo + gv + c * 8);   \
            }                                                                   \
        }

        LOAD_KV_P(0, 0);
        CP_ASYNC_MBAR_ARRIVE(mb_full0);     // covers Q + stage0
        LOAD_KV_P(1, 1);
        CP_ASYNC_MBAR_ARRIVE(mb_full1);

        int ep0 = 0, ep1 = 0;
        for (int kt = 2; kt <= ktmax; kt++) {
            const int s = kt & 1;
            if (s == 0) { MBAR_WAIT(mb_empty0, ep0); ep0 ^= 1; }
            else        { MBAR_WAIT(mb_empty1, ep1); ep1 ^= 1; }
            LOAD_KV_P(s, kt);
            CP_ASYNC_MBAR_ARRIVE(s == 0 ? mb_full0 : mb_full1);
        }
        return;
    }

    // =================== CONSUMER warps (wid 0..7) ===================
    float sacc[8][4];
    float oacc[16][4];
#pragma unroll
    for (int i = 0; i < 16; i++)
#pragma unroll
        for (int e = 0; e < 4; e++) oacc[i][e] = 0.f;
    float m0 = -1e30f, m1 = -1e30f, l0 = 0.f, l1 = 0.f;

    const float scale = 0.08838834764831845f;
    const int gr0 = qt * AQ + wid * 16 + gid;
    int fph0 = 0, fph1 = 0;

    for (int kt = 0; kt <= ktmax; kt++) {
        const int s = kt & 1;

        if (s == 0) { MBAR_WAIT(mb_full0, fph0); fph0 ^= 1; }
        else        { MBAR_WAIT(mb_full1, fph1); fph1 ^= 1; }

#pragma unroll
        for (int ns = 0; ns < 8; ns++)
#pragma unroll
            for (int e = 0; e < 4; e++) sacc[ns][e] = 0.f;

        const uint32_t ukh = ubase + A_KH(s) * 2;
        const uint32_t ukl = ubase + A_KL(s) * 2;
#pragma unroll
        for (int kk = 0; kk < 8; kk++) {
            uint32_t aoff = ((wid * 16 + arow) * AHS + kk * 16 + acol) * 2;
            uint32_t ah[4], al[4];
            ldsm_x4(ah, ubase + A_QH * 2 + aoff);
            ldsm_x4(al, ubase + A_QL * 2 + aoff);
#pragma unroll
            for (int nsp = 0; nsp < 4; nsp++) {
                uint32_t boff = ((nsp * 16 + brow) * AHS + kk * 16 + bcol) * 2;
                uint32_t rh[4], rl[4];
                ldsm_x4(rh, ukh + boff);
                ldsm_x4(rl, ukl + boff);
                uint32_t b0h[2] = {rh[0], rh[1]}, b1h[2] = {rh[2], rh[3]};
                uint32_t b0l[2] = {rl[0], rl[1]}, b1l[2] = {rl[2], rl[3]};
                mma_bf16(sacc[2*nsp],   ah, b0h);
                mma_bf16(sacc[2*nsp+1], ah, b1h);
                mma_bf16(sacc[2*nsp],   al, b0h);
                mma_bf16(sacc[2*nsp+1], al, b1h);
                mma_bf16(sacc[2*nsp],   ah, b0l);
                mma_bf16(sacc[2*nsp+1], ah, b1l);
            }
        }

        if (kt * AK + 63 > qt * AQ + wid * 16) {
            int rl0 = gr0 - kt * AK;
            int rl1 = rl0 + 8;
#pragma unroll
            for (int ns = 0; ns < 8; ns++) {
#pragma unroll
                for (int e = 0; e < 4; e++) {
                    float v = sacc[ns][e] * scale;
                    int cl = ns * 8 + 2 * tig + (e & 1);
                    int rl = (e < 2) ? rl0 : rl1;
                    sacc[ns][e] = (cl > rl) ? -1e30f : v;
                }
            }
        } else {
#pragma unroll
            for (int ns = 0; ns < 8; ns++)
#pragma unroll
                for (int e = 0; e < 4; e++) sacc[ns][e] *= scale;
        }

        float mx0 = -1e30f, mx1 = -1e30f;
#pragma unroll
        for (int ns = 0; ns < 8; ns++) {
            mx0 = fmaxf(mx0, fmaxf(sacc[ns][0], sacc[ns][1]));
            mx1 = fmaxf(mx1, fmaxf(sacc[ns][2], sacc[ns][3]));
        }
        mx0 = fmaxf(mx0, __shfl_xor_sync(0xffffffffu, mx0, 1));
        mx0 = fmaxf(mx0, __shfl_xor_sync(0xffffffffu, mx0, 2));
        mx1 = fmaxf(mx1, __shfl_xor_sync(0xffffffffu, mx1, 1));
        mx1 = fmaxf(mx1, __shfl_xor_sync(0xffffffffu, mx1, 2));
        float mn0 = fmaxf(m0, mx0), mn1 = fmaxf(m1, mx1);
        float a0 = __expf(m0 - mn0), a1 = __expf(m1 - mn1);
        m0 = mn0; m1 = mn1;

        float sum0 = 0.f, sum1 = 0.f;
#pragma unroll
        for (int ns = 0; ns < 8; ns++) {
            float p0 = __expf(sacc[ns][0] - mn0);
            float p1 = __expf(sacc[ns][1] - mn0);
            float p2 = __expf(sacc[ns][2] - mn1);
            float p3 = __expf(sacc[ns][3] - mn1);
            sacc[ns][0] = p0; sacc[ns][1] = p1;
            sacc[ns][2] = p2; sacc[ns][3] = p3;
            sum0 += p0 + p1; sum1 += p2 + p3;
        }
        sum0 += __shfl_xor_sync(0xffffffffu, sum0, 1);
        sum0 += __shfl_xor_sync(0xffffffffu, sum0, 2);
        sum1 += __shfl_xor_sync(0xffffffffu, sum1, 1);
        sum1 += __shfl_xor_sync(0xffffffffu, sum1, 2);
        l0 = l0 * a0 + sum0;
        l1 = l1 * a1 + sum1;

#pragma unroll
        for (int nd = 0; nd < 16; nd++) {
            oacc[nd][0] *= a0; oacc[nd][1] *= a0;
            oacc[nd][2] *= a1; oacc[nd][3] *= a1;
        }

        const uint32_t uvh = ubase + A_VH(s) * 2;
        const uint32_t uvl = ubase + A_VL(s) * 2;
#pragma unroll
        for (int kc = 0; kc < 4; kc++) {
            uint32_t ph[4], pl[4];
#pragma unroll
            for (int j = 0; j < 4; j++) {
                int ns = 2 * kc + (j >> 1);
                int e0 = (j & 1) * 2;
                float c0 = sacc[ns][e0], c1 = sacc[ns][e0 + 1];
                __nv_bfloat162 hb = __floats2bfloat162_rn(c0, c1);
                uint32_t hu = *(uint32_t*)&hb;
                float f0 = __uint_as_float(hu << 16);
                float f1 = __uint_as_float(hu & 0xffff0000u);
                __nv_bfloat162 lb = __floats2bfloat162_rn(c0 - f0, c1 - f1);
                ph[j] = hu;
                pl[j] = *(uint32_t*)&lb;
            }
#pragma unroll
            for (int ndp = 0; ndp < 8; ndp++) {
                uint32_t boff = ((ndp * 16 + brow) * AVS + kc * 16 + bcol) * 2;
                uint32_t rh[4], rl[4];
                ldsm_x4(rh, uvh + boff);
                ldsm_x4(rl, uvl + boff);
                uint32_t b0h[2] = {rh[0], rh[1]}, b1h[2] = {rh[2], rh[3]};
                uint32_t b0l[2] = {rl[0], rl[1]}, b1l[2] = {rl[2], rl[3]};
                mma_bf16(oacc[2*ndp],   ph, b0h);
                mma_bf16(oacc[2*ndp+1], ph, b1h);
                mma_bf16(oacc[2*ndp],   pl, b0h);
                mma_bf16(oacc[2*ndp+1], pl, b1h);
                mma_bf16(oacc[2*ndp],   ph, b0l);
                mma_bf16(oacc[2*ndp+1], ph, b1l);
            }
        }

        // ---- done reading stage s ----
        if (s == 0) MBAR_ARRIVE(mb_empty0); else MBAR_ARRIVE(mb_empty1);
    }

    // ---- normalize + split-store ----
    float i0 = 1.f / l0, i1 = 1.f / l1;
    size_t r0 = (size_t)(b * SEQ + gr0) * DIM + h * HD;
    size_t r1 = r0 + 8 * DIM;
#pragma unroll
    for (int nd = 0; nd < 16; nd++) {
        int col = nd * 8 + 2 * tig;
        split_store2(ohi, olo, (r0 + col) >> 1, oacc[nd][0] * i0, oacc[nd][1] * i0);
        split_store2(ohi, olo, (r1 + col) >> 1, oacc[nd][2] * i1, oacc[nd][3] * i1);
    }
}

// ---------------- launcher ---------------------------------------------------
extern "C" void kernel_launch(void* const* d_in, const int* in_sizes, int n_in,
                              void* d_out, int out_size)
{
    const float* x    = (const float*)d_in[0];
    const float* w[4] = {(const float*)d_in[1], (const float*)d_in[2],
                         (const float*)d_in[3], (const float*)d_in[4]};
    const float* fcos = (const float*)d_in[5];
    const float* fsin = (const float*)d_in[6];
    float* out = (float*)d_out;

    __nv_bfloat16 *xhi, *xlo, *ohi, *olo, *whi, *wlo;
    __nv_bfloat16 *qhi, *qlo, *khi, *klo, *vthi, *vtlo;
    cudaGetSymbolAddress((void**)&xhi, g_xhi);
    cudaGetSymbolAddress((void**)&xlo, g_xlo);
    cudaGetSymbolAddress((void**)&ohi, g_ohi);
    cudaGetSymbolAddress((void**)&olo, g_olo);
    cudaGetSymbolAddress((void**)&whi, g_whi);
    cudaGetSymbolAddress((void**)&wlo, g_wlo);
    cudaGetSymbolAddress((void**)&qhi, g_qhi);
    cudaGetSymbolAddress((void**)&qlo, g_qlo);
    cudaGetSymbolAddress((void**)&khi, g_khi);
    cudaGetSymbolAddress((void**)&klo, g_klo);
    cudaGetSymbolAddress((void**)&vthi, g_vthi);
    cudaGetSymbolAddress((void**)&vtlo, g_vtlo);

    cudaFuncSetAttribute(gemm_qkv,
                         cudaFuncAttributeMaxDynamicSharedMemorySize, GEMM_SMEM_BYTES);
    cudaFuncSetAttribute(gemm_out,
                         cudaFuncAttributeMaxDynamicSharedMemorySize, GEMM_SMEM_BYTES);
    cudaFuncSetAttribute(attn_tc_kernel,
                         cudaFuncAttributeMaxDynamicSharedMemorySize, ATTN_SMEM_BYTES);

    int nx4 = ROWS * DIM / 4;
    int nw4 = DIM * DIM / 4;
    split_kernel<<<nx4 / 256, 256>>>(x, xhi, xlo, nx4);
    split4_kernel<<<dim3(nw4 / 256, 4), 256>>>(w[0], w[1], w[2], w[3], whi, wlo, nw4);

    dim3 gqkv(DIM / BN, ROWS / BM, 3);   // (16, 32, 3)
    gemm_qkv<<<gqkv, 256, GEMM_SMEM_BYTES>>>(
        xhi, xlo, whi, wlo, qhi, qlo, khi, klo, vthi, vtlo, fcos, fsin);

    attn_tc_kernel<<<dim3(SEQ / AQ, NH, BATCH), 384, ATTN_SMEM_BYTES>>>(
        qhi, qlo, khi, klo, vthi, vtlo, ohi, olo);

    gemm_out<<<dim3(DIM / BN, ROWS / BM), 256, GEMM_SMEM_BYTES>>>(
        ohi, olo, whi + 3*(size_t)DIM*DIM, wlo + 3*(size_t)DIM*DIM, out);
}

// round 16
// speedup vs baseline: 3.4018x; 1.0671x over previous
#include <cuda_runtime.h>
#include <cuda_bf16.h>
#include <cstdint>

#define BATCH 2
#define SEQ   2048
#define DIM   2048
#define NH    16
#define HD    128
#define ROWS  (BATCH*SEQ)   // 4096
#define NSM   148
#define NITEM 512           // 16 qt x 16 h x 2 b

// ---------------- scratch (static device globals; no allocs allowed) --------
__device__ __nv_bfloat16 g_xhi[ROWS*DIM];
__device__ __nv_bfloat16 g_xlo[ROWS*DIM];
__device__ __nv_bfloat16 g_ohi[ROWS*DIM];
__device__ __nv_bfloat16 g_olo[ROWS*DIM];
__device__ __nv_bfloat16 g_whi[4][DIM*DIM];   // q,k,v,o
__device__ __nv_bfloat16 g_wlo[4][DIM*DIM];

__device__ __nv_bfloat16 g_qhi[ROWS*DIM];
__device__ __nv_bfloat16 g_qlo[ROWS*DIM];
__device__ __nv_bfloat16 g_khi[ROWS*DIM];
__device__ __nv_bfloat16 g_klo[ROWS*DIM];
__device__ __nv_bfloat16 g_vthi[ROWS*DIM];    // per-head transposed [b,h,d,s]
__device__ __nv_bfloat16 g_vtlo[ROWS*DIM];

// ============================================================================
// helpers
// ============================================================================
__device__ __forceinline__ void cp_async16(void* smem, const void* gmem) {
    uint32_t s = (uint32_t)__cvta_generic_to_shared(smem);
    asm volatile("cp.async.cg.shared.global [%0], [%1], 16;\n" :: "r"(s), "l"(gmem));
}
__device__ __forceinline__ void cp_async16_s(uint32_t saddr, const void* gmem) {
    asm volatile("cp.async.cg.shared.global [%0], [%1], 16;\n" :: "r"(saddr), "l"(gmem));
}
#define CP_COMMIT() asm volatile("cp.async.commit_group;\n" ::: "memory")
#define CP_WAIT1()  asm volatile("cp.async.wait_group 1;\n" ::: "memory")
#define CP_WAIT0()  asm volatile("cp.async.wait_group 0;\n" ::: "memory")

__device__ __forceinline__ void mma_bf16(float* c, const uint32_t* a, const uint32_t* b) {
    asm volatile(
        "mma.sync.aligned.m16n8k16.row.col.f32.bf16.bf16.f32 "
        "{%0,%1,%2,%3}, {%4,%5,%6,%7}, {%8,%9}, {%0,%1,%2,%3};\n"
        : "+f"(c[0]), "+f"(c[1]), "+f"(c[2]), "+f"(c[3])
        : "r"(a[0]), "r"(a[1]), "r"(a[2]), "r"(a[3]),
          "r"(b[0]), "r"(b[1]));
}
__device__ __forceinline__ void ldsm_x4(uint32_t* r, uint32_t saddr) {
    asm volatile("ldmatrix.sync.aligned.m8n8.x4.shared.b16 {%0,%1,%2,%3}, [%4];"
        : "=r"(r[0]), "=r"(r[1]), "=r"(r[2]), "=r"(r[3]) : "r"(saddr));
}
__device__ __forceinline__ uint32_t smem_u32(const void* p) {
    return (uint32_t)__cvta_generic_to_shared(p);
}

// ---- mbarrier ---------------------------------------------------------------
#define MBAR_INIT(addr, cnt) \
    asm volatile("mbarrier.init.shared.b64 [%0], %1;" :: "r"(addr), "r"(cnt) : "memory")
#define MBAR_ARRIVE(addr) \
    asm volatile("{\n\t.reg .b64 st;\n\tmbarrier.arrive.shared.b64 st, [%0];\n\t}" \
                 :: "r"(addr) : "memory")
// .noinc: async arrive counts against the initialized expected count and
// covers ALL prior cp.asyncs issued by this thread.
#define CP_ASYNC_MBAR_ARRIVE(addr) \
    asm volatile("cp.async.mbarrier.arrive.noinc.shared.b64 [%0];" :: "r"(addr) : "memory")
// Bounded spin: protocol bugs fail fast (wrong answer), never hang containers.
#define MBAR_WAIT(addr, parity) do {                                            \
    uint32_t _done = 0; uint32_t _spin = 0;                                     \
    while (!_done && _spin < (1u << 24)) {                                      \
        asm volatile(                                                           \
            "{\n\t.reg .pred p;\n\t"                                            \
            "mbarrier.try_wait.parity.shared.b64 p, [%1], %2;\n\t"              \
            "selp.b32 %0, 1, 0, p;\n\t}"                                        \
            : "=r"(_done) : "r"(addr), "r"(parity) : "memory");                 \
        _spin++;                                                                \
    }                                                                           \
} while (0)

// ---------------- fp32 -> bf16 hi/lo split (x) -------------------------------
__global__ void split_kernel(const float* __restrict__ in,
                             __nv_bfloat16* __restrict__ hi,
                             __nv_bfloat16* __restrict__ lo, int n4)
{
    int idx = blockIdx.x * blockDim.x + threadIdx.x;
    if (idx >= n4) return;
    float4 v = ((const float4*)in)[idx];
    __nv_bfloat16 h0 = __float2bfloat16(v.x);
    __nv_bfloat16 h1 = __float2bfloat16(v.y);
    __nv_bfloat16 h2 = __float2bfloat16(v.z);
    __nv_bfloat16 h3 = __float2bfloat16(v.w);
    __nv_bfloat16 l0 = __float2bfloat16(v.x - __bfloat162float(h0));
    __nv_bfloat16 l1 = __float2bfloat16(v.y - __bfloat162float(h1));
    __nv_bfloat16 l2 = __float2bfloat16(v.z - __bfloat162float(h2));
    __nv_bfloat16 l3 = __float2bfloat16(v.w - __bfloat162float(h3));
    ((__nv_bfloat162*)hi)[idx*2+0] = __nv_bfloat162(h0, h1);
    ((__nv_bfloat162*)hi)[idx*2+1] = __nv_bfloat162(h2, h3);
    ((__nv_bfloat162*)lo)[idx*2+0] = __nv_bfloat162(l0, l1);
    ((__nv_bfloat162*)lo)[idx*2+1] = __nv_bfloat162(l2, l3);
}

// ---------------- fused 4-weight split (grid.y selects weight) ---------------
__global__ void split4_kernel(const float* __restrict__ w0,
                              const float* __restrict__ w1,
                              const float* __restrict__ w2,
                              const float* __restrict__ w3,
                              __nv_bfloat16* __restrict__ hib,
                              __nv_bfloat16* __restrict__ lob, int n4)
{
    int idx = blockIdx.x * blockDim.x + threadIdx.x;
    if (idx >= n4) return;
    int wsel = blockIdx.y;
    const float* in = (wsel == 0) ? w0 : (wsel == 1) ? w1 : (wsel == 2) ? w2 : w3;
    __nv_bfloat16* hi = hib + (size_t)wsel * DIM * DIM;
    __nv_bfloat16* lo = lob + (size_t)wsel * DIM * DIM;
    float4 v = ((const float4*)in)[idx];
    __nv_bfloat16 h0 = __float2bfloat16(v.x);
    __nv_bfloat16 h1 = __float2bfloat16(v.y);
    __nv_bfloat16 h2 = __float2bfloat16(v.z);
    __nv_bfloat16 h3 = __float2bfloat16(v.w);
    __nv_bfloat16 l0 = __float2bfloat16(v.x - __bfloat162float(h0));
    __nv_bfloat16 l1 = __float2bfloat16(v.y - __bfloat162float(h1));
    __nv_bfloat16 l2 = __float2bfloat16(v.z - __bfloat162float(h2));
    __nv_bfloat16 l3 = __float2bfloat16(v.w - __bfloat162float(h3));
    ((__nv_bfloat162*)hi)[idx*2+0] = __nv_bfloat162(h0, h1);
    ((__nv_bfloat162*)hi)[idx*2+1] = __nv_bfloat162(h2, h3);
    ((__nv_bfloat162*)lo)[idx*2+0] = __nv_bfloat162(l0, l1);
    ((__nv_bfloat162*)lo)[idx*2+1] = __nv_bfloat162(l2, l3);
}

// ============================================================================
// bf16x3 GEMM (unchanged from R15)
// ============================================================================
#define BM 128
#define BN 128
#define BK 32
#define NSTG 3
#define TILE_B (BM*BK*2)
#define GEMM_SMEM_BYTES (4*NSTG*TILE_B)   // 98304

__device__ __forceinline__ uint32_t swz(int row, int chunk) {
    return (uint32_t)(row * 64 + ((chunk ^ ((row >> 1) & 3)) << 4));
}

struct GemmCore {
    uint32_t uAh, uAl, uBh, uBl;
    int t, lane, wid, gid, tig, wm, wn, m0, n0;
    int arow, achk, brow, bchk;
    int lr0, lc0, lr1;
    uint32_t so0, so1;
    float acc[4][4][4];

    __device__ __forceinline__ void init(char* smc, int bx, int by, int tid) {
        uAh = smem_u32(smc);
        uAl = uAh + NSTG * TILE_B;
        uBh = uAh + 2 * NSTG * TILE_B;
        uBl = uAh + 3 * NSTG * TILE_B;
        t = tid; lane = t & 31; wid = t >> 5;
        gid = lane >> 2; tig = lane & 3;
        wm = (wid & 1) * 64; wn = (wid >> 1) * 32;
        m0 = by * BM; n0 = bx * BN;
        arow = lane & 15; achk = lane >> 4;
        brow = ((lane >> 4) << 3) + (lane & 7);
        bchk = (lane >> 3) & 1;
        lr0 = t >> 2; lc0 = (t & 3) * 8; lr1 = lr0 + 64;
        so0 = swz(lr0, t & 3);
        so1 = swz(lr1, t & 3);
#pragma unroll
        for (int i = 0; i < 4; i++)
#pragma unroll
            for (int j = 0; j < 4; j++)
#pragma unroll
                for (int e = 0; e < 4; e++) acc[i][j][e] = 0.f;
    }

    __device__ __forceinline__ void load_stage(
        int stg, int k0,
        const __nv_bfloat16* Ahi, const __nv_bfloat16* Alo,
        const __nv_bfloat16* Bhi, const __nv_bfloat16* Blo, int K)
    {
        const uint32_t sb = stg * TILE_B;
        size_t ga0 = (size_t)(m0 + lr0) * K + k0 + lc0;
        size_t ga1 = (size_t)(m0 + lr1) * K + k0 + lc0;
        size_t gb0 = (size_t)(n0 + lr0) * K + k0 + lc0;
        size_t gb1 = (size_t)(n0 + lr1) * K + k0 + lc0;
        cp_async16_s(uAh + sb + so0, Ahi + ga0);  cp_async16_s(uAh + sb + so1, Ahi + ga1);
        cp_async16_s(uAl + sb + so0, Alo + ga0);  cp_async16_s(uAl + sb + so1, Alo + ga1);
        cp_async16_s(uBh + sb + so0, Bhi + gb0);  cp_async16_s(uBh + sb + so1, Bhi + gb1);
        cp_async16_s(uBl + sb + so0, Blo + gb0);  cp_async16_s(uBl + sb + so1, Blo + gb1);
        CP_COMMIT();
    }

    __device__ __forceinline__ void consume_stage(int stg) {
        const uint32_t stb = stg * TILE_B;
#pragma unroll
        for (int kk = 0; kk < 2; kk++) {
            uint32_t ah[4][4], al[4][4], bh[4][2], bl[4][2];
#pragma unroll
            for (int ms = 0; ms < 4; ms++) {
                int row = wm + ms * 16 + arow;
                uint32_t off = stb + swz(row, 2 * kk + achk);
                ldsm_x4(ah[ms], uAh + off);
                ldsm_x4(al[ms], uAl + off);
            }
#pragma unroll
            for (int nsp = 0; nsp < 2; nsp++) {
                int row = wn + nsp * 16 + brow;
                uint32_t off = stb + swz(row, 2 * kk + bchk);
                uint32_t r[4];
                ldsm_x4(r, uBh + off);
                bh[2*nsp][0] = r[0]; bh[2*nsp][1] = r[1];
                bh[2*nsp+1][0] = r[2]; bh[2*nsp+1][1] = r[3];
                ldsm_x4(r, uBl + off);
                bl[2*nsp][0] = r[0]; bl[2*nsp][1] = r[1];
                bl[2*nsp+1][0] = r[2]; bl[2*nsp+1][1] = r[3];
            }
#pragma unroll
            for (int ms = 0; ms < 4; ms++)
#pragma unroll
                for (int ns = 0; ns < 4; ns++) {
                    mma_bf16(acc[ms][ns], ah[ms], bh[ns]);
                    mma_bf16(acc[ms][ns], al[ms], bh[ns]);
                    mma_bf16(acc[ms][ns], ah[ms], bl[ns]);
                }
        }
    }

    __device__ __forceinline__ void mainloop(
        const __nv_bfloat16* Ahi, const __nv_bfloat16* Alo,
        const __nv_bfloat16* Bhi, const __nv_bfloat16* Blo, int K)
    {
        const int NK = K / BK;
        load_stage(0, 0, Ahi, Alo, Bhi, Blo, K);
        load_stage(1, BK, Ahi, Alo, Bhi, Blo, K);
        int s2 = 2;
        for (int kt = 0; kt < NK; kt++) {
            if (kt + 1 < NK) { CP_WAIT1(); } else { CP_WAIT0(); }
            __syncthreads();
            if (kt + 2 < NK) {
                load_stage(s2, (kt + 2) * BK, Ahi, Alo, Bhi, Blo, K);
            }
            int sc = s2 + 1; if (sc >= NSTG) sc -= NSTG;
            consume_stage(sc);
            s2 = sc;
        }
    }
};

__device__ __forceinline__ void split_store2(
    __nv_bfloat16* hi, __nv_bfloat16* lo, size_t idx2, float x, float y)
{
    __nv_bfloat16 hx = __float2bfloat16(x);
    __nv_bfloat16 hy = __float2bfloat16(y);
    ((__nv_bfloat162*)hi)[idx2] = __nv_bfloat162(hx, hy);
    ((__nv_bfloat162*)lo)[idx2] = __nv_bfloat162(
        __float2bfloat16(x - __bfloat162float(hx)),
        __float2bfloat16(y - __bfloat162float(hy)));
}

// proj 0=Q(rope), 1=K(rope), 2=V^T (A/B swapped, scatter to [b,h,d,s])
__global__ void __launch_bounds__(256, 2) gemm_qkv(
    const __nv_bfloat16* __restrict__ xhi, const __nv_bfloat16* __restrict__ xlo,
    const __nv_bfloat16* __restrict__ whi, const __nv_bfloat16* __restrict__ wlo,
    __nv_bfloat16* __restrict__ qhi, __nv_bfloat16* __restrict__ qlo,
    __nv_bfloat16* __restrict__ khi, __nv_bfloat16* __restrict__ klo,
    __nv_bfloat16* __restrict__ vthi, __nv_bfloat16* __restrict__ vtlo,
    const float* __restrict__ fc, const float* __restrict__ fs)
{
    extern __shared__ char smc[];
    const int proj = blockIdx.z;
    GemmCore g;
    const __nv_bfloat16* Whi = whi + (size_t)proj * DIM * DIM;
    const __nv_bfloat16* Wlo = wlo + (size_t)proj * DIM * DIM;

    if (proj == 2) {
        g.init(smc, blockIdx.y, blockIdx.x, threadIdx.x);
        g.mainloop(Whi, Wlo, xhi, xlo, DIM);
#pragma unroll
        for (int ms = 0; ms < 4; ms++)
#pragma unroll
            for (int ns = 0; ns < 4; ns++) {
                int e0 = g.m0 + g.wm + ms * 16 + g.gid;
                int sg = g.n0 + g.wn + ns * 8 + g.tig * 2;
                int b  = sg >> 11;
                int sl = sg & (SEQ - 1);
#pragma unroll
                for (int half = 0; half < 2; half++) {
                    int e = e0 + half * 8;
                    size_t off = (size_t)b * DIM * SEQ + (size_t)e * SEQ + sl;
                    split_store2(vthi, vtlo, off >> 1,
                                 g.acc[ms][ns][half * 2], g.acc[ms][ns][half * 2 + 1]);
                }
            }
        return;
    }

    g.init(smc, blockIdx.x, blockIdx.y, threadIdx.x);
    g.mainloop(xhi, xlo, Whi, Wlo, DIM);
    const int N = DIM;
    __nv_bfloat16* Chi = proj ? khi : qhi;
    __nv_bfloat16* Clo = proj ? klo : qlo;
#pragma unroll
    for (int ms = 0; ms < 4; ms++)
#pragma unroll
        for (int ns = 0; ns < 4; ns++) {
            int row0 = g.m0 + g.wm + ms * 16 + g.gid;
            int col  = g.n0 + g.wn + ns * 8 + g.tig * 2;
            int i = (col & 127) >> 1;
#pragma unroll
            for (int half = 0; half < 2; half++) {
                int row = row0 + half * 8;
                int s   = row & (SEQ - 1);
                float cs = __ldg(fc + s * 64 + i);
                float sn = __ldg(fs + s * 64 + i);
                float re = g.acc[ms][ns][half * 2];
                float im = g.acc[ms][ns][half * 2 + 1];
                float rx = re * cs - im * sn;
                float ry = re * sn + im * cs;
                split_store2(Chi, Clo, ((size_t)row * N + col) >> 1, rx, ry);
            }
        }
}

__global__ void __launch_bounds__(256, 2) gemm_out(
    const __nv_bfloat16* __restrict__ Ahi, const __nv_bfloat16* __restrict__ Alo,
    const __nv_bfloat16* __restrict__ Bhi, const __nv_bfloat16* __restrict__ Blo,
    float* __restrict__ C)
{
    extern __shared__ char smc[];
    GemmCore g;
    g.init(smc, blockIdx.x, blockIdx.y, threadIdx.x);
    g.mainloop(Ahi, Alo, Bhi, Blo, DIM);
    const int N = DIM;
#pragma unroll
    for (int ms = 0; ms < 4; ms++)
#pragma unroll
        for (int ns = 0; ns < 4; ns++) {
            int row = g.m0 + g.wm + ms * 16 + g.gid;
            int col = g.n0 + g.wn + ns * 8 + g.tig * 2;
            float2 c0 = {g.acc[ms][ns][0], g.acc[ms][ns][1]};
            float2 c1 = {g.acc[ms][ns][2], g.acc[ms][ns][3]};
            *(float2*)&C[(size_t)row * N + col]       = c0;
            *(float2*)&C[(size_t)(row + 8) * N + col] = c1;
        }
}

// ============================================================================
// R16: PERSISTENT warp-specialized flash attention, bf16x3, causal.
// 148 CTAs; each snake-walks a qt-descending work list (balanced +-10%).
// mbarrier full/empty pipeline extends across items (continuing phases);
// qfree barrier protects Q overwrite between items. exp2-domain softmax.
// ============================================================================
#define AQ  128
#define AK  64
#define AHS 136
#define AVS 72
#define A_QH        0
#define A_QL        17408
#define A_KH(bf)    (34816 + (bf)*8704)
#define A_KL(bf)    (52224 + (bf)*8704)
#define A_VH(bf)    (69632 + (bf)*9216)
#define A_VL(bf)    (88064 + (bf)*9216)
#define A_MBAR_B    212992
#define ATTN_SMEM_BYTES (212992 + 64)

__global__ void __launch_bounds__(384) attn_tc_kernel(
    const __nv_bfloat16* __restrict__ qhi, const __nv_bfloat16* __restrict__ qlo,
    const __nv_bfloat16* __restrict__ khi, const __nv_bfloat16* __restrict__ klo,
    const __nv_bfloat16* __restrict__ vthi, const __nv_bfloat16* __restrict__ vtlo,
    __nv_bfloat16* __restrict__ ohi, __nv_bfloat16* __restrict__ olo)
{
    extern __shared__ __nv_bfloat16 smh[];
    const uint32_t ubase = smem_u32(smh);
    const uint32_t mb_full0  = ubase + A_MBAR_B;
    const uint32_t mb_full1  = ubase + A_MBAR_B + 8;
    const uint32_t mb_empty0 = ubase + A_MBAR_B + 16;
    const uint32_t mb_empty1 = ubase + A_MBAR_B + 24;
    const uint32_t mb_qfree  = ubase + A_MBAR_B + 32;

    const int t    = threadIdx.x;
    const int lane = t & 31;
    const int wid  = t >> 5;            // 0..7 consumer, 8..11 producer
    const int gid  = lane >> 2;
    const int tig  = lane & 3;
    const int cta  = blockIdx.x;

    const int arow = (lane & 15);
    const int acol = (lane >> 4) << 3;
    const int brow = ((lane >> 4) << 3) + (lane & 7);
    const int bcol = ((lane >> 3) & 1) << 3;

    if (t == 0) {
        MBAR_INIT(mb_full0, 128);
        MBAR_INIT(mb_full1, 128);
        MBAR_INIT(mb_empty0, 256);
        MBAR_INIT(mb_empty1, 256);
        MBAR_INIT(mb_qfree, 256);
    }
    __syncthreads();

    // scale folded into exp2 domain: p = 2^(s*scale2 - m)
    const float scale2 = 0.08838834764831845f * 1.4426950408889634f;

    // =================== PRODUCER warps (wid 8..11) ===================
    if (wid >= 8) {
        const int pt = t - 256;   // 0..127
        int ep0 = 0, ep1 = 0, qph = 0;
        bool first = true;

#define LOAD_KV_P(BUFI, KT, B_, H_)                                             \
        {                                                                       \
            int row = pt >> 1;                                                  \
            int cb  = (pt & 1) * 8;                                             \
            size_t g = (size_t)((B_) * SEQ + (KT) * AK + row) * DIM + (H_) * HD + cb * 8; \
            int so = row * AHS + cb * 8;                                        \
            _Pragma("unroll")                                                   \
            for (int c = 0; c < 8; c++) {                                       \
                cp_async16(smh + A_KH(BUFI) + so + c * 8, khi + g + c * 8);     \
                cp_async16(smh + A_KL(BUFI) + so + c * 8, klo + g + c * 8);     \
            }                                                                   \
            size_t gv = (size_t)(((B_) * NH + (H_)) * HD + pt) * SEQ + (KT) * AK; \
            int sv = pt * AVS;                                                  \
            _Pragma("unroll")                                                   \
            for (int c = 0; c < 8; c++) {                                       \
                cp_async16(smh + A_VH(BUFI) + sv + c * 8, vthi + gv + c * 8);   \
                cp_async16(smh + A_VL(BUFI) + sv + c * 8, vtlo + gv + c * 8);   \
            }                                                                   \
        }

        for (int j = 0; j < 4; j++) {
            int p = (j & 1) ? ((j + 1) * NSM - 1 - cta) : (j * NSM + cta);
            if (p >= NITEM) continue;
            const int qt = 15 - (p >> 5);
            const int hb = p & 31;
            const int h = hb >> 1, b = hb & 1;
            const int ktmax = 2 * qt + 1;

            if (!first) { MBAR_WAIT(mb_qfree, qph); qph ^= 1; }

            // Q tile (covered by the stage-0 full arrive)
            {
                size_t g = (size_t)(b * SEQ + qt * AQ + pt) * DIM + h * HD;
                int so = pt * AHS;
#pragma unroll
                for (int c = 0; c < 16; c++) {
                    cp_async16(smh + A_QH + so + c * 8, qhi + g + c * 8);
                    cp_async16(smh + A_QL + so + c * 8, qlo + g + c * 8);
                }
            }
            if (!first) { MBAR_WAIT(mb_empty0, ep0); ep0 ^= 1; }
            LOAD_KV_P(0, 0, b, h);
            CP_ASYNC_MBAR_ARRIVE(mb_full0);
            if (!first) { MBAR_WAIT(mb_empty1, ep1); ep1 ^= 1; }
            LOAD_KV_P(1, 1, b, h);
            CP_ASYNC_MBAR_ARRIVE(mb_full1);
            first = false;

            for (int kt = 2; kt <= ktmax; kt++) {
                const int s = kt & 1;
                if (s == 0) { MBAR_WAIT(mb_empty0, ep0); ep0 ^= 1; }
                else        { MBAR_WAIT(mb_empty1, ep1); ep1 ^= 1; }
                LOAD_KV_P(s, kt, b, h);
                CP_ASYNC_MBAR_ARRIVE(s == 0 ? mb_full0 : mb_full1);
            }
        }
        return;
    }

    // =================== CONSUMER warps (wid 0..7) ===================
    int fph0 = 0, fph1 = 0;

    for (int j = 0; j < 4; j++) {
        int p = (j & 1) ? ((j + 1) * NSM - 1 - cta) : (j * NSM + cta);
        if (p >= NITEM) continue;
        const int qt = 15 - (p >> 5);
        const int hb = p & 31;
        const int h = hb >> 1, b = hb & 1;
        const int ktmax = 2 * qt + 1;
        const int gr0 = qt * AQ + wid * 16 + gid;

        float sacc[8][4];
        float oacc[16][4];
#pragma unroll
        for (int i = 0; i < 16; i++)
#pragma unroll
            for (int e = 0; e < 4; e++) oacc[i][e] = 0.f;
        float m0 = -1e30f, m1 = -1e30f, l0 = 0.f, l1 = 0.f;

        for (int kt = 0; kt <= ktmax; kt++) {
            const int s = kt & 1;
            if (s == 0) { MBAR_WAIT(mb_full0, fph0); fph0 ^= 1; }
            else        { MBAR_WAIT(mb_full1, fph1); fph1 ^= 1; }

#pragma unroll
            for (int ns = 0; ns < 8; ns++)
#pragma unroll
                for (int e = 0; e < 4; e++) sacc[ns][e] = 0.f;

            const uint32_t ukh = ubase + A_KH(s) * 2;
            const uint32_t ukl = ubase + A_KL(s) * 2;
#pragma unroll
            for (int kk = 0; kk < 8; kk++) {
                uint32_t aoff = ((wid * 16 + arow) * AHS + kk * 16 + acol) * 2;
                uint32_t ah[4], al[4];
                ldsm_x4(ah, ubase + A_QH * 2 + aoff);
                ldsm_x4(al, ubase + A_QL * 2 + aoff);
#pragma unroll
                for (int nsp = 0; nsp < 4; nsp++) {
                    uint32_t boff = ((nsp * 16 + brow) * AHS + kk * 16 + bcol) * 2;
                    uint32_t rh[4], rl[4];
                    ldsm_x4(rh, ukh + boff);
                    ldsm_x4(rl, ukl + boff);
                    uint32_t b0h[2] = {rh[0], rh[1]}, b1h[2] = {rh[2], rh[3]};
                    uint32_t b0l[2] = {rl[0], rl[1]}, b1l[2] = {rl[2], rl[3]};
                    mma_bf16(sacc[2*nsp],   ah, b0h);
                    mma_bf16(sacc[2*nsp+1], ah, b1h);
                    mma_bf16(sacc[2*nsp],   al, b0h);
                    mma_bf16(sacc[2*nsp+1], al, b1h);
                    mma_bf16(sacc[2*nsp],   ah, b0l);
                    mma_bf16(sacc[2*nsp+1], ah, b1l);
                }
            }

            if (kt * AK + 63 > qt * AQ + wid * 16) {
                int rl0 = gr0 - kt * AK;
                int rl1 = rl0 + 8;
#pragma unroll
                for (int ns = 0; ns < 8; ns++) {
#pragma unroll
                    for (int e = 0; e < 4; e++) {
                        float v = sacc[ns][e] * scale2;
                        int cl = ns * 8 + 2 * tig + (e & 1);
                        int rl = (e < 2) ? rl0 : rl1;
                        sacc[ns][e] = (cl > rl) ? -1e30f : v;
                    }
                }
            } else {
#pragma unroll
                for (int ns = 0; ns < 8; ns++)
#pragma unroll
                    for (int e = 0; e < 4; e++) sacc[ns][e] *= scale2;
            }

            float mx0 = -1e30f, mx1 = -1e30f;
#pragma unroll
            for (int ns = 0; ns < 8; ns++) {
                mx0 = fmaxf(mx0, fmaxf(sacc[ns][0], sacc[ns][1]));
                mx1 = fmaxf(mx1, fmaxf(sacc[ns][2], sacc[ns][3]));
            }
            mx0 = fmaxf(mx0, __shfl_xor_sync(0xffffffffu, mx0, 1));
            mx0 = fmaxf(mx0, __shfl_xor_sync(0xffffffffu, mx0, 2));
            mx1 = fmaxf(mx1, __shfl_xor_sync(0xffffffffu, mx1, 1));
            mx1 = fmaxf(mx1, __shfl_xor_sync(0xffffffffu, mx1, 2));
            float mn0 = fmaxf(m0, mx0), mn1 = fmaxf(m1, mx1);
            float a0 = exp2f(m0 - mn0), a1 = exp2f(m1 - mn1);
            m0 = mn0; m1 = mn1;

            float sum0 = 0.f, sum1 = 0.f;
#pragma unroll
            for (int ns = 0; ns < 8; ns++) {
                float p0 = exp2f(sacc[ns][0] - mn0);
                float p1 = exp2f(sacc[ns][1] - mn0);
                float p2 = exp2f(sacc[ns][2] - mn1);
                float p3 = exp2f(sacc[ns][3] - mn1);
                sacc[ns][0] = p0; sacc[ns][1] = p1;
                sacc[ns][2] = p2; sacc[ns][3] = p3;
                sum0 += p0 + p1; sum1 += p2 + p3;
            }
            sum0 += __shfl_xor_sync(0xffffffffu, sum0, 1);
            sum0 += __shfl_xor_sync(0xffffffffu, sum0, 2);
            sum1 += __shfl_xor_sync(0xffffffffu, sum1, 1);
            sum1 += __shfl_xor_sync(0xffffffffu, sum1, 2);
            l0 = l0 * a0 + sum0;
            l1 = l1 * a1 + sum1;

#pragma unroll
            for (int nd = 0; nd < 16; nd++) {
                oacc[nd][0] *= a0; oacc[nd][1] *= a0;
                oacc[nd][2] *= a1; oacc[nd][3] *= a1;
            }

            const uint32_t uvh = ubase + A_VH(s) * 2;
            const uint32_t uvl = ubase + A_VL(s) * 2;
#pragma unroll
            for (int kc = 0; kc < 4; kc++) {
                uint32_t ph[4], pl[4];
#pragma unroll
                for (int jj = 0; jj < 4; jj++) {
                    int ns = 2 * kc + (jj >> 1);
                    int e0 = (jj & 1) * 2;
                    float c0 = sacc[ns][e0], c1 = sacc[ns][e0 + 1];
                    __nv_bfloat162 hb2 = __floats2bfloat162_rn(c0, c1);
                    uint32_t hu = *(uint32_t*)&hb2;
                    float f0 = __uint_as_float(hu << 16);
                    float f1 = __uint_as_float(hu & 0xffff0000u);
                    __nv_bfloat162 lb = __floats2bfloat162_rn(c0 - f0, c1 - f1);
                    ph[jj] = hu;
                    pl[jj] = *(uint32_t*)&lb;
                }
#pragma unroll
                for (int ndp = 0; ndp < 8; ndp++) {
                    uint32_t boff = ((ndp * 16 + brow) * AVS + kc * 16 + bcol) * 2;
                    uint32_t rh[4], rl[4];
                    ldsm_x4(rh, uvh + boff);
                    ldsm_x4(rl, uvl + boff);
                    uint32_t b0h[2] = {rh[0], rh[1]}, b1h[2] = {rh[2], rh[3]};
                    uint32_t b0l[2] = {rl[0], rl[1]}, b1l[2] = {rl[2], rl[3]};
                    mma_bf16(oacc[2*ndp],   ph, b0h);
                    mma_bf16(oacc[2*ndp+1], ph, b1h);
                    mma_bf16(oacc[2*ndp],   pl, b0h);
                    mma_bf16(oacc[2*ndp+1], pl, b1h);
                    mma_bf16(oacc[2*ndp],   ph, b0l);
                    mma_bf16(oacc[2*ndp+1], ph, b1l);
                }
            }

            if (s == 0) MBAR_ARRIVE(mb_empty0); else MBAR_ARRIVE(mb_empty1);
        }

        // item done: release Q for producers
        MBAR_ARRIVE(mb_qfree);

        // normalize + split-store
        float i0 = 1.f / l0, i1 = 1.f / l1;
        size_t r0 = (size_t)(b * SEQ + gr0) * DIM + h * HD;
        size_t r1 = r0 + 8 * DIM;
#pragma unroll
        for (int nd = 0; nd < 16; nd++) {
            int col = nd * 8 + 2 * tig;
            split_store2(ohi, olo, (r0 + col) >> 1, oacc[nd][0] * i0, oacc[nd][1] * i0);
            split_store2(ohi, olo, (r1 + col) >> 1, oacc[nd][2] * i1, oacc[nd][3] * i1);
        }
    }
}

// ---------------- launcher ---------------------------------------------------
extern "C" void kernel_launch(void* const* d_in, const int* in_sizes, int n_in,
                              void* d_out, int out_size)
{
    const float* x    = (const float*)d_in[0];
    const float* w[4] = {(const float*)d_in[1], (const float*)d_in[2],
                         (const float*)d_in[3], (const float*)d_in[4]};
    const float* fcos = (const float*)d_in[5];
    const float* fsin = (const float*)d_in[6];
    float* out = (float*)d_out;

    __nv_bfloat16 *xhi, *xlo, *ohi, *olo, *whi, *wlo;
    __nv_bfloat16 *qhi, *qlo, *khi, *klo, *vthi, *vtlo;
    cudaGetSymbolAddress((void**)&xhi, g_xhi);
    cudaGetSymbolAddress((void**)&xlo, g_xlo);
    cudaGetSymbolAddress((void**)&ohi, g_ohi);
    cudaGetSymbolAddress((void**)&olo, g_olo);
    cudaGetSymbolAddress((void**)&whi, g_whi);
    cudaGetSymbolAddress((void**)&wlo, g_wlo);
    cudaGetSymbolAddress((void**)&qhi, g_qhi);
    cudaGetSymbolAddress((void**)&qlo, g_qlo);
    cudaGetSymbolAddress((void**)&khi, g_khi);
    cudaGetSymbolAddress((void**)&klo, g_klo);
    cudaGetSymbolAddress((void**)&vthi, g_vthi);
    cudaGetSymbolAddress((void**)&vtlo, g_vtlo);

    cudaFuncSetAttribute(gemm_qkv,
                         cudaFuncAttributeMaxDynamicSharedMemorySize, GEMM_SMEM_BYTES);
    cudaFuncSetAttribute(gemm_out,
                         cudaFuncAttributeMaxDynamicSharedMemorySize, GEMM_SMEM_BYTES);
    cudaFuncSetAttribute(attn_tc_kernel,
                         cudaFuncAttributeMaxDynamicSharedMemorySize, ATTN_SMEM_BYTES);

    int nx4 = ROWS * DIM / 4;
    int nw4 = DIM * DIM / 4;
    split_kernel<<<nx4 / 256, 256>>>(x, xhi, xlo, nx4);
    split4_kernel<<<dim3(nw4 / 256, 4), 256>>>(w[0], w[1], w[2], w[3], whi, wlo, nw4);

    dim3 gqkv(DIM / BN, ROWS / BM, 3);   // (16, 32, 3)
    gemm_qkv<<<gqkv, 256, GEMM_SMEM_BYTES>>>(
        xhi, xlo, whi, wlo, qhi, qlo, khi, klo, vthi, vtlo, fcos, fsin);

    attn_tc_kernel<<<NSM, 384, ATTN_SMEM_BYTES>>>(
        qhi, qlo, khi, klo, vthi, vtlo, ohi, olo);

    gemm_out<<<dim3(DIM / BN, ROWS / BM), 256, GEMM_SMEM_BYTES>>>(
        ohi, olo, whi + 3*(size_t)DIM*DIM, wlo + 3*(size_t)DIM*DIM, out);
}